// round 1
// baseline (speedup 1.0000x reference)
#include <cuda_runtime.h>
#include <math.h>

// ---------------- problem constants ----------------
#define T_LEN 1024
#define NSLOT 8
#define DS 1024
#define DR 512
#define HEADS 8
#define DHS 128
#define DHR 64
#define TOPK 4
#define ROWS_R (T_LEN * NSLOT)   // 8192
#define SCALE_S 0.08838834764831845f  // 1/sqrt(128)
#define SCALE_R 0.125f                // 1/sqrt(64)
#define EPS 1e-6f

// ---------------- scratch (static device memory; no allocation) -------------
__device__ float g_sn[T_LEN * DS];        // rmsnorm(s)
__device__ float g_rn[ROWS_R * DR];       // rmsnorm(r) flattened (T*N, DR)
__device__ float g_q[T_LEN * DS];         // s_n @ Wsq
__device__ float g_k[ROWS_R * DS];        // r_n @ Wsk
__device__ float g_v[ROWS_R * DS];        // r_n @ Wsv
__device__ float g_attn_s[T_LEN * DS];    // s-attention output (pre Wso)
__device__ float g_rsp[T_LEN * DS];       // sparse top-k write-back
__device__ float g_qr[ROWS_R * DR];       // r_n @ Wrq
__device__ float g_kr[T_LEN * DR];        // s_n @ Wrk
__device__ float g_vr[T_LEN * DR];        // s_n @ Wrv
__device__ float g_attn_r[ROWS_R * DR];   // causal attention output (pre Wro)

// ---------------- rmsnorm ----------------
__global__ __launch_bounds__(256) void rmsnorm_kernel(
    const float* __restrict__ x, const float* __restrict__ w,
    float* __restrict__ out, int C)
{
    int row = blockIdx.x;
    const float* xr = x + (size_t)row * C;
    float s = 0.f;
    for (int j = threadIdx.x; j < C; j += blockDim.x) {
        float v = xr[j];
        s += v * v;
    }
    // block reduce
    __shared__ float red[8];
    int lane = threadIdx.x & 31, warp = threadIdx.x >> 5;
    #pragma unroll
    for (int off = 16; off; off >>= 1) s += __shfl_xor_sync(0xffffffffu, s, off);
    if (lane == 0) red[warp] = s;
    __syncthreads();
    __shared__ float scale;
    if (threadIdx.x == 0) {
        float tot = 0.f;
        #pragma unroll
        for (int i = 0; i < 8; i++) tot += red[i];
        scale = rsqrtf(tot / (float)C + EPS);
    }
    __syncthreads();
    float sc = scale;
    float* orow = out + (size_t)row * C;
    for (int j = threadIdx.x; j < C; j += blockDim.x)
        orow[j] = xr[j] * sc * w[j];
}

// ---------------- SGEMM: C = A(MxK) @ B(KxN) [+ add1] [+ rowscale*add2] -----
// All dims multiples of 128 (checked for every call site). 128x128 tile,
// BK=8, 256 threads, 8x8 microtile, float4 smem reads.
#define BM 128
#define BN 128
#define BK 8
__global__ __launch_bounds__(256) void sgemm_kernel(
    const float* __restrict__ A, const float* __restrict__ B,
    float* __restrict__ C, int M, int N, int K,
    const float* __restrict__ add1,
    const float* __restrict__ add2, const float* __restrict__ rowscale)
{
    __shared__ float As[BK][BM];
    __shared__ float Bs[BK][BN];
    int tid = threadIdx.x;
    int bm = blockIdx.y * BM;
    int bn = blockIdx.x * BN;

    int arow = tid >> 1;            // 0..127
    int acol = (tid & 1) << 2;      // 0 or 4
    int brow = tid >> 5;            // 0..7
    int bcol = (tid & 31) << 2;     // 0..124

    int ty = (tid >> 4) << 3;       // 0..120
    int tx = (tid & 15) << 3;       // 0..120

    float acc[8][8];
    #pragma unroll
    for (int i = 0; i < 8; i++)
        #pragma unroll
        for (int j = 0; j < 8; j++) acc[i][j] = 0.f;

    const float* Aptr = A + (size_t)(bm + arow) * K + acol;
    const float* Bptr = B + (size_t)brow * N + bn + bcol;

    for (int k0 = 0; k0 < K; k0 += BK) {
        float4 av = *(const float4*)(Aptr + k0);
        As[acol + 0][arow] = av.x;
        As[acol + 1][arow] = av.y;
        As[acol + 2][arow] = av.z;
        As[acol + 3][arow] = av.w;
        float4 bv = *(const float4*)(Bptr + (size_t)k0 * N);
        *(float4*)(&Bs[brow][bcol]) = bv;
        __syncthreads();
        #pragma unroll
        for (int k = 0; k < BK; k++) {
            float4 a0 = *(const float4*)(&As[k][ty]);
            float4 a1 = *(const float4*)(&As[k][ty + 4]);
            float4 b0 = *(const float4*)(&Bs[k][tx]);
            float4 b1 = *(const float4*)(&Bs[k][tx + 4]);
            float a[8] = {a0.x, a0.y, a0.z, a0.w, a1.x, a1.y, a1.z, a1.w};
            float b[8] = {b0.x, b0.y, b0.z, b0.w, b1.x, b1.y, b1.z, b1.w};
            #pragma unroll
            for (int i = 0; i < 8; i++)
                #pragma unroll
                for (int j = 0; j < 8; j++)
                    acc[i][j] += a[i] * b[j];
        }
        __syncthreads();
    }

    #pragma unroll
    for (int i = 0; i < 8; i++) {
        int row = bm + ty + i;
        float rs = (rowscale != nullptr) ? rowscale[row] : 0.f;
        #pragma unroll
        for (int j = 0; j < 8; j += 4) {
            size_t off = (size_t)row * N + bn + tx + j;
            float4 v = make_float4(acc[i][j], acc[i][j+1], acc[i][j+2], acc[i][j+3]);
            if (add1) {
                float4 x = *(const float4*)(add1 + off);
                v.x += x.x; v.y += x.y; v.z += x.z; v.w += x.w;
            }
            if (add2) {
                float4 x = *(const float4*)(add2 + off);
                v.x += rs * x.x; v.y += rs * x.y; v.z += rs * x.z; v.w += rs * x.w;
            }
            *(float4*)(C + off) = v;
        }
    }
}

// ---------------- s-attention (per-token, slot softmax) + top-k sparse ------
// block per token t; 256 threads = 8 warps (warp h computes logits[h][n]).
// sp[t,n] = SCALE_S * sum_h logits[h][n]  (algebraic identity with reference).
__global__ __launch_bounds__(256) void s_attn_kernel(
    const float* __restrict__ qmat,   // (T, DS)
    const float* __restrict__ kmat,   // (T*N, DS)
    const float* __restrict__ vmat,   // (T*N, DS)
    float* __restrict__ attn_s,       // (T, DS)
    float* __restrict__ rsp)          // (T, DS)
{
    int t = blockIdx.x;
    int tid = threadIdx.x;
    int warp = tid >> 5, lane = tid & 31;

    __shared__ float qs[DS];
    __shared__ float logits[HEADS][NSLOT];
    __shared__ float wattn[HEADS][NSLOT];
    __shared__ float wsp[NSLOT];

    for (int j = tid; j < DS; j += 256) qs[j] = qmat[(size_t)t * DS + j];
    __syncthreads();

    {
        int h = warp;
        #pragma unroll
        for (int n = 0; n < NSLOT; n++) {
            const float* krow = kmat + (size_t)(t * NSLOT + n) * DS + h * DHS;
            const float* qrow = qs + h * DHS;
            float p = 0.f;
            #pragma unroll
            for (int d = lane; d < DHS; d += 32) p += qrow[d] * krow[d];
            #pragma unroll
            for (int off = 16; off; off >>= 1) p += __shfl_xor_sync(0xffffffffu, p, off);
            if (lane == 0) logits[h][n] = p;
        }
    }
    __syncthreads();

    if (tid < HEADS) {
        int h = tid;
        float m = -INFINITY;
        #pragma unroll
        for (int n = 0; n < NSLOT; n++) m = fmaxf(m, logits[h][n] * SCALE_S);
        float s = 0.f;
        #pragma unroll
        for (int n = 0; n < NSLOT; n++) {
            float e = expf(logits[h][n] * SCALE_S - m);
            wattn[h][n] = e;
            s += e;
        }
        float inv = 1.f / s;
        #pragma unroll
        for (int n = 0; n < NSLOT; n++) wattn[h][n] *= inv;
    }
    if (tid == 8) {
        float sp[NSLOT];
        #pragma unroll
        for (int n = 0; n < NSLOT; n++) {
            float a = 0.f;
            #pragma unroll
            for (int h = 0; h < HEADS; h++) a += logits[h][n];
            sp[n] = a * SCALE_S;
        }
        bool sel[NSLOT];
        #pragma unroll
        for (int n = 0; n < NSLOT; n++) { sel[n] = false; wsp[n] = 0.f; }
        int idxs[TOPK];
        #pragma unroll
        for (int kk = 0; kk < TOPK; kk++) {
            int best = -1; float bv = -INFINITY;
            #pragma unroll
            for (int n = 0; n < NSLOT; n++)
                if (!sel[n] && sp[n] > bv) { bv = sp[n]; best = n; }
            sel[best] = true; idxs[kk] = best;
        }
        float m = -INFINITY;
        #pragma unroll
        for (int kk = 0; kk < TOPK; kk++) m = fmaxf(m, sp[idxs[kk]]);
        float s = 0.f, e[TOPK];
        #pragma unroll
        for (int kk = 0; kk < TOPK; kk++) { e[kk] = expf(sp[idxs[kk]] - m); s += e[kk]; }
        float inv = 1.f / s;
        #pragma unroll
        for (int kk = 0; kk < TOPK; kk++) wsp[idxs[kk]] = e[kk] * inv;
    }
    __syncthreads();

    for (int j = tid; j < DS; j += 256) {
        int h = j >> 7;
        float a1 = 0.f, a2 = 0.f;
        #pragma unroll
        for (int n = 0; n < NSLOT; n++) {
            float vv = vmat[(size_t)(t * NSLOT + n) * DS + j];
            a1 += wattn[h][n] * vv;
            a2 += wsp[n] * vv;
        }
        attn_s[(size_t)t * DS + j] = a1;
        rsp[(size_t)t * DS + j] = a2;
    }
}

// ---------------- causal r-attention (flash-style, online softmax) ----------
// grid (T, H); block = 256 threads = 8 warps; warp n owns query slot n.
#define PT 64
__global__ __launch_bounds__(256) void r_attn_kernel(
    const float* __restrict__ qr,   // (T*N, DR), col h*64+d
    const float* __restrict__ kr,   // (T, DR)
    const float* __restrict__ vr,   // (T, DR)
    float* __restrict__ attn_r)     // (T*N, DR)
{
    int t = blockIdx.x;
    int h = blockIdx.y;
    int tid = threadIdx.x;
    int warp = tid >> 5, lane = tid & 31;
    int n = warp;

    __shared__ float q8[NSLOT][DHR];
    __shared__ float kt[PT][DHR + 1];
    __shared__ float vt[PT][DHR + 1];
    __shared__ float sc[NSLOT][PT];

    for (int i = tid; i < NSLOT * DHR; i += 256) {
        int nn = i >> 6, d = i & 63;
        q8[nn][d] = qr[(size_t)(t * NSLOT + nn) * DR + h * DHR + d];
    }

    float m = -INFINITY, l = 0.f;
    float acc0 = 0.f, acc1 = 0.f;   // output dims d=lane, d=lane+32

    int pmax = t;  // inclusive causal bound
    for (int p0 = 0; p0 <= pmax; p0 += PT) {
        int pcnt = min(PT, pmax - p0 + 1);
        __syncthreads();  // prev phase done (also covers q8 load on iter 0)
        for (int i = tid; i < PT * DHR; i += 256) {
            int pr = i >> 6, d = i & 63;
            float kv = 0.f, vv = 0.f;
            if (pr < pcnt) {
                size_t off = (size_t)(p0 + pr) * DR + h * DHR + d;
                kv = kr[off];
                vv = vr[off];
            }
            kt[pr][d] = kv;
            vt[pr][d] = vv;
        }
        __syncthreads();

        float s0 = -INFINITY, s1 = -INFINITY;
        if (lane < pcnt) {
            float a = 0.f;
            #pragma unroll
            for (int d = 0; d < DHR; d++) a += q8[n][d] * kt[lane][d];
            s0 = a * SCALE_R;
        }
        if (lane + 32 < pcnt) {
            float a = 0.f;
            #pragma unroll
            for (int d = 0; d < DHR; d++) a += q8[n][d] * kt[lane + 32][d];
            s1 = a * SCALE_R;
        }
        float tmax = fmaxf(s0, s1);
        #pragma unroll
        for (int off = 16; off; off >>= 1)
            tmax = fmaxf(tmax, __shfl_xor_sync(0xffffffffu, tmax, off));
        float newm = fmaxf(m, tmax);
        float corr = expf(m - newm);       // exp(-inf)=0 on first tile
        acc0 *= corr; acc1 *= corr; l *= corr;
        float e0 = (lane < pcnt) ? expf(s0 - newm) : 0.f;
        float e1 = (lane + 32 < pcnt) ? expf(s1 - newm) : 0.f;
        sc[n][lane] = e0;
        sc[n][lane + 32] = e1;
        float esum = e0 + e1;
        #pragma unroll
        for (int off = 16; off; off >>= 1)
            esum += __shfl_xor_sync(0xffffffffu, esum, off);
        l += esum;
        m = newm;
        __syncwarp();

        for (int p = 0; p < pcnt; p++) {
            float w = sc[n][p];
            acc0 += w * vt[p][lane];
            acc1 += w * vt[p][lane + 32];
        }
    }
    float inv = 1.f / l;
    size_t base = (size_t)(t * NSLOT + n) * DR + h * DHR;
    attn_r[base + lane] = acc0 * inv;
    attn_r[base + lane + 32] = acc1 * inv;
}

// ---------------- host launch ----------------
extern "C" void kernel_launch(void* const* d_in, const int* in_sizes, int n_in,
                              void* d_out, int out_size)
{
    const float* s      = (const float*)d_in[0];
    const float* r      = (const float*)d_in[1];
    const float* gate_v = (const float*)d_in[2];
    const float* nsw    = (const float*)d_in[3];
    const float* nrw    = (const float*)d_in[4];
    const float* Wsq    = (const float*)d_in[5];
    const float* Wsk    = (const float*)d_in[6];
    const float* Wsv    = (const float*)d_in[7];
    const float* Wso    = (const float*)d_in[8];
    const float* Wrq    = (const float*)d_in[9];
    const float* Wrk    = (const float*)d_in[10];
    const float* Wrv    = (const float*)d_in[11];
    const float* Wro    = (const float*)d_in[12];

    float* out_s = (float*)d_out;                    // (T, DS)
    float* out_r = (float*)d_out + T_LEN * DS;       // (T*N, DR)

    float *sn, *rn, *q, *k, *v, *attn_s, *rsp, *qr, *kr, *vr, *attn_r;
    cudaGetSymbolAddress((void**)&sn, g_sn);
    cudaGetSymbolAddress((void**)&rn, g_rn);
    cudaGetSymbolAddress((void**)&q, g_q);
    cudaGetSymbolAddress((void**)&k, g_k);
    cudaGetSymbolAddress((void**)&v, g_v);
    cudaGetSymbolAddress((void**)&attn_s, g_attn_s);
    cudaGetSymbolAddress((void**)&rsp, g_rsp);
    cudaGetSymbolAddress((void**)&qr, g_qr);
    cudaGetSymbolAddress((void**)&kr, g_kr);
    cudaGetSymbolAddress((void**)&vr, g_vr);
    cudaGetSymbolAddress((void**)&attn_r, g_attn_r);

    // 1-2. rmsnorm
    rmsnorm_kernel<<<T_LEN, 256>>>(s, nsw, sn, DS);
    rmsnorm_kernel<<<ROWS_R, 256>>>(r, nrw, rn, DR);

    // 3-5. s-branch projections
    sgemm_kernel<<<dim3(DS / BN, T_LEN / BM), 256>>>(sn, Wsq, q, T_LEN, DS, DS,
                                                     nullptr, nullptr, nullptr);
    sgemm_kernel<<<dim3(DS / BN, ROWS_R / BM), 256>>>(rn, Wsk, k, ROWS_R, DS, DR,
                                                      nullptr, nullptr, nullptr);
    sgemm_kernel<<<dim3(DS / BN, ROWS_R / BM), 256>>>(rn, Wsv, v, ROWS_R, DS, DR,
                                                      nullptr, nullptr, nullptr);

    // 6. s-attention + sparse top-k
    s_attn_kernel<<<T_LEN, 256>>>(q, k, v, attn_s, rsp);

    // 7. s output: attn_s @ Wso + s + gate * r_sparse
    sgemm_kernel<<<dim3(DS / BN, T_LEN / BM), 256>>>(attn_s, Wso, out_s,
                                                     T_LEN, DS, DS,
                                                     s, rsp, gate_v);

    // 8-10. r-branch projections
    sgemm_kernel<<<dim3(DR / BN, ROWS_R / BM), 256>>>(rn, Wrq, qr, ROWS_R, DR, DR,
                                                      nullptr, nullptr, nullptr);
    sgemm_kernel<<<dim3(DR / BN, T_LEN / BM), 256>>>(sn, Wrk, kr, T_LEN, DR, DS,
                                                     nullptr, nullptr, nullptr);
    sgemm_kernel<<<dim3(DR / BN, T_LEN / BM), 256>>>(sn, Wrv, vr, T_LEN, DR, DS,
                                                     nullptr, nullptr, nullptr);

    // 11. causal r attention
    r_attn_kernel<<<dim3(T_LEN, HEADS), 256>>>(qr, kr, vr, attn_r);

    // 12. r output: attn_r @ Wro + r
    sgemm_kernel<<<dim3(DR / BN, ROWS_R / BM), 256>>>(attn_r, Wro, out_r,
                                                      ROWS_R, DR, DR,
                                                      r, nullptr, nullptr);
}

// round 4
// speedup vs baseline: 1.5064x; 1.5064x over previous
#include <cuda_runtime.h>
#include <cuda_bf16.h>
#include <math.h>
#include <stdint.h>

// ---------------- problem constants ----------------
#define T_LEN 1024
#define NSLOT 8
#define DS 1024
#define DR 512
#define HEADS 8
#define DHS 128
#define DHR 64
#define TOPK 4
#define ROWS_R (T_LEN * NSLOT)   // 8192
#define SCALE_S 0.08838834764831845f  // 1/sqrt(128)
#define SCALE_R 0.125f                // 1/sqrt(64)
#define EPS 1e-6f

// ---------------- scratch (static device memory; no allocation) -------------
__device__ float g_sn[T_LEN * DS];
__device__ float g_rn[ROWS_R * DR];
__device__ float g_q[T_LEN * DS];
__device__ float g_k[ROWS_R * DS];
__device__ float g_v[ROWS_R * DS];
__device__ float g_attn_s[T_LEN * DS];
__device__ float g_rsp[T_LEN * DS];
__device__ float g_qr[ROWS_R * DR];
__device__ float g_kr[T_LEN * DR];
__device__ float g_vr[T_LEN * DR];
__device__ float g_attn_r[ROWS_R * DR];

// ---------------- PTX helpers ----------------
__device__ __forceinline__ uint32_t smem_u32(const void* p) {
    uint32_t a;
    asm("{ .reg .u64 t; cvta.to.shared.u64 t, %1; cvt.u32.u64 %0, t; }"
        : "=r"(a) : "l"(p));
    return a;
}
__device__ __forceinline__ void cp16(uint32_t dst, const void* src) {
    asm volatile("cp.async.cg.shared.global [%0], [%1], 16;"
                 :: "r"(dst), "l"(src) : "memory");
}
__device__ __forceinline__ void mma_bf16(
    float* c, const uint32_t* a, uint32_t b0, uint32_t b1)
{
    asm volatile(
        "mma.sync.aligned.m16n8k16.row.col.f32.bf16.bf16.f32 "
        "{%0,%1,%2,%3}, {%4,%5,%6,%7}, {%8,%9}, {%0,%1,%2,%3};"
        : "+f"(c[0]), "+f"(c[1]), "+f"(c[2]), "+f"(c[3])
        : "r"(a[0]), "r"(a[1]), "r"(a[2]), "r"(a[3]), "r"(b0), "r"(b1));
}
// split pair (x,y) into packed bf16x2 hi and lo (lo = residual)
__device__ __forceinline__ void split2(float x, float y,
                                       uint32_t& hi, uint32_t& lo)
{
    __nv_bfloat162 h = __floats2bfloat162_rn(x, y);
    float xr = x - __bfloat162float(h.x);
    float yr = y - __bfloat162float(h.y);
    __nv_bfloat162 l = __floats2bfloat162_rn(xr, yr);
    hi = *(uint32_t*)&h;
    lo = *(uint32_t*)&l;
}

// ---------------- bf16x3 mma.sync GEMM ----------------
// C(MxN) = A(MxK) @ B(KxN) [+ add1] [+ rowscale*add2]
// M%128==0, N%128==0, K%16==0. 256 threads, 128x128 tile, BK=16,
// 2-stage cp.async pipeline. Warp grid 4x2, warp tile 32x64.
// Numerics: each fp32 operand split to bf16 hi+lo; products
// ah*bh + ah*bl + al*bh in fp32 accumulators (bf16x3, eps ~2^-16).
#define BM 128
#define BN 128
#define BK 16
#define A_STR 20
#define B_STR 136

__global__ __launch_bounds__(256) void mma_gemm(
    const float* __restrict__ A, const float* __restrict__ B,
    float* __restrict__ C, int M, int N, int K,
    const float* __restrict__ add1,
    const float* __restrict__ add2, const float* __restrict__ rowscale)
{
    __shared__ __align__(16) float sA[2][BM * A_STR];   // 2 x 10KB
    __shared__ __align__(16) float sB[2][BK * B_STR];   // 2 x 8.5KB

    int tid = threadIdx.x;
    int lane = tid & 31, wid = tid >> 5;
    int wm = wid >> 1, wn = wid & 1;
    int bm = blockIdx.y * BM, bn = blockIdx.x * BN;
    int gid = lane >> 2, tig = lane & 3;

    float acc[2][8][4];
    #pragma unroll
    for (int i = 0; i < 2; i++)
        #pragma unroll
        for (int j = 0; j < 8; j++)
            #pragma unroll
            for (int l = 0; l < 4; l++) acc[i][j][l] = 0.f;

    uint32_t baseA = smem_u32(sA);
    uint32_t baseB = smem_u32(sB);

    auto issue = [&](int st, int k0) {
        #pragma unroll
        for (int i = 0; i < 2; i++) {
            int f = tid + i * 256;
            int row = f >> 2, c4 = (f & 3) * 4;     // 128 rows x 16 floats
            uint32_t d = baseA + (uint32_t)(st * BM * A_STR + row * A_STR + c4) * 4;
            cp16(d, A + (size_t)(bm + row) * K + k0 + c4);
        }
        #pragma unroll
        for (int i = 0; i < 2; i++) {
            int f = tid + i * 256;
            int row = f >> 5, c4 = (f & 31) * 4;    // 16 rows x 128 floats
            uint32_t d = baseB + (uint32_t)(st * BK * B_STR + row * B_STR + c4) * 4;
            cp16(d, B + (size_t)(k0 + row) * N + bn + c4);
        }
        asm volatile("cp.async.commit_group;" ::: "memory");
    };

    int nch = K >> 4;
    issue(0, 0);

    for (int c = 0; c < nch; c++) {
        if (c + 1 < nch) {
            issue((c + 1) & 1, (c + 1) * BK);
            asm volatile("cp.async.wait_group 1;" ::: "memory");
        } else {
            asm volatile("cp.async.wait_group 0;" ::: "memory");
        }
        __syncthreads();

        const float* a_s = sA[c & 1];
        const float* b_s = sB[c & 1];

        // ---- A fragments: rows (gid, gid+8) x k (2tig..+1, 2tig+8..+9) ----
        uint32_t ah[2][4], al[2][4];
        #pragma unroll
        for (int mt = 0; mt < 2; mt++) {
            int r0 = wm * 32 + mt * 16 + gid;
            float2 x0 = *(const float2*)(a_s + r0 * A_STR + 2 * tig);
            float2 x1 = *(const float2*)(a_s + (r0 + 8) * A_STR + 2 * tig);
            float2 x2 = *(const float2*)(a_s + r0 * A_STR + 2 * tig + 8);
            float2 x3 = *(const float2*)(a_s + (r0 + 8) * A_STR + 2 * tig + 8);
            split2(x0.x, x0.y, ah[mt][0], al[mt][0]);
            split2(x1.x, x1.y, ah[mt][1], al[mt][1]);
            split2(x2.x, x2.y, ah[mt][2], al[mt][2]);
            split2(x3.x, x3.y, ah[mt][3], al[mt][3]);
        }

        #pragma unroll
        for (int nt = 0; nt < 8; nt++) {
            int n0 = wn * 64 + nt * 8 + gid;
            float y0 = b_s[(2 * tig) * B_STR + n0];
            float y1 = b_s[(2 * tig + 1) * B_STR + n0];
            float y2 = b_s[(2 * tig + 8) * B_STR + n0];
            float y3 = b_s[(2 * tig + 9) * B_STR + n0];
            uint32_t bh0, bl0, bh1, bl1;
            split2(y0, y1, bh0, bl0);
            split2(y2, y3, bh1, bl1);

            mma_bf16(acc[0][nt], ah[0], bh0, bh1);
            mma_bf16(acc[0][nt], ah[0], bl0, bl1);
            mma_bf16(acc[0][nt], al[0], bh0, bh1);
            mma_bf16(acc[1][nt], ah[1], bh0, bh1);
            mma_bf16(acc[1][nt], ah[1], bl0, bl1);
            mma_bf16(acc[1][nt], al[1], bh0, bh1);
        }
        __syncthreads();
    }

    // ---- epilogue with fused adds ----
    #pragma unroll
    for (int mt = 0; mt < 2; mt++) {
        int r0 = bm + wm * 32 + mt * 16 + gid;
        float rs0 = (rowscale != nullptr) ? rowscale[r0] : 0.f;
        float rs8 = (rowscale != nullptr) ? rowscale[r0 + 8] : 0.f;
        #pragma unroll
        for (int nt = 0; nt < 8; nt++) {
            int col = bn + wn * 64 + nt * 8 + 2 * tig;
            size_t o0 = (size_t)r0 * N + col;
            size_t o8 = (size_t)(r0 + 8) * N + col;
            float2 v0 = make_float2(acc[mt][nt][0], acc[mt][nt][1]);
            float2 v8 = make_float2(acc[mt][nt][2], acc[mt][nt][3]);
            if (add1) {
                float2 x = *(const float2*)(add1 + o0);
                v0.x += x.x; v0.y += x.y;
                x = *(const float2*)(add1 + o8);
                v8.x += x.x; v8.y += x.y;
            }
            if (add2) {
                float2 x = *(const float2*)(add2 + o0);
                v0.x += rs0 * x.x; v0.y += rs0 * x.y;
                x = *(const float2*)(add2 + o8);
                v8.x += rs8 * x.x; v8.y += rs8 * x.y;
            }
            *(float2*)(C + o0) = v0;
            *(float2*)(C + o8) = v8;
        }
    }
}

// ---------------- rmsnorm ----------------
__global__ __launch_bounds__(256) void rmsnorm_kernel(
    const float* __restrict__ x, const float* __restrict__ w,
    float* __restrict__ out, int C)
{
    int row = blockIdx.x;
    const float* xr = x + (size_t)row * C;
    float s = 0.f;
    for (int j = threadIdx.x; j < C; j += blockDim.x) {
        float v = xr[j];
        s += v * v;
    }
    __shared__ float red[8];
    int lane = threadIdx.x & 31, warp = threadIdx.x >> 5;
    #pragma unroll
    for (int off = 16; off; off >>= 1) s += __shfl_xor_sync(0xffffffffu, s, off);
    if (lane == 0) red[warp] = s;
    __syncthreads();
    __shared__ float scale;
    if (threadIdx.x == 0) {
        float tot = 0.f;
        #pragma unroll
        for (int i = 0; i < 8; i++) tot += red[i];
        scale = rsqrtf(tot / (float)C + EPS);
    }
    __syncthreads();
    float sc = scale;
    float* orow = out + (size_t)row * C;
    for (int j = threadIdx.x; j < C; j += blockDim.x)
        orow[j] = xr[j] * sc * w[j];
}

// ---------------- s-attention + top-k sparse ----------------
__global__ __launch_bounds__(256) void s_attn_kernel(
    const float* __restrict__ qmat,
    const float* __restrict__ kmat,
    const float* __restrict__ vmat,
    float* __restrict__ attn_s,
    float* __restrict__ rsp)
{
    int t = blockIdx.x;
    int tid = threadIdx.x;
    int warp = tid >> 5, lane = tid & 31;

    __shared__ float qs[DS];
    __shared__ float logits[HEADS][NSLOT];
    __shared__ float wattn[HEADS][NSLOT];
    __shared__ float wsp[NSLOT];

    for (int j = tid; j < DS; j += 256) qs[j] = qmat[(size_t)t * DS + j];
    __syncthreads();

    {
        int h = warp;
        #pragma unroll
        for (int n = 0; n < NSLOT; n++) {
            const float* krow = kmat + (size_t)(t * NSLOT + n) * DS + h * DHS;
            const float* qrow = qs + h * DHS;
            float p = 0.f;
            #pragma unroll
            for (int d = lane; d < DHS; d += 32) p += qrow[d] * krow[d];
            #pragma unroll
            for (int off = 16; off; off >>= 1) p += __shfl_xor_sync(0xffffffffu, p, off);
            if (lane == 0) logits[h][n] = p;
        }
    }
    __syncthreads();

    if (tid < HEADS) {
        int h = tid;
        float m = -INFINITY;
        #pragma unroll
        for (int n = 0; n < NSLOT; n++) m = fmaxf(m, logits[h][n] * SCALE_S);
        float s = 0.f;
        #pragma unroll
        for (int n = 0; n < NSLOT; n++) {
            float e = expf(logits[h][n] * SCALE_S - m);
            wattn[h][n] = e;
            s += e;
        }
        float inv = 1.f / s;
        #pragma unroll
        for (int n = 0; n < NSLOT; n++) wattn[h][n] *= inv;
    }
    if (tid == 8) {
        float sp[NSLOT];
        #pragma unroll
        for (int n = 0; n < NSLOT; n++) {
            float a = 0.f;
            #pragma unroll
            for (int h = 0; h < HEADS; h++) a += logits[h][n];
            sp[n] = a * SCALE_S;
        }
        bool sel[NSLOT];
        #pragma unroll
        for (int n = 0; n < NSLOT; n++) { sel[n] = false; wsp[n] = 0.f; }
        int idxs[TOPK];
        #pragma unroll
        for (int kk = 0; kk < TOPK; kk++) {
            int best = -1; float bv = -INFINITY;
            #pragma unroll
            for (int n = 0; n < NSLOT; n++)
                if (!sel[n] && sp[n] > bv) { bv = sp[n]; best = n; }
            sel[best] = true; idxs[kk] = best;
        }
        float m = -INFINITY;
        #pragma unroll
        for (int kk = 0; kk < TOPK; kk++) m = fmaxf(m, sp[idxs[kk]]);
        float s = 0.f, e[TOPK];
        #pragma unroll
        for (int kk = 0; kk < TOPK; kk++) { e[kk] = expf(sp[idxs[kk]] - m); s += e[kk]; }
        float inv = 1.f / s;
        #pragma unroll
        for (int kk = 0; kk < TOPK; kk++) wsp[idxs[kk]] = e[kk] * inv;
    }
    __syncthreads();

    for (int j = tid; j < DS; j += 256) {
        int h = j >> 7;
        float a1 = 0.f, a2 = 0.f;
        #pragma unroll
        for (int n = 0; n < NSLOT; n++) {
            float vv = vmat[(size_t)(t * NSLOT + n) * DS + j];
            a1 += wattn[h][n] * vv;
            a2 += wsp[n] * vv;
        }
        attn_s[(size_t)t * DS + j] = a1;
        rsp[(size_t)t * DS + j] = a2;
    }
}

// ---------------- causal r-attention (flash-style) ----------------
#define PT 64
__global__ __launch_bounds__(256) void r_attn_kernel(
    const float* __restrict__ qr,
    const float* __restrict__ kr,
    const float* __restrict__ vr,
    float* __restrict__ attn_r)
{
    int t = blockIdx.x;
    int h = blockIdx.y;
    int tid = threadIdx.x;
    int warp = tid >> 5, lane = tid & 31;
    int n = warp;

    __shared__ float q8[NSLOT][DHR];
    __shared__ float kt[PT][DHR + 1];
    __shared__ float vt[PT][DHR + 1];
    __shared__ float sc[NSLOT][PT];

    for (int i = tid; i < NSLOT * DHR; i += 256) {
        int nn = i >> 6, d = i & 63;
        q8[nn][d] = qr[(size_t)(t * NSLOT + nn) * DR + h * DHR + d];
    }

    float m = -INFINITY, l = 0.f;
    float acc0 = 0.f, acc1 = 0.f;

    int pmax = t;
    for (int p0 = 0; p0 <= pmax; p0 += PT) {
        int pcnt = min(PT, pmax - p0 + 1);
        __syncthreads();
        for (int i = tid; i < PT * DHR; i += 256) {
            int pr = i >> 6, d = i & 63;
            float kv = 0.f, vv = 0.f;
            if (pr < pcnt) {
                size_t off = (size_t)(p0 + pr) * DR + h * DHR + d;
                kv = kr[off];
                vv = vr[off];
            }
            kt[pr][d] = kv;
            vt[pr][d] = vv;
        }
        __syncthreads();

        float s0 = -INFINITY, s1 = -INFINITY;
        if (lane < pcnt) {
            float a = 0.f;
            #pragma unroll
            for (int d = 0; d < DHR; d++) a += q8[n][d] * kt[lane][d];
            s0 = a * SCALE_R;
        }
        if (lane + 32 < pcnt) {
            float a = 0.f;
            #pragma unroll
            for (int d = 0; d < DHR; d++) a += q8[n][d] * kt[lane + 32][d];
            s1 = a * SCALE_R;
        }
        float tmax = fmaxf(s0, s1);
        #pragma unroll
        for (int off = 16; off; off >>= 1)
            tmax = fmaxf(tmax, __shfl_xor_sync(0xffffffffu, tmax, off));
        float newm = fmaxf(m, tmax);
        float corr = expf(m - newm);
        acc0 *= corr; acc1 *= corr; l *= corr;
        float e0 = (lane < pcnt) ? expf(s0 - newm) : 0.f;
        float e1 = (lane + 32 < pcnt) ? expf(s1 - newm) : 0.f;
        sc[n][lane] = e0;
        sc[n][lane + 32] = e1;
        float esum = e0 + e1;
        #pragma unroll
        for (int off = 16; off; off >>= 1)
            esum += __shfl_xor_sync(0xffffffffu, esum, off);
        l += esum;
        m = newm;
        __syncwarp();

        for (int p = 0; p < pcnt; p++) {
            float w = sc[n][p];
            acc0 += w * vt[p][lane];
            acc1 += w * vt[p][lane + 32];
        }
    }
    float inv = 1.f / l;
    size_t base = (size_t)(t * NSLOT + n) * DR + h * DHR;
    attn_r[base + lane] = acc0 * inv;
    attn_r[base + lane + 32] = acc1 * inv;
}

// ---------------- host launch ----------------
extern "C" void kernel_launch(void* const* d_in, const int* in_sizes, int n_in,
                              void* d_out, int out_size)
{
    const float* s      = (const float*)d_in[0];
    const float* r      = (const float*)d_in[1];
    const float* gate_v = (const float*)d_in[2];
    const float* nsw    = (const float*)d_in[3];
    const float* nrw    = (const float*)d_in[4];
    const float* Wsq    = (const float*)d_in[5];
    const float* Wsk    = (const float*)d_in[6];
    const float* Wsv    = (const float*)d_in[7];
    const float* Wso    = (const float*)d_in[8];
    const float* Wrq    = (const float*)d_in[9];
    const float* Wrk    = (const float*)d_in[10];
    const float* Wrv    = (const float*)d_in[11];
    const float* Wro    = (const float*)d_in[12];

    float* out_s = (float*)d_out;
    float* out_r = (float*)d_out + T_LEN * DS;

    float *sn, *rn, *q, *k, *v, *attn_s, *rsp, *qr, *kr, *vr, *attn_r;
    cudaGetSymbolAddress((void**)&sn, g_sn);
    cudaGetSymbolAddress((void**)&rn, g_rn);
    cudaGetSymbolAddress((void**)&q, g_q);
    cudaGetSymbolAddress((void**)&k, g_k);
    cudaGetSymbolAddress((void**)&v, g_v);
    cudaGetSymbolAddress((void**)&attn_s, g_attn_s);
    cudaGetSymbolAddress((void**)&rsp, g_rsp);
    cudaGetSymbolAddress((void**)&qr, g_qr);
    cudaGetSymbolAddress((void**)&kr, g_kr);
    cudaGetSymbolAddress((void**)&vr, g_vr);
    cudaGetSymbolAddress((void**)&attn_r, g_attn_r);

    // 1-2. rmsnorm
    rmsnorm_kernel<<<T_LEN, 256>>>(s, nsw, sn, DS);
    rmsnorm_kernel<<<ROWS_R, 256>>>(r, nrw, rn, DR);

    // 3-5. s-branch projections (bf16x3 mma.sync)
    mma_gemm<<<dim3(DS / BN, T_LEN / BM), 256>>>(sn, Wsq, q, T_LEN, DS, DS,
                                                 nullptr, nullptr, nullptr);
    mma_gemm<<<dim3(DS / BN, ROWS_R / BM), 256>>>(rn, Wsk, k, ROWS_R, DS, DR,
                                                  nullptr, nullptr, nullptr);
    mma_gemm<<<dim3(DS / BN, ROWS_R / BM), 256>>>(rn, Wsv, v, ROWS_R, DS, DR,
                                                  nullptr, nullptr, nullptr);

    // 6. s-attention + sparse top-k
    s_attn_kernel<<<T_LEN, 256>>>(q, k, v, attn_s, rsp);

    // 7. s output: attn_s @ Wso + s + gate * r_sparse
    mma_gemm<<<dim3(DS / BN, T_LEN / BM), 256>>>(attn_s, Wso, out_s,
                                                 T_LEN, DS, DS,
                                                 s, rsp, gate_v);

    // 8-10. r-branch projections
    mma_gemm<<<dim3(DR / BN, ROWS_R / BM), 256>>>(rn, Wrq, qr, ROWS_R, DR, DR,
                                                  nullptr, nullptr, nullptr);
    mma_gemm<<<dim3(DR / BN, T_LEN / BM), 256>>>(sn, Wrk, kr, T_LEN, DR, DS,
                                                 nullptr, nullptr, nullptr);
    mma_gemm<<<dim3(DR / BN, T_LEN / BM), 256>>>(sn, Wrv, vr, T_LEN, DR, DS,
                                                 nullptr, nullptr, nullptr);

    // 11. causal r attention
    r_attn_kernel<<<dim3(T_LEN, HEADS), 256>>>(qr, kr, vr, attn_r);

    // 12. r output: attn_r @ Wro + r
    mma_gemm<<<dim3(DR / BN, ROWS_R / BM), 256>>>(attn_r, Wro, out_r,
                                                  ROWS_R, DR, DR,
                                                  r, nullptr, nullptr);
}

// round 5
// speedup vs baseline: 2.6729x; 1.7744x over previous
#include <cuda_runtime.h>
#include <cuda_bf16.h>
#include <math.h>
#include <stdint.h>

// ---------------- problem constants ----------------
#define T_LEN 1024
#define NSLOT 8
#define DS 1024
#define DR 512
#define HEADS 8
#define DHS 128
#define DHR 64
#define TOPK 4
#define ROWS_R (T_LEN * NSLOT)   // 8192
#define SCALE_S 0.08838834764831845f  // 1/sqrt(128)
#define SCALE_R 0.125f                // 1/sqrt(64)
#define EPS 1e-6f

// ---------------- scratch (static device memory; no allocation) -------------
__device__ float g_sn[T_LEN * DS];
__device__ float g_rn[ROWS_R * DR];
__device__ float g_q[T_LEN * DS];
__device__ float g_k[ROWS_R * DS];
__device__ float g_v[ROWS_R * DS];
__device__ float g_attn_s[T_LEN * DS];
__device__ float g_rsp[T_LEN * DS];
__device__ float g_qr[ROWS_R * DR];
__device__ float g_kr[T_LEN * DR];
__device__ float g_vr[T_LEN * DR];
__device__ float g_attn_r[ROWS_R * DR];

// ---------------- PTX helpers ----------------
__device__ __forceinline__ uint32_t smem_u32(const void* p) {
    uint32_t a;
    asm("{ .reg .u64 t; cvta.to.shared.u64 t, %1; cvt.u32.u64 %0, t; }"
        : "=r"(a) : "l"(p));
    return a;
}
__device__ __forceinline__ void cp16(uint32_t dst, const void* src) {
    asm volatile("cp.async.cg.shared.global [%0], [%1], 16;"
                 :: "r"(dst), "l"(src) : "memory");
}
__device__ __forceinline__ void mma_bf16(
    float* c, const uint32_t* a, uint32_t b0, uint32_t b1)
{
    asm volatile(
        "mma.sync.aligned.m16n8k16.row.col.f32.bf16.bf16.f32 "
        "{%0,%1,%2,%3}, {%4,%5,%6,%7}, {%8,%9}, {%0,%1,%2,%3};"
        : "+f"(c[0]), "+f"(c[1]), "+f"(c[2]), "+f"(c[3])
        : "r"(a[0]), "r"(a[1]), "r"(a[2]), "r"(a[3]), "r"(b0), "r"(b1));
}
// split pair (x,y) into packed bf16x2 hi and lo (lo = residual)
__device__ __forceinline__ void split2(float x, float y,
                                       uint32_t& hi, uint32_t& lo)
{
    __nv_bfloat162 h = __floats2bfloat162_rn(x, y);
    float xr = x - __bfloat162float(h.x);
    float yr = y - __bfloat162float(h.y);
    __nv_bfloat162 l = __floats2bfloat162_rn(xr, yr);
    hi = *(uint32_t*)&h;
    lo = *(uint32_t*)&l;
}

// ---------------- bf16x3 mma.sync GEMM (unchanged from R4) ----------------
#define BM 128
#define BN 128
#define BK 16
#define A_STR 20
#define B_STR 136

__global__ __launch_bounds__(256) void mma_gemm(
    const float* __restrict__ A, const float* __restrict__ B,
    float* __restrict__ C, int M, int N, int K,
    const float* __restrict__ add1,
    const float* __restrict__ add2, const float* __restrict__ rowscale)
{
    __shared__ __align__(16) float sA[2][BM * A_STR];
    __shared__ __align__(16) float sB[2][BK * B_STR];

    int tid = threadIdx.x;
    int lane = tid & 31, wid = tid >> 5;
    int wm = wid >> 1, wn = wid & 1;
    int bm = blockIdx.y * BM, bn = blockIdx.x * BN;
    int gid = lane >> 2, tig = lane & 3;

    float acc[2][8][4];
    #pragma unroll
    for (int i = 0; i < 2; i++)
        #pragma unroll
        for (int j = 0; j < 8; j++)
            #pragma unroll
            for (int l = 0; l < 4; l++) acc[i][j][l] = 0.f;

    uint32_t baseA = smem_u32(sA);
    uint32_t baseB = smem_u32(sB);

    auto issue = [&](int st, int k0) {
        #pragma unroll
        for (int i = 0; i < 2; i++) {
            int f = tid + i * 256;
            int row = f >> 2, c4 = (f & 3) * 4;
            uint32_t d = baseA + (uint32_t)(st * BM * A_STR + row * A_STR + c4) * 4;
            cp16(d, A + (size_t)(bm + row) * K + k0 + c4);
        }
        #pragma unroll
        for (int i = 0; i < 2; i++) {
            int f = tid + i * 256;
            int row = f >> 5, c4 = (f & 31) * 4;
            uint32_t d = baseB + (uint32_t)(st * BK * B_STR + row * B_STR + c4) * 4;
            cp16(d, B + (size_t)(k0 + row) * N + bn + c4);
        }
        asm volatile("cp.async.commit_group;" ::: "memory");
    };

    int nch = K >> 4;
    issue(0, 0);

    for (int c = 0; c < nch; c++) {
        if (c + 1 < nch) {
            issue((c + 1) & 1, (c + 1) * BK);
            asm volatile("cp.async.wait_group 1;" ::: "memory");
        } else {
            asm volatile("cp.async.wait_group 0;" ::: "memory");
        }
        __syncthreads();

        const float* a_s = sA[c & 1];
        const float* b_s = sB[c & 1];

        uint32_t ah[2][4], al[2][4];
        #pragma unroll
        for (int mt = 0; mt < 2; mt++) {
            int r0 = wm * 32 + mt * 16 + gid;
            float2 x0 = *(const float2*)(a_s + r0 * A_STR + 2 * tig);
            float2 x1 = *(const float2*)(a_s + (r0 + 8) * A_STR + 2 * tig);
            float2 x2 = *(const float2*)(a_s + r0 * A_STR + 2 * tig + 8);
            float2 x3 = *(const float2*)(a_s + (r0 + 8) * A_STR + 2 * tig + 8);
            split2(x0.x, x0.y, ah[mt][0], al[mt][0]);
            split2(x1.x, x1.y, ah[mt][1], al[mt][1]);
            split2(x2.x, x2.y, ah[mt][2], al[mt][2]);
            split2(x3.x, x3.y, ah[mt][3], al[mt][3]);
        }

        #pragma unroll
        for (int nt = 0; nt < 8; nt++) {
            int n0 = wn * 64 + nt * 8 + gid;
            float y0 = b_s[(2 * tig) * B_STR + n0];
            float y1 = b_s[(2 * tig + 1) * B_STR + n0];
            float y2 = b_s[(2 * tig + 8) * B_STR + n0];
            float y3 = b_s[(2 * tig + 9) * B_STR + n0];
            uint32_t bh0, bl0, bh1, bl1;
            split2(y0, y1, bh0, bl0);
            split2(y2, y3, bh1, bl1);

            mma_bf16(acc[0][nt], ah[0], bh0, bh1);
            mma_bf16(acc[0][nt], ah[0], bl0, bl1);
            mma_bf16(acc[0][nt], al[0], bh0, bh1);
            mma_bf16(acc[1][nt], ah[1], bh0, bh1);
            mma_bf16(acc[1][nt], ah[1], bl0, bl1);
            mma_bf16(acc[1][nt], al[1], bh0, bh1);
        }
        __syncthreads();
    }

    #pragma unroll
    for (int mt = 0; mt < 2; mt++) {
        int r0 = bm + wm * 32 + mt * 16 + gid;
        float rs0 = (rowscale != nullptr) ? rowscale[r0] : 0.f;
        float rs8 = (rowscale != nullptr) ? rowscale[r0 + 8] : 0.f;
        #pragma unroll
        for (int nt = 0; nt < 8; nt++) {
            int col = bn + wn * 64 + nt * 8 + 2 * tig;
            size_t o0 = (size_t)r0 * N + col;
            size_t o8 = (size_t)(r0 + 8) * N + col;
            float2 v0 = make_float2(acc[mt][nt][0], acc[mt][nt][1]);
            float2 v8 = make_float2(acc[mt][nt][2], acc[mt][nt][3]);
            if (add1) {
                float2 x = *(const float2*)(add1 + o0);
                v0.x += x.x; v0.y += x.y;
                x = *(const float2*)(add1 + o8);
                v8.x += x.x; v8.y += x.y;
            }
            if (add2) {
                float2 x = *(const float2*)(add2 + o0);
                v0.x += rs0 * x.x; v0.y += rs0 * x.y;
                x = *(const float2*)(add2 + o8);
                v8.x += rs8 * x.x; v8.y += rs8 * x.y;
            }
            *(float2*)(C + o0) = v0;
            *(float2*)(C + o8) = v8;
        }
    }
}

// ---------------- rmsnorm ----------------
__global__ __launch_bounds__(256) void rmsnorm_kernel(
    const float* __restrict__ x, const float* __restrict__ w,
    float* __restrict__ out, int C)
{
    int row = blockIdx.x;
    const float* xr = x + (size_t)row * C;
    float s = 0.f;
    for (int j = threadIdx.x; j < C; j += blockDim.x) {
        float v = xr[j];
        s += v * v;
    }
    __shared__ float red[8];
    int lane = threadIdx.x & 31, warp = threadIdx.x >> 5;
    #pragma unroll
    for (int off = 16; off; off >>= 1) s += __shfl_xor_sync(0xffffffffu, s, off);
    if (lane == 0) red[warp] = s;
    __syncthreads();
    __shared__ float scale;
    if (threadIdx.x == 0) {
        float tot = 0.f;
        #pragma unroll
        for (int i = 0; i < 8; i++) tot += red[i];
        scale = rsqrtf(tot / (float)C + EPS);
    }
    __syncthreads();
    float sc = scale;
    float* orow = out + (size_t)row * C;
    for (int j = threadIdx.x; j < C; j += blockDim.x)
        orow[j] = xr[j] * sc * w[j];
}

// ---------------- s-attention + top-k sparse ----------------
__global__ __launch_bounds__(256) void s_attn_kernel(
    const float* __restrict__ qmat,
    const float* __restrict__ kmat,
    const float* __restrict__ vmat,
    float* __restrict__ attn_s,
    float* __restrict__ rsp)
{
    int t = blockIdx.x;
    int tid = threadIdx.x;
    int warp = tid >> 5, lane = tid & 31;

    __shared__ float qs[DS];
    __shared__ float logits[HEADS][NSLOT];
    __shared__ float wattn[HEADS][NSLOT];
    __shared__ float wsp[NSLOT];

    for (int j = tid; j < DS; j += 256) qs[j] = qmat[(size_t)t * DS + j];
    __syncthreads();

    {
        int h = warp;
        #pragma unroll
        for (int n = 0; n < NSLOT; n++) {
            const float* krow = kmat + (size_t)(t * NSLOT + n) * DS + h * DHS;
            const float* qrow = qs + h * DHS;
            float p = 0.f;
            #pragma unroll
            for (int d = lane; d < DHS; d += 32) p += qrow[d] * krow[d];
            #pragma unroll
            for (int off = 16; off; off >>= 1) p += __shfl_xor_sync(0xffffffffu, p, off);
            if (lane == 0) logits[h][n] = p;
        }
    }
    __syncthreads();

    if (tid < HEADS) {
        int h = tid;
        float m = -INFINITY;
        #pragma unroll
        for (int n = 0; n < NSLOT; n++) m = fmaxf(m, logits[h][n] * SCALE_S);
        float s = 0.f;
        #pragma unroll
        for (int n = 0; n < NSLOT; n++) {
            float e = __expf(logits[h][n] * SCALE_S - m);
            wattn[h][n] = e;
            s += e;
        }
        float inv = 1.f / s;
        #pragma unroll
        for (int n = 0; n < NSLOT; n++) wattn[h][n] *= inv;
    }
    if (tid == 8) {
        float sp[NSLOT];
        #pragma unroll
        for (int n = 0; n < NSLOT; n++) {
            float a = 0.f;
            #pragma unroll
            for (int h = 0; h < HEADS; h++) a += logits[h][n];
            sp[n] = a * SCALE_S;
        }
        bool sel[NSLOT];
        #pragma unroll
        for (int n = 0; n < NSLOT; n++) { sel[n] = false; wsp[n] = 0.f; }
        int idxs[TOPK];
        #pragma unroll
        for (int kk = 0; kk < TOPK; kk++) {
            int best = -1; float bv = -INFINITY;
            #pragma unroll
            for (int n = 0; n < NSLOT; n++)
                if (!sel[n] && sp[n] > bv) { bv = sp[n]; best = n; }
            sel[best] = true; idxs[kk] = best;
        }
        float m = -INFINITY;
        #pragma unroll
        for (int kk = 0; kk < TOPK; kk++) m = fmaxf(m, sp[idxs[kk]]);
        float s = 0.f, e[TOPK];
        #pragma unroll
        for (int kk = 0; kk < TOPK; kk++) { e[kk] = __expf(sp[idxs[kk]] - m); s += e[kk]; }
        float inv = 1.f / s;
        #pragma unroll
        for (int kk = 0; kk < TOPK; kk++) wsp[idxs[kk]] = e[kk] * inv;
    }
    __syncthreads();

    for (int j = tid; j < DS; j += 256) {
        int h = j >> 7;
        float a1 = 0.f, a2 = 0.f;
        #pragma unroll
        for (int n = 0; n < NSLOT; n++) {
            float vv = vmat[(size_t)(t * NSLOT + n) * DS + j];
            a1 += wattn[h][n] * vv;
            a2 += wsp[n] * vv;
        }
        attn_s[(size_t)t * DS + j] = a1;
        rsp[(size_t)t * DS + j] = a2;
    }
}

// ---------------- causal r-attention: MMA flash kernel ----------------
// Block = (8-token tile tt, head h). 128 threads = 4 warps; warp w owns
// 16 query rows (global qr rows t0*8 + 16w .. +16). K tiles of 64 positions.
// QK and PV via bf16x3 m16n8k16. Causal mask only on diagonal tile.
#define KSTR 33   // padded u32 stride for split smem tiles

__global__ __launch_bounds__(128) void r_attn_mma(
    const float* __restrict__ qr,   // (T*N, DR)
    const float* __restrict__ kr,   // (T, DR)
    const float* __restrict__ vr,   // (T, DR)
    float* __restrict__ attn_r)     // (T*N, DR)
{
    __shared__ uint32_t khi[64 * KSTR], klo[64 * KSTR];
    __shared__ uint32_t vhi[64 * KSTR], vlo[64 * KSTR];

    int tt = (int)(gridDim.x - 1 - blockIdx.x);  // long blocks first
    int h = blockIdx.y;
    int t0 = tt * 8;
    int hb = h * DHR;

    int tid = threadIdx.x;
    int w = tid >> 5, lane = tid & 31;
    int gid = lane >> 2, tig = lane & 3;

    // ---- Q fragments (scaled by SCALE_R), split to bf16 hi/lo ----
    int r0 = t0 * 8 + 16 * w + gid;   // global qr row for frag-row "gid"
    int r8 = r0 + 8;
    uint32_t qh[4][4], ql[4][4];
    #pragma unroll
    for (int kc = 0; kc < 4; kc++) {
        float2 x0 = *(const float2*)(qr + (size_t)r0 * DR + hb + kc * 16 + 2 * tig);
        float2 x1 = *(const float2*)(qr + (size_t)r8 * DR + hb + kc * 16 + 2 * tig);
        float2 x2 = *(const float2*)(qr + (size_t)r0 * DR + hb + kc * 16 + 2 * tig + 8);
        float2 x3 = *(const float2*)(qr + (size_t)r8 * DR + hb + kc * 16 + 2 * tig + 8);
        split2(x0.x * SCALE_R, x0.y * SCALE_R, qh[kc][0], ql[kc][0]);
        split2(x1.x * SCALE_R, x1.y * SCALE_R, qh[kc][1], ql[kc][1]);
        split2(x2.x * SCALE_R, x2.y * SCALE_R, qh[kc][2], ql[kc][2]);
        split2(x3.x * SCALE_R, x3.y * SCALE_R, qh[kc][3], ql[kc][3]);
    }
    int tok0 = t0 + ((16 * w + gid) >> 3);       // token of frag-row gid
    int tok8 = t0 + ((16 * w + gid + 8) >> 3);   // token of frag-row gid+8

    float m0 = -INFINITY, m1 = -INFINITY, l0 = 0.f, l1 = 0.f;
    float acco[8][4];
    #pragma unroll
    for (int i = 0; i < 8; i++)
        #pragma unroll
        for (int j = 0; j < 4; j++) acco[i][j] = 0.f;

    int plast = t0 + 7;
    for (int p0 = 0; p0 <= plast; p0 += 64) {
        __syncthreads();
        // ---- convert K tile: [pos][dims] fp32 -> split bf16 pairs ----
        #pragma unroll
        for (int it = 0; it < 8; it++) {
            int idx = tid + it * 128;            // 0..1023
            int p = idx >> 4, c4 = idx & 15;
            float4 kv = *(const float4*)(kr + (size_t)(p0 + p) * DR + hb + c4 * 4);
            uint32_t h0, lo0, h1, lo1;
            split2(kv.x, kv.y, h0, lo0);
            split2(kv.z, kv.w, h1, lo1);
            khi[p * KSTR + c4 * 2] = h0;
            khi[p * KSTR + c4 * 2 + 1] = h1;
            klo[p * KSTR + c4 * 2] = lo0;
            klo[p * KSTR + c4 * 2 + 1] = lo1;
        }
        // ---- convert V tile transposed: pack adjacent positions per dim ----
        #pragma unroll
        for (int it = 0; it < 16; it++) {
            int idx = tid + it * 128;            // 0..2047
            int d = idx & 63, pp = idx >> 6;     // pp 0..31
            float v0 = vr[(size_t)(p0 + 2 * pp) * DR + hb + d];
            float v1 = vr[(size_t)(p0 + 2 * pp + 1) * DR + hb + d];
            uint32_t hh, ll;
            split2(v0, v1, hh, ll);
            vhi[d * KSTR + pp] = hh;
            vlo[d * KSTR + pp] = ll;
        }
        __syncthreads();

        // ---- QK: scores s[nt][4] over 64 positions ----
        float s[8][4];
        #pragma unroll
        for (int i = 0; i < 8; i++)
            #pragma unroll
            for (int j = 0; j < 4; j++) s[i][j] = 0.f;

        #pragma unroll
        for (int nt = 0; nt < 8; nt++) {
            int n0 = nt * 8 + gid;
            #pragma unroll
            for (int kc = 0; kc < 4; kc++) {
                uint32_t bh0 = khi[n0 * KSTR + kc * 8 + tig];
                uint32_t bh1 = khi[n0 * KSTR + kc * 8 + tig + 4];
                uint32_t bl0 = klo[n0 * KSTR + kc * 8 + tig];
                uint32_t bl1 = klo[n0 * KSTR + kc * 8 + tig + 4];
                mma_bf16(s[nt], qh[kc], bh0, bh1);
                mma_bf16(s[nt], qh[kc], bl0, bl1);
                mma_bf16(s[nt], ql[kc], bh0, bh1);
            }
        }

        // ---- causal mask (diagonal tile only) ----
        if (p0 + 64 > t0) {
            #pragma unroll
            for (int nt = 0; nt < 8; nt++) {
                int pg = p0 + nt * 8 + 2 * tig;
                if (pg > tok0)     s[nt][0] = -INFINITY;
                if (pg + 1 > tok0) s[nt][1] = -INFINITY;
                if (pg > tok8)     s[nt][2] = -INFINITY;
                if (pg + 1 > tok8) s[nt][3] = -INFINITY;
            }
        }

        // ---- online softmax ----
        float mx0 = -INFINITY, mx1 = -INFINITY;
        #pragma unroll
        for (int nt = 0; nt < 8; nt++) {
            mx0 = fmaxf(mx0, fmaxf(s[nt][0], s[nt][1]));
            mx1 = fmaxf(mx1, fmaxf(s[nt][2], s[nt][3]));
        }
        mx0 = fmaxf(mx0, __shfl_xor_sync(0xffffffffu, mx0, 1));
        mx0 = fmaxf(mx0, __shfl_xor_sync(0xffffffffu, mx0, 2));
        mx1 = fmaxf(mx1, __shfl_xor_sync(0xffffffffu, mx1, 1));
        mx1 = fmaxf(mx1, __shfl_xor_sync(0xffffffffu, mx1, 2));
        float nm0 = fmaxf(m0, mx0), nm1 = fmaxf(m1, mx1);
        float cr0 = __expf(m0 - nm0), cr1 = __expf(m1 - nm1);
        m0 = nm0; m1 = nm1;

        float rs0 = 0.f, rs1 = 0.f;
        #pragma unroll
        for (int nt = 0; nt < 8; nt++) {
            s[nt][0] = __expf(s[nt][0] - nm0);
            s[nt][1] = __expf(s[nt][1] - nm0);
            s[nt][2] = __expf(s[nt][2] - nm1);
            s[nt][3] = __expf(s[nt][3] - nm1);
            rs0 += s[nt][0] + s[nt][1];
            rs1 += s[nt][2] + s[nt][3];
        }
        rs0 += __shfl_xor_sync(0xffffffffu, rs0, 1);
        rs0 += __shfl_xor_sync(0xffffffffu, rs0, 2);
        rs1 += __shfl_xor_sync(0xffffffffu, rs1, 1);
        rs1 += __shfl_xor_sync(0xffffffffu, rs1, 2);
        l0 = l0 * cr0 + rs0;
        l1 = l1 * cr1 + rs1;

        #pragma unroll
        for (int ntd = 0; ntd < 8; ntd++) {
            acco[ntd][0] *= cr0; acco[ntd][1] *= cr0;
            acco[ntd][2] *= cr1; acco[ntd][3] *= cr1;
        }

        // ---- PV: out += P @ V ----
        #pragma unroll
        for (int kc = 0; kc < 4; kc++) {
            uint32_t pah[4], pal[4];
            split2(s[2 * kc][0],     s[2 * kc][1],     pah[0], pal[0]);
            split2(s[2 * kc][2],     s[2 * kc][3],     pah[1], pal[1]);
            split2(s[2 * kc + 1][0], s[2 * kc + 1][1], pah[2], pal[2]);
            split2(s[2 * kc + 1][2], s[2 * kc + 1][3], pah[3], pal[3]);
            #pragma unroll
            for (int ntd = 0; ntd < 8; ntd++) {
                int d0 = ntd * 8 + gid;
                uint32_t bh0 = vhi[d0 * KSTR + kc * 8 + tig];
                uint32_t bh1 = vhi[d0 * KSTR + kc * 8 + tig + 4];
                uint32_t bl0 = vlo[d0 * KSTR + kc * 8 + tig];
                uint32_t bl1 = vlo[d0 * KSTR + kc * 8 + tig + 4];
                mma_bf16(acco[ntd], pah, bh0, bh1);
                mma_bf16(acco[ntd], pah, bl0, bl1);
                mma_bf16(acco[ntd], pal, bh0, bh1);
            }
        }
    }

    // ---- normalize + store ----
    float i0 = 1.f / l0, i1 = 1.f / l1;
    #pragma unroll
    for (int ntd = 0; ntd < 8; ntd++) {
        int col = hb + ntd * 8 + 2 * tig;
        *(float2*)(attn_r + (size_t)r0 * DR + col) =
            make_float2(acco[ntd][0] * i0, acco[ntd][1] * i0);
        *(float2*)(attn_r + (size_t)r8 * DR + col) =
            make_float2(acco[ntd][2] * i1, acco[ntd][3] * i1);
    }
}

// ---------------- host launch ----------------
extern "C" void kernel_launch(void* const* d_in, const int* in_sizes, int n_in,
                              void* d_out, int out_size)
{
    const float* s      = (const float*)d_in[0];
    const float* r      = (const float*)d_in[1];
    const float* gate_v = (const float*)d_in[2];
    const float* nsw    = (const float*)d_in[3];
    const float* nrw    = (const float*)d_in[4];
    const float* Wsq    = (const float*)d_in[5];
    const float* Wsk    = (const float*)d_in[6];
    const float* Wsv    = (const float*)d_in[7];
    const float* Wso    = (const float*)d_in[8];
    const float* Wrq    = (const float*)d_in[9];
    const float* Wrk    = (const float*)d_in[10];
    const float* Wrv    = (const float*)d_in[11];
    const float* Wro    = (const float*)d_in[12];

    float* out_s = (float*)d_out;
    float* out_r = (float*)d_out + T_LEN * DS;

    float *sn, *rn, *q, *k, *v, *attn_s, *rsp, *qr, *kr, *vr, *attn_r;
    cudaGetSymbolAddress((void**)&sn, g_sn);
    cudaGetSymbolAddress((void**)&rn, g_rn);
    cudaGetSymbolAddress((void**)&q, g_q);
    cudaGetSymbolAddress((void**)&k, g_k);
    cudaGetSymbolAddress((void**)&v, g_v);
    cudaGetSymbolAddress((void**)&attn_s, g_attn_s);
    cudaGetSymbolAddress((void**)&rsp, g_rsp);
    cudaGetSymbolAddress((void**)&qr, g_qr);
    cudaGetSymbolAddress((void**)&kr, g_kr);
    cudaGetSymbolAddress((void**)&vr, g_vr);
    cudaGetSymbolAddress((void**)&attn_r, g_attn_r);

    // 1-2. rmsnorm
    rmsnorm_kernel<<<T_LEN, 256>>>(s, nsw, sn, DS);
    rmsnorm_kernel<<<ROWS_R, 256>>>(r, nrw, rn, DR);

    // 3-5. s-branch projections (bf16x3 mma.sync)
    mma_gemm<<<dim3(DS / BN, T_LEN / BM), 256>>>(sn, Wsq, q, T_LEN, DS, DS,
                                                 nullptr, nullptr, nullptr);
    mma_gemm<<<dim3(DS / BN, ROWS_R / BM), 256>>>(rn, Wsk, k, ROWS_R, DS, DR,
                                                  nullptr, nullptr, nullptr);
    mma_gemm<<<dim3(DS / BN, ROWS_R / BM), 256>>>(rn, Wsv, v, ROWS_R, DS, DR,
                                                  nullptr, nullptr, nullptr);

    // 6. s-attention + sparse top-k
    s_attn_kernel<<<T_LEN, 256>>>(q, k, v, attn_s, rsp);

    // 7. s output: attn_s @ Wso + s + gate * r_sparse
    mma_gemm<<<dim3(DS / BN, T_LEN / BM), 256>>>(attn_s, Wso, out_s,
                                                 T_LEN, DS, DS,
                                                 s, rsp, gate_v);

    // 8-10. r-branch projections
    mma_gemm<<<dim3(DR / BN, ROWS_R / BM), 256>>>(rn, Wrq, qr, ROWS_R, DR, DR,
                                                  nullptr, nullptr, nullptr);
    mma_gemm<<<dim3(DR / BN, T_LEN / BM), 256>>>(sn, Wrk, kr, T_LEN, DR, DS,
                                                 nullptr, nullptr, nullptr);
    mma_gemm<<<dim3(DR / BN, T_LEN / BM), 256>>>(sn, Wrv, vr, T_LEN, DR, DS,
                                                 nullptr, nullptr, nullptr);

    // 11. causal r attention (MMA flash)
    r_attn_mma<<<dim3(T_LEN / 8, HEADS), 128>>>(qr, kr, vr, attn_r);

    // 12. r output: attn_r @ Wro + r
    mma_gemm<<<dim3(DR / BN, ROWS_R / BM), 256>>>(attn_r, Wro, out_r,
                                                  ROWS_R, DR, DR,
                                                  r, nullptr, nullptr);
}

// round 6
// speedup vs baseline: 3.0360x; 1.1358x over previous
#include <cuda_runtime.h>
#include <cuda_bf16.h>
#include <math.h>
#include <stdint.h>

// ---------------- problem constants ----------------
#define T_LEN 1024
#define NSLOT 8
#define DS 1024
#define DR 512
#define HEADS 8
#define DHS 128
#define DHR 64
#define TOPK 4
#define ROWS_R (T_LEN * NSLOT)   // 8192
#define SCALE_S 0.08838834764831845f  // 1/sqrt(128)
#define SCALE_R 0.125f                // 1/sqrt(64)
#define EPS 1e-6f

// weight arena offsets (elements, transposed (N,K) layouts)
#define OWSQ 0
#define OWSK 1048576
#define OWSV 1572864
#define OWSO 2097152
#define OWRQ 3145728
#define OWRK 3407872
#define OWRV 3932160
#define OWRO 4456448
#define WTOT 4718592

// ---------------- scratch (static device memory; no allocation) -------------
__device__ __nv_bfloat16 g_sn_h[T_LEN * DS], g_sn_l[T_LEN * DS];
__device__ __nv_bfloat16 g_rn_h[ROWS_R * DR], g_rn_l[ROWS_R * DR];
__device__ __nv_bfloat16 g_as_h[T_LEN * DS], g_as_l[T_LEN * DS];
__device__ __nv_bfloat16 g_ar_h[ROWS_R * DR], g_ar_l[ROWS_R * DR];
__device__ __nv_bfloat16 g_wth[WTOT], g_wtl[WTOT];
__device__ float g_q[T_LEN * DS];
__device__ float g_k[ROWS_R * DS];
__device__ float g_v[ROWS_R * DS];
__device__ float g_rsp[T_LEN * DS];
__device__ float g_qr[ROWS_R * DR];
__device__ float g_kr[T_LEN * DR];
__device__ float g_vr[T_LEN * DR];
__device__ uint32_t g_kh[T_LEN * 256], g_kl[T_LEN * 256];
__device__ uint32_t g_vth[HEADS * DHR * (T_LEN / 2)];   // [h][d][pp]
__device__ uint32_t g_vtl[HEADS * DHR * (T_LEN / 2)];

// ---------------- PTX helpers ----------------
__device__ __forceinline__ uint32_t smem_u32(const void* p) {
    uint32_t a;
    asm("{ .reg .u64 t; cvta.to.shared.u64 t, %1; cvt.u32.u64 %0, t; }"
        : "=r"(a) : "l"(p));
    return a;
}
__device__ __forceinline__ void cp16(uint32_t dst, const void* src) {
    asm volatile("cp.async.cg.shared.global [%0], [%1], 16;"
                 :: "r"(dst), "l"(src) : "memory");
}
__device__ __forceinline__ void mma_bf16(
    float* c, const uint32_t* a, uint32_t b0, uint32_t b1)
{
    asm volatile(
        "mma.sync.aligned.m16n8k16.row.col.f32.bf16.bf16.f32 "
        "{%0,%1,%2,%3}, {%4,%5,%6,%7}, {%8,%9}, {%0,%1,%2,%3};"
        : "+f"(c[0]), "+f"(c[1]), "+f"(c[2]), "+f"(c[3])
        : "r"(a[0]), "r"(a[1]), "r"(a[2]), "r"(a[3]), "r"(b0), "r"(b1));
}
__device__ __forceinline__ void split2(float x, float y,
                                       uint32_t& hi, uint32_t& lo)
{
    __nv_bfloat162 h = __floats2bfloat162_rn(x, y);
    float xr = x - __bfloat162float(h.x);
    float yr = y - __bfloat162float(h.y);
    __nv_bfloat162 l = __floats2bfloat162_rn(xr, yr);
    hi = *(uint32_t*)&h;
    lo = *(uint32_t*)&l;
}

// ---------------- weight transpose + split: W (K,N) -> Wt hi/lo (N,K) -------
__global__ __launch_bounds__(256) void wtrans_split(
    const float* __restrict__ W,
    __nv_bfloat16* __restrict__ th, __nv_bfloat16* __restrict__ tl,
    int K, int N)
{
    __shared__ float t[32][33];
    int bx = blockIdx.x * 32;   // N dim
    int by = blockIdx.y * 32;   // K dim
    int tx = threadIdx.x & 31, ty = threadIdx.x >> 5;  // (32, 8)
    #pragma unroll
    for (int i = 0; i < 4; i++)
        t[ty + i * 8][tx] = W[(size_t)(by + ty + i * 8) * N + bx + tx];
    __syncthreads();
    #pragma unroll
    for (int i = 0; i < 4; i++) {
        int n = bx + ty + i * 8;
        int k = by + tx;
        float v = t[tx][ty + i * 8];
        __nv_bfloat16 h = __float2bfloat16(v);
        th[(size_t)n * K + k] = h;
        tl[(size_t)n * K + k] = __float2bfloat16(v - __bfloat162float(h));
    }
}

// ---------------- rmsnorm with split bf16 output ----------------
__global__ __launch_bounds__(256) void rmsnorm_split(
    const float* __restrict__ x, const float* __restrict__ w,
    __nv_bfloat16* __restrict__ oh, __nv_bfloat16* __restrict__ ol, int C)
{
    int row = blockIdx.x;
    const float* xr = x + (size_t)row * C;
    float s = 0.f;
    for (int j = threadIdx.x; j < C; j += 256) {
        float v = xr[j];
        s += v * v;
    }
    __shared__ float red[8];
    int lane = threadIdx.x & 31, warp = threadIdx.x >> 5;
    #pragma unroll
    for (int off = 16; off; off >>= 1) s += __shfl_xor_sync(0xffffffffu, s, off);
    if (lane == 0) red[warp] = s;
    __syncthreads();
    __shared__ float scale;
    if (threadIdx.x == 0) {
        float tot = 0.f;
        #pragma unroll
        for (int i = 0; i < 8; i++) tot += red[i];
        scale = rsqrtf(tot / (float)C + EPS);
    }
    __syncthreads();
    float sc = scale;
    uint32_t* ph = (uint32_t*)(oh + (size_t)row * C);
    uint32_t* pl = (uint32_t*)(ol + (size_t)row * C);
    for (int j2 = threadIdx.x; j2 < C / 2; j2 += 256) {
        float v0 = xr[2 * j2] * sc * w[2 * j2];
        float v1 = xr[2 * j2 + 1] * sc * w[2 * j2 + 1];
        uint32_t h, l;
        split2(v0, v1, h, l);
        ph[j2] = h;
        pl[j2] = l;
    }
}

// ---------------- bf16-split mma GEMM ----------------
// C(MxN) = A(MxK) @ Bt(N,K)^T [+ add1] [+ rowscale*add2]
// A given as hi/lo bf16 (M,K); Bt as hi/lo bf16 (N,K). K%16==0, M,N%128==0.
__global__ __launch_bounds__(256) void mma_gemm_bf(
    const __nv_bfloat16* __restrict__ Ah, const __nv_bfloat16* __restrict__ Al,
    const __nv_bfloat16* __restrict__ Bh, const __nv_bfloat16* __restrict__ Bl,
    float* __restrict__ C, int M, int N, int K,
    const float* __restrict__ add1,
    const float* __restrict__ add2, const float* __restrict__ rowscale)
{
    __shared__ __align__(16) uint32_t sAh[2][128 * 8], sAl[2][128 * 8];
    __shared__ __align__(16) uint32_t sBh[2][128 * 8], sBl[2][128 * 8];

    int tid = threadIdx.x;
    int lane = tid & 31, wid = tid >> 5;
    int wm = wid >> 1, wn = wid & 1;
    int bm = blockIdx.y * 128, bn = blockIdx.x * 128;
    int gid = lane >> 2, tig = lane & 3;

    float acc[2][8][4];
    #pragma unroll
    for (int i = 0; i < 2; i++)
        #pragma unroll
        for (int j = 0; j < 8; j++)
            #pragma unroll
            for (int l = 0; l < 4; l++) acc[i][j][l] = 0.f;

    uint32_t bAh = smem_u32(sAh), bAl = smem_u32(sAl);
    uint32_t bBh = smem_u32(sBh), bBl = smem_u32(sBl);

    int row = tid >> 1;           // 0..127
    int gg = tid & 1;             // 16B granule within row
    auto issue = [&](int st, int k0) {
        uint32_t doff = (uint32_t)(st * 128 * 8 + row * 8 + gg * 4) * 4;
        size_t asrc = (size_t)(bm + row) * K + k0 + gg * 8;
        size_t bsrc = (size_t)(bn + row) * K + k0 + gg * 8;
        cp16(bAh + doff, Ah + asrc);
        cp16(bAl + doff, Al + asrc);
        cp16(bBh + doff, Bh + bsrc);
        cp16(bBl + doff, Bl + bsrc);
        asm volatile("cp.async.commit_group;" ::: "memory");
    };

    int nch = K >> 4;
    issue(0, 0);

    for (int c = 0; c < nch; c++) {
        if (c + 1 < nch) {
            issue((c + 1) & 1, (c + 1) * 16);
            asm volatile("cp.async.wait_group 1;" ::: "memory");
        } else {
            asm volatile("cp.async.wait_group 0;" ::: "memory");
        }
        __syncthreads();

        const uint32_t* ah_s = sAh[c & 1];
        const uint32_t* al_s = sAl[c & 1];
        const uint32_t* bh_s = sBh[c & 1];
        const uint32_t* bl_s = sBl[c & 1];

        uint32_t ah[2][4], al[2][4];
        #pragma unroll
        for (int mt = 0; mt < 2; mt++) {
            int r0 = wm * 32 + mt * 16 + gid;
            ah[mt][0] = ah_s[r0 * 8 + tig];
            ah[mt][1] = ah_s[(r0 + 8) * 8 + tig];
            ah[mt][2] = ah_s[r0 * 8 + tig + 4];
            ah[mt][3] = ah_s[(r0 + 8) * 8 + tig + 4];
            al[mt][0] = al_s[r0 * 8 + tig];
            al[mt][1] = al_s[(r0 + 8) * 8 + tig];
            al[mt][2] = al_s[r0 * 8 + tig + 4];
            al[mt][3] = al_s[(r0 + 8) * 8 + tig + 4];
        }

        #pragma unroll
        for (int nt = 0; nt < 8; nt++) {
            int n0 = wn * 64 + nt * 8 + gid;
            uint32_t bh0 = bh_s[n0 * 8 + tig];
            uint32_t bh1 = bh_s[n0 * 8 + tig + 4];
            uint32_t bl0 = bl_s[n0 * 8 + tig];
            uint32_t bl1 = bl_s[n0 * 8 + tig + 4];
            mma_bf16(acc[0][nt], ah[0], bh0, bh1);
            mma_bf16(acc[0][nt], ah[0], bl0, bl1);
            mma_bf16(acc[0][nt], al[0], bh0, bh1);
            mma_bf16(acc[1][nt], ah[1], bh0, bh1);
            mma_bf16(acc[1][nt], ah[1], bl0, bl1);
            mma_bf16(acc[1][nt], al[1], bh0, bh1);
        }
        __syncthreads();
    }

    #pragma unroll
    for (int mt = 0; mt < 2; mt++) {
        int r0 = bm + wm * 32 + mt * 16 + gid;
        float rs0 = (rowscale != nullptr) ? rowscale[r0] : 0.f;
        float rs8 = (rowscale != nullptr) ? rowscale[r0 + 8] : 0.f;
        #pragma unroll
        for (int nt = 0; nt < 8; nt++) {
            int col = bn + wn * 64 + nt * 8 + 2 * tig;
            size_t o0 = (size_t)r0 * N + col;
            size_t o8 = (size_t)(r0 + 8) * N + col;
            float2 v0 = make_float2(acc[mt][nt][0], acc[mt][nt][1]);
            float2 v8 = make_float2(acc[mt][nt][2], acc[mt][nt][3]);
            if (add1) {
                float2 x = *(const float2*)(add1 + o0);
                v0.x += x.x; v0.y += x.y;
                x = *(const float2*)(add1 + o8);
                v8.x += x.x; v8.y += x.y;
            }
            if (add2) {
                float2 x = *(const float2*)(add2 + o0);
                v0.x += rs0 * x.x; v0.y += rs0 * x.y;
                x = *(const float2*)(add2 + o8);
                v8.x += rs8 * x.x; v8.y += rs8 * x.y;
            }
            *(float2*)(C + o0) = v0;
            *(float2*)(C + o8) = v8;
        }
    }
}

// ---------------- s-attention + top-k sparse (split bf16 output) ------------
__global__ __launch_bounds__(256) void s_attn_kernel(
    const float* __restrict__ qmat,
    const float* __restrict__ kmat,
    const float* __restrict__ vmat,
    __nv_bfloat16* __restrict__ as_h,
    __nv_bfloat16* __restrict__ as_l,
    float* __restrict__ rsp)
{
    int t = blockIdx.x;
    int tid = threadIdx.x;
    int warp = tid >> 5, lane = tid & 31;

    __shared__ float qs[DS];
    __shared__ float logits[HEADS][NSLOT];
    __shared__ float wattn[HEADS][NSLOT];
    __shared__ float wsp[NSLOT];

    for (int j = tid; j < DS; j += 256) qs[j] = qmat[(size_t)t * DS + j];
    __syncthreads();

    {
        int h = warp;
        #pragma unroll
        for (int n = 0; n < NSLOT; n++) {
            const float* krow = kmat + (size_t)(t * NSLOT + n) * DS + h * DHS;
            const float* qrow = qs + h * DHS;
            float p = 0.f;
            #pragma unroll
            for (int d = lane; d < DHS; d += 32) p += qrow[d] * krow[d];
            #pragma unroll
            for (int off = 16; off; off >>= 1) p += __shfl_xor_sync(0xffffffffu, p, off);
            if (lane == 0) logits[h][n] = p;
        }
    }
    __syncthreads();

    if (tid < HEADS) {
        int h = tid;
        float m = -INFINITY;
        #pragma unroll
        for (int n = 0; n < NSLOT; n++) m = fmaxf(m, logits[h][n] * SCALE_S);
        float s = 0.f;
        #pragma unroll
        for (int n = 0; n < NSLOT; n++) {
            float e = __expf(logits[h][n] * SCALE_S - m);
            wattn[h][n] = e;
            s += e;
        }
        float inv = 1.f / s;
        #pragma unroll
        for (int n = 0; n < NSLOT; n++) wattn[h][n] *= inv;
    }
    if (tid == 8) {
        float sp[NSLOT];
        #pragma unroll
        for (int n = 0; n < NSLOT; n++) {
            float a = 0.f;
            #pragma unroll
            for (int h = 0; h < HEADS; h++) a += logits[h][n];
            sp[n] = a * SCALE_S;
        }
        bool sel[NSLOT];
        #pragma unroll
        for (int n = 0; n < NSLOT; n++) { sel[n] = false; wsp[n] = 0.f; }
        int idxs[TOPK];
        #pragma unroll
        for (int kk = 0; kk < TOPK; kk++) {
            int best = -1; float bv = -INFINITY;
            #pragma unroll
            for (int n = 0; n < NSLOT; n++)
                if (!sel[n] && sp[n] > bv) { bv = sp[n]; best = n; }
            sel[best] = true; idxs[kk] = best;
        }
        float m = -INFINITY;
        #pragma unroll
        for (int kk = 0; kk < TOPK; kk++) m = fmaxf(m, sp[idxs[kk]]);
        float s = 0.f, e[TOPK];
        #pragma unroll
        for (int kk = 0; kk < TOPK; kk++) { e[kk] = __expf(sp[idxs[kk]] - m); s += e[kk]; }
        float inv = 1.f / s;
        #pragma unroll
        for (int kk = 0; kk < TOPK; kk++) wsp[idxs[kk]] = e[kk] * inv;
    }
    __syncthreads();

    uint32_t* ph = (uint32_t*)(as_h + (size_t)t * DS);
    uint32_t* pl = (uint32_t*)(as_l + (size_t)t * DS);
    for (int j2 = tid; j2 < DS / 2; j2 += 256) {
        int j = 2 * j2;
        int h = j >> 7;
        float a0 = 0.f, a1 = 0.f, b0 = 0.f, b1 = 0.f;
        #pragma unroll
        for (int n = 0; n < NSLOT; n++) {
            float2 vv = *(const float2*)(vmat + (size_t)(t * NSLOT + n) * DS + j);
            a0 += wattn[h][n] * vv.x;
            a1 += wattn[h][n] * vv.y;
            b0 += wsp[n] * vv.x;
            b1 += wsp[n] * vv.y;
        }
        uint32_t hh, ll;
        split2(a0, a1, hh, ll);
        ph[j2] = hh;
        pl[j2] = ll;
        *(float2*)(rsp + (size_t)t * DS + j) = make_float2(b0, b1);
    }
}

// ---------------- K/V pre-split converts for r-attention ----------------
__global__ __launch_bounds__(256) void conv_k(
    const float* __restrict__ kr, uint32_t* __restrict__ kh,
    uint32_t* __restrict__ kl)
{
    int t = blockIdx.x, j = threadIdx.x;   // j < 256 (u32 pairs per row)
    float2 v = *(const float2*)(kr + (size_t)t * DR + 2 * j);
    uint32_t h, l;
    split2(v.x, v.y, h, l);
    kh[(size_t)t * 256 + j] = h;
    kl[(size_t)t * 256 + j] = l;
}
__global__ __launch_bounds__(256) void conv_vt(
    const float* __restrict__ vr, uint32_t* __restrict__ vh,
    uint32_t* __restrict__ vl)
{
    int idx = blockIdx.x * 256 + threadIdx.x;  // h*32768 + d*512 + pp
    int pp = idx & 511;
    int d = (idx >> 9) & 63;
    int h = idx >> 15;
    float v0 = vr[(size_t)(2 * pp) * DR + h * DHR + d];
    float v1 = vr[(size_t)(2 * pp + 1) * DR + h * DHR + d];
    uint32_t hh, ll;
    split2(v0, v1, hh, ll);
    vh[idx] = hh;
    vl[idx] = ll;
}

// ---------------- causal r-attention: MMA flash, pre-split K/V --------------
__global__ __launch_bounds__(128) void r_attn_mma(
    const float* __restrict__ qr,
    const uint32_t* __restrict__ kh_g, const uint32_t* __restrict__ kl_g,
    const uint32_t* __restrict__ vh_g, const uint32_t* __restrict__ vl_g,
    __nv_bfloat16* __restrict__ ar_h, __nv_bfloat16* __restrict__ ar_l)
{
    __shared__ __align__(16) uint32_t skh[64 * 32], skl[64 * 32];
    __shared__ __align__(16) uint32_t svh[64 * 32], svl[64 * 32];

    int tt = (int)(gridDim.x - 1 - blockIdx.x);
    int h = blockIdx.y;
    int t0 = tt * 8;
    int hb = h * DHR;

    int tid = threadIdx.x;
    int w = tid >> 5, lane = tid & 31;
    int gid = lane >> 2, tig = lane & 3;

    uint32_t bkh = smem_u32(skh), bkl = smem_u32(skl);
    uint32_t bvh = smem_u32(svh), bvl = smem_u32(svl);

    // ---- Q fragments (scaled), split once ----
    int r0 = t0 * 8 + 16 * w + gid;
    int r8 = r0 + 8;
    uint32_t qh[4][4], ql[4][4];
    #pragma unroll
    for (int kc = 0; kc < 4; kc++) {
        float2 x0 = *(const float2*)(qr + (size_t)r0 * DR + hb + kc * 16 + 2 * tig);
        float2 x1 = *(const float2*)(qr + (size_t)r8 * DR + hb + kc * 16 + 2 * tig);
        float2 x2 = *(const float2*)(qr + (size_t)r0 * DR + hb + kc * 16 + 2 * tig + 8);
        float2 x3 = *(const float2*)(qr + (size_t)r8 * DR + hb + kc * 16 + 2 * tig + 8);
        split2(x0.x * SCALE_R, x0.y * SCALE_R, qh[kc][0], ql[kc][0]);
        split2(x1.x * SCALE_R, x1.y * SCALE_R, qh[kc][1], ql[kc][1]);
        split2(x2.x * SCALE_R, x2.y * SCALE_R, qh[kc][2], ql[kc][2]);
        split2(x3.x * SCALE_R, x3.y * SCALE_R, qh[kc][3], ql[kc][3]);
    }
    int tok0 = t0 + ((16 * w + gid) >> 3);
    int tok8 = t0 + ((16 * w + gid + 8) >> 3);

    float m0 = -INFINITY, m1 = -INFINITY, l0 = 0.f, l1 = 0.f;
    float acco[8][4];
    #pragma unroll
    for (int i = 0; i < 8; i++)
        #pragma unroll
        for (int j = 0; j < 4; j++) acco[i][j] = 0.f;

    int plast = t0 + 7;
    for (int p0 = 0; p0 <= plast; p0 += 64) {
        __syncthreads();
        // ---- cp.async K and V tiles (16B-granule XOR swizzle) ----
        int pp0 = p0 >> 1;
        #pragma unroll
        for (int it = 0; it < 4; it++) {
            int idx = tid + it * 128;            // 0..511
            int p = idx >> 3, g = idx & 7;       // p: K pos / V dim; g: granule
            uint32_t doff = (uint32_t)(p * 32 + ((g ^ (p & 7)) << 2)) * 4;
            size_t ksrc = (size_t)(p0 + p) * 256 + h * 32 + g * 4;
            cp16(bkh + doff, kh_g + ksrc);
            cp16(bkl + doff, kl_g + ksrc);
            size_t vsrc = (size_t)h * 32768 + (size_t)p * 512 + pp0 + g * 4;
            cp16(bvh + doff, vh_g + vsrc);
            cp16(bvl + doff, vl_g + vsrc);
        }
        asm volatile("cp.async.commit_group;" ::: "memory");
        asm volatile("cp.async.wait_group 0;" ::: "memory");
        __syncthreads();

        // ---- QK ----
        float s[8][4];
        #pragma unroll
        for (int i = 0; i < 8; i++)
            #pragma unroll
            for (int j = 0; j < 4; j++) s[i][j] = 0.f;

        #pragma unroll
        for (int nt = 0; nt < 8; nt++) {
            int n0 = nt * 8 + gid;
            int sw = n0 & 7;
            #pragma unroll
            for (int kc = 0; kc < 4; kc++) {
                uint32_t o0 = n0 * 32 + (((2 * kc) ^ sw) << 2) + tig;
                uint32_t o1 = n0 * 32 + (((2 * kc + 1) ^ sw) << 2) + tig;
                uint32_t bh0 = skh[o0], bh1 = skh[o1];
                uint32_t bl0 = skl[o0], bl1 = skl[o1];
                mma_bf16(s[nt], qh[kc], bh0, bh1);
                mma_bf16(s[nt], qh[kc], bl0, bl1);
                mma_bf16(s[nt], ql[kc], bh0, bh1);
            }
        }

        // ---- causal mask (diagonal region only) ----
        if (p0 + 64 > t0) {
            #pragma unroll
            for (int nt = 0; nt < 8; nt++) {
                int pg = p0 + nt * 8 + 2 * tig;
                if (pg > tok0)     s[nt][0] = -INFINITY;
                if (pg + 1 > tok0) s[nt][1] = -INFINITY;
                if (pg > tok8)     s[nt][2] = -INFINITY;
                if (pg + 1 > tok8) s[nt][3] = -INFINITY;
            }
        }

        // ---- online softmax ----
        float mx0 = -INFINITY, mx1 = -INFINITY;
        #pragma unroll
        for (int nt = 0; nt < 8; nt++) {
            mx0 = fmaxf(mx0, fmaxf(s[nt][0], s[nt][1]));
            mx1 = fmaxf(mx1, fmaxf(s[nt][2], s[nt][3]));
        }
        mx0 = fmaxf(mx0, __shfl_xor_sync(0xffffffffu, mx0, 1));
        mx0 = fmaxf(mx0, __shfl_xor_sync(0xffffffffu, mx0, 2));
        mx1 = fmaxf(mx1, __shfl_xor_sync(0xffffffffu, mx1, 1));
        mx1 = fmaxf(mx1, __shfl_xor_sync(0xffffffffu, mx1, 2));
        float nm0 = fmaxf(m0, mx0), nm1 = fmaxf(m1, mx1);
        float cr0 = __expf(m0 - nm0), cr1 = __expf(m1 - nm1);
        m0 = nm0; m1 = nm1;

        float rs0 = 0.f, rs1 = 0.f;
        #pragma unroll
        for (int nt = 0; nt < 8; nt++) {
            s[nt][0] = __expf(s[nt][0] - nm0);
            s[nt][1] = __expf(s[nt][1] - nm0);
            s[nt][2] = __expf(s[nt][2] - nm1);
            s[nt][3] = __expf(s[nt][3] - nm1);
            rs0 += s[nt][0] + s[nt][1];
            rs1 += s[nt][2] + s[nt][3];
        }
        rs0 += __shfl_xor_sync(0xffffffffu, rs0, 1);
        rs0 += __shfl_xor_sync(0xffffffffu, rs0, 2);
        rs1 += __shfl_xor_sync(0xffffffffu, rs1, 1);
        rs1 += __shfl_xor_sync(0xffffffffu, rs1, 2);
        l0 = l0 * cr0 + rs0;
        l1 = l1 * cr1 + rs1;

        #pragma unroll
        for (int ntd = 0; ntd < 8; ntd++) {
            acco[ntd][0] *= cr0; acco[ntd][1] *= cr0;
            acco[ntd][2] *= cr1; acco[ntd][3] *= cr1;
        }

        // ---- PV ----
        #pragma unroll
        for (int kc = 0; kc < 4; kc++) {
            uint32_t pah[4], pal[4];
            split2(s[2 * kc][0],     s[2 * kc][1],     pah[0], pal[0]);
            split2(s[2 * kc][2],     s[2 * kc][3],     pah[1], pal[1]);
            split2(s[2 * kc + 1][0], s[2 * kc + 1][1], pah[2], pal[2]);
            split2(s[2 * kc + 1][2], s[2 * kc + 1][3], pah[3], pal[3]);
            #pragma unroll
            for (int ntd = 0; ntd < 8; ntd++) {
                int d0 = ntd * 8 + gid;
                int sw = d0 & 7;
                uint32_t o0 = d0 * 32 + (((2 * kc) ^ sw) << 2) + tig;
                uint32_t o1 = d0 * 32 + (((2 * kc + 1) ^ sw) << 2) + tig;
                uint32_t bh0 = svh[o0], bh1 = svh[o1];
                uint32_t bl0 = svl[o0], bl1 = svl[o1];
                mma_bf16(acco[ntd], pah, bh0, bh1);
                mma_bf16(acco[ntd], pah, bl0, bl1);
                mma_bf16(acco[ntd], pal, bh0, bh1);
            }
        }
    }

    // ---- normalize + store split bf16 ----
    float i0 = 1.f / l0, i1 = 1.f / l1;
    #pragma unroll
    for (int ntd = 0; ntd < 8; ntd++) {
        int col = hb + ntd * 8 + 2 * tig;
        uint32_t hh, ll;
        split2(acco[ntd][0] * i0, acco[ntd][1] * i0, hh, ll);
        *(uint32_t*)(ar_h + (size_t)r0 * DR + col) = hh;
        *(uint32_t*)(ar_l + (size_t)r0 * DR + col) = ll;
        split2(acco[ntd][2] * i1, acco[ntd][3] * i1, hh, ll);
        *(uint32_t*)(ar_h + (size_t)r8 * DR + col) = hh;
        *(uint32_t*)(ar_l + (size_t)r8 * DR + col) = ll;
    }
}

// ---------------- host launch ----------------
extern "C" void kernel_launch(void* const* d_in, const int* in_sizes, int n_in,
                              void* d_out, int out_size)
{
    const float* s      = (const float*)d_in[0];
    const float* r      = (const float*)d_in[1];
    const float* gate_v = (const float*)d_in[2];
    const float* nsw    = (const float*)d_in[3];
    const float* nrw    = (const float*)d_in[4];
    const float* Wsq    = (const float*)d_in[5];
    const float* Wsk    = (const float*)d_in[6];
    const float* Wsv    = (const float*)d_in[7];
    const float* Wso    = (const float*)d_in[8];
    const float* Wrq    = (const float*)d_in[9];
    const float* Wrk    = (const float*)d_in[10];
    const float* Wrv    = (const float*)d_in[11];
    const float* Wro    = (const float*)d_in[12];

    float* out_s = (float*)d_out;
    float* out_r = (float*)d_out + T_LEN * DS;

    __nv_bfloat16 *snh, *snl, *rnh, *rnl, *ash, *asl, *arh, *arl, *wth, *wtl;
    float *q, *k, *v, *rsp, *qr, *kr, *vr;
    uint32_t *kh, *kl, *vth, *vtl;
    cudaGetSymbolAddress((void**)&snh, g_sn_h);
    cudaGetSymbolAddress((void**)&snl, g_sn_l);
    cudaGetSymbolAddress((void**)&rnh, g_rn_h);
    cudaGetSymbolAddress((void**)&rnl, g_rn_l);
    cudaGetSymbolAddress((void**)&ash, g_as_h);
    cudaGetSymbolAddress((void**)&asl, g_as_l);
    cudaGetSymbolAddress((void**)&arh, g_ar_h);
    cudaGetSymbolAddress((void**)&arl, g_ar_l);
    cudaGetSymbolAddress((void**)&wth, g_wth);
    cudaGetSymbolAddress((void**)&wtl, g_wtl);
    cudaGetSymbolAddress((void**)&q, g_q);
    cudaGetSymbolAddress((void**)&k, g_k);
    cudaGetSymbolAddress((void**)&v, g_v);
    cudaGetSymbolAddress((void**)&rsp, g_rsp);
    cudaGetSymbolAddress((void**)&qr, g_qr);
    cudaGetSymbolAddress((void**)&kr, g_kr);
    cudaGetSymbolAddress((void**)&vr, g_vr);
    cudaGetSymbolAddress((void**)&kh, g_kh);
    cudaGetSymbolAddress((void**)&kl, g_kl);
    cudaGetSymbolAddress((void**)&vth, g_vth);
    cudaGetSymbolAddress((void**)&vtl, g_vtl);

    // weight transpose+split (independent of activations)
    wtrans_split<<<dim3(DS / 32, DS / 32), 256>>>(Wsq, wth + OWSQ, wtl + OWSQ, DS, DS);
    wtrans_split<<<dim3(DS / 32, DR / 32), 256>>>(Wsk, wth + OWSK, wtl + OWSK, DR, DS);
    wtrans_split<<<dim3(DS / 32, DR / 32), 256>>>(Wsv, wth + OWSV, wtl + OWSV, DR, DS);
    wtrans_split<<<dim3(DS / 32, DS / 32), 256>>>(Wso, wth + OWSO, wtl + OWSO, DS, DS);
    wtrans_split<<<dim3(DR / 32, DR / 32), 256>>>(Wrq, wth + OWRQ, wtl + OWRQ, DR, DR);
    wtrans_split<<<dim3(DR / 32, DS / 32), 256>>>(Wrk, wth + OWRK, wtl + OWRK, DS, DR);
    wtrans_split<<<dim3(DR / 32, DS / 32), 256>>>(Wrv, wth + OWRV, wtl + OWRV, DS, DR);
    wtrans_split<<<dim3(DR / 32, DR / 32), 256>>>(Wro, wth + OWRO, wtl + OWRO, DR, DR);

    // rmsnorm → split bf16
    rmsnorm_split<<<T_LEN, 256>>>(s, nsw, snh, snl, DS);
    rmsnorm_split<<<ROWS_R, 256>>>(r, nrw, rnh, rnl, DR);

    // s-branch projections
    mma_gemm_bf<<<dim3(DS / 128, T_LEN / 128), 256>>>(
        snh, snl, wth + OWSQ, wtl + OWSQ, q, T_LEN, DS, DS,
        nullptr, nullptr, nullptr);
    mma_gemm_bf<<<dim3(DS / 128, ROWS_R / 128), 256>>>(
        rnh, rnl, wth + OWSK, wtl + OWSK, k, ROWS_R, DS, DR,
        nullptr, nullptr, nullptr);
    mma_gemm_bf<<<dim3(DS / 128, ROWS_R / 128), 256>>>(
        rnh, rnl, wth + OWSV, wtl + OWSV, v, ROWS_R, DS, DR,
        nullptr, nullptr, nullptr);

    // s-attention + sparse top-k
    s_attn_kernel<<<T_LEN, 256>>>(q, k, v, ash, asl, rsp);

    // s output
    mma_gemm_bf<<<dim3(DS / 128, T_LEN / 128), 256>>>(
        ash, asl, wth + OWSO, wtl + OWSO, out_s, T_LEN, DS, DS,
        s, rsp, gate_v);

    // r-branch projections
    mma_gemm_bf<<<dim3(DR / 128, ROWS_R / 128), 256>>>(
        rnh, rnl, wth + OWRQ, wtl + OWRQ, qr, ROWS_R, DR, DR,
        nullptr, nullptr, nullptr);
    mma_gemm_bf<<<dim3(DR / 128, T_LEN / 128), 256>>>(
        snh, snl, wth + OWRK, wtl + OWRK, kr, T_LEN, DR, DS,
        nullptr, nullptr, nullptr);
    mma_gemm_bf<<<dim3(DR / 128, T_LEN / 128), 256>>>(
        snh, snl, wth + OWRV, wtl + OWRV, vr, T_LEN, DR, DS,
        nullptr, nullptr, nullptr);

    // pre-split K/V for r-attention
    conv_k<<<T_LEN, 256>>>(kr, kh, kl);
    conv_vt<<<1024, 256>>>(vr, vth, vtl);

    // causal r attention
    r_attn_mma<<<dim3(T_LEN / 8, HEADS), 128>>>(qr, kh, kl, vth, vtl, arh, arl);

    // r output
    mma_gemm_bf<<<dim3(DR / 128, ROWS_R / 128), 256>>>(
        arh, arl, wth + OWRO, wtl + OWRO, out_r, ROWS_R, DR, DR,
        r, nullptr, nullptr);
}

// round 7
// speedup vs baseline: 3.6814x; 1.2126x over previous
#include <cuda_runtime.h>
#include <cuda_bf16.h>
#include <math.h>
#include <stdint.h>

// ---------------- problem constants ----------------
#define T_LEN 1024
#define NSLOT 8
#define DS 1024
#define DR 512
#define HEADS 8
#define DHS 128
#define DHR 64
#define TOPK 4
#define ROWS_R (T_LEN * NSLOT)   // 8192
#define SCALE_S 0.08838834764831845f  // 1/sqrt(128)
#define SCALE_R 0.125f                // 1/sqrt(64)
#define EPS 1e-6f

// fused layouts
#define N_SN 2048        // q(1024) | kr(512) | vr(512), K=1024
#define N_RN 2560        // k(1024) | v(1024) | qr(512), K=512

// ---------------- scratch (static device memory; no allocation) -------------
__device__ __nv_bfloat16 g_sn_h[T_LEN * DS], g_sn_l[T_LEN * DS];
__device__ __nv_bfloat16 g_rn_h[ROWS_R * DR], g_rn_l[ROWS_R * DR];
__device__ __nv_bfloat16 g_as_h[T_LEN * DS], g_as_l[T_LEN * DS];
__device__ __nv_bfloat16 g_ar_h[ROWS_R * DR], g_ar_l[ROWS_R * DR];
__device__ __nv_bfloat16 g_wsn_h[N_SN * DS], g_wsn_l[N_SN * DS];
__device__ __nv_bfloat16 g_wrn_h[N_RN * DR], g_wrn_l[N_RN * DR];
__device__ __nv_bfloat16 g_wso_h[DS * DS], g_wso_l[DS * DS];
__device__ __nv_bfloat16 g_wro_h[DR * DR], g_wro_l[DR * DR];
__device__ float g_csn[T_LEN * N_SN];     // q | kr | vr
__device__ float g_crn[ROWS_R * N_RN];    // k | v | qr
__device__ float g_rsp[T_LEN * DS];
__device__ uint32_t g_kh[T_LEN * 256], g_kl[T_LEN * 256];
__device__ uint32_t g_vth[HEADS * DHR * (T_LEN / 2)];
__device__ uint32_t g_vtl[HEADS * DHR * (T_LEN / 2)];

// ---------------- PTX helpers ----------------
__device__ __forceinline__ uint32_t smem_u32(const void* p) {
    uint32_t a;
    asm("{ .reg .u64 t; cvta.to.shared.u64 t, %1; cvt.u32.u64 %0, t; }"
        : "=r"(a) : "l"(p));
    return a;
}
__device__ __forceinline__ void cp16(uint32_t dst, const void* src) {
    asm volatile("cp.async.cg.shared.global [%0], [%1], 16;"
                 :: "r"(dst), "l"(src) : "memory");
}
__device__ __forceinline__ void ldm_x4(uint32_t* r, uint32_t addr) {
    asm volatile("ldmatrix.sync.aligned.m8n8.x4.shared.b16 {%0,%1,%2,%3}, [%4];"
                 : "=r"(r[0]), "=r"(r[1]), "=r"(r[2]), "=r"(r[3]) : "r"(addr));
}
__device__ __forceinline__ void mma_bf16(
    float* c, const uint32_t* a, uint32_t b0, uint32_t b1)
{
    asm volatile(
        "mma.sync.aligned.m16n8k16.row.col.f32.bf16.bf16.f32 "
        "{%0,%1,%2,%3}, {%4,%5,%6,%7}, {%8,%9}, {%0,%1,%2,%3};"
        : "+f"(c[0]), "+f"(c[1]), "+f"(c[2]), "+f"(c[3])
        : "r"(a[0]), "r"(a[1]), "r"(a[2]), "r"(a[3]), "r"(b0), "r"(b1));
}
__device__ __forceinline__ void split2(float x, float y,
                                       uint32_t& hi, uint32_t& lo)
{
    __nv_bfloat162 h = __floats2bfloat162_rn(x, y);
    float xr = x - __bfloat162float(h.x);
    float yr = y - __bfloat162float(h.y);
    __nv_bfloat162 l = __floats2bfloat162_rn(xr, yr);
    hi = *(uint32_t*)&h;
    lo = *(uint32_t*)&l;
}

// ---------------- weight transpose + split: W (K,N) -> Wt hi/lo (N,K) -------
__global__ __launch_bounds__(256) void wtrans_split(
    const float* __restrict__ W,
    __nv_bfloat16* __restrict__ th, __nv_bfloat16* __restrict__ tl,
    int K, int N)
{
    __shared__ float t[32][33];
    int bx = blockIdx.x * 32;
    int by = blockIdx.y * 32;
    int tx = threadIdx.x & 31, ty = threadIdx.x >> 5;
    #pragma unroll
    for (int i = 0; i < 4; i++)
        t[ty + i * 8][tx] = W[(size_t)(by + ty + i * 8) * N + bx + tx];
    __syncthreads();
    #pragma unroll
    for (int i = 0; i < 4; i++) {
        int n = bx + ty + i * 8;
        int k = by + tx;
        float v = t[tx][ty + i * 8];
        __nv_bfloat16 h = __float2bfloat16(v);
        th[(size_t)n * K + k] = h;
        tl[(size_t)n * K + k] = __float2bfloat16(v - __bfloat162float(h));
    }
}

// ---------------- rmsnorm with split bf16 output ----------------
__global__ __launch_bounds__(256) void rmsnorm_split(
    const float* __restrict__ x, const float* __restrict__ w,
    __nv_bfloat16* __restrict__ oh, __nv_bfloat16* __restrict__ ol, int C)
{
    int row = blockIdx.x;
    const float* xr = x + (size_t)row * C;
    float s = 0.f;
    for (int j = threadIdx.x; j < C; j += 256) {
        float v = xr[j];
        s += v * v;
    }
    __shared__ float red[8];
    int lane = threadIdx.x & 31, warp = threadIdx.x >> 5;
    #pragma unroll
    for (int off = 16; off; off >>= 1) s += __shfl_xor_sync(0xffffffffu, s, off);
    if (lane == 0) red[warp] = s;
    __syncthreads();
    __shared__ float scale;
    if (threadIdx.x == 0) {
        float tot = 0.f;
        #pragma unroll
        for (int i = 0; i < 8; i++) tot += red[i];
        scale = rsqrtf(tot / (float)C + EPS);
    }
    __syncthreads();
    float sc = scale;
    uint32_t* ph = (uint32_t*)(oh + (size_t)row * C);
    uint32_t* pl = (uint32_t*)(ol + (size_t)row * C);
    for (int j2 = threadIdx.x; j2 < C / 2; j2 += 256) {
        float v0 = xr[2 * j2] * sc * w[2 * j2];
        float v1 = xr[2 * j2 + 1] * sc * w[2 * j2 + 1];
        uint32_t h, l;
        split2(v0, v1, h, l);
        ph[j2] = h;
        pl[j2] = l;
    }
}

// ---------------- bf16-split mma GEMM with ldmatrix fragments ---------------
// C(M x N, row stride ldc) = A(M,K) @ Bt(N,K)^T [+ add1] [+ rowscale*add2]
__global__ __launch_bounds__(256) void mma_gemm_bf(
    const __nv_bfloat16* __restrict__ Ah, const __nv_bfloat16* __restrict__ Al,
    const __nv_bfloat16* __restrict__ Bh, const __nv_bfloat16* __restrict__ Bl,
    float* __restrict__ C, int M, int N, int K, int ldc,
    const float* __restrict__ add1,
    const float* __restrict__ add2, const float* __restrict__ rowscale)
{
    __shared__ __align__(16) uint32_t sAh[2][128 * 8], sAl[2][128 * 8];
    __shared__ __align__(16) uint32_t sBh[2][128 * 8], sBl[2][128 * 8];

    int tid = threadIdx.x;
    int lane = tid & 31, wid = tid >> 5;
    int wm = wid >> 1, wn = wid & 1;
    int bm = blockIdx.y * 128, bn = blockIdx.x * 128;
    int gid = lane >> 2, tig = lane & 3;

    float acc[2][8][4];
    #pragma unroll
    for (int i = 0; i < 2; i++)
        #pragma unroll
        for (int j = 0; j < 8; j++)
            #pragma unroll
            for (int l = 0; l < 4; l++) acc[i][j][l] = 0.f;

    uint32_t bAh = smem_u32(sAh), bAl = smem_u32(sAl);
    uint32_t bBh = smem_u32(sBh), bBl = smem_u32(sBl);

    // ldmatrix per-lane byte offsets (within a stage)
    uint32_t aoff[2], boff[4];
    {
        int lrow = lane & 7;
        int rA = wm * 32 + lrow + (lane & 8);
        int cA = (lane & 16) >> 2;
        aoff[0] = (uint32_t)(rA * 8 + cA) * 4;
        aoff[1] = (uint32_t)((rA + 16) * 8 + cA) * 4;
        int rB = wn * 64 + lrow + ((lane & 16) >> 1);
        int cB = (lane & 8) >> 1;
        #pragma unroll
        for (int ntp = 0; ntp < 4; ntp++)
            boff[ntp] = (uint32_t)((rB + ntp * 16) * 8 + cB) * 4;
    }

    int row = tid >> 1;
    int gg = tid & 1;
    auto issue = [&](int st, int k0) {
        uint32_t doff = (uint32_t)(st * 128 * 8 + row * 8 + gg * 4) * 4;
        size_t asrc = (size_t)(bm + row) * K + k0 + gg * 8;
        size_t bsrc = (size_t)(bn + row) * K + k0 + gg * 8;
        cp16(bAh + doff, Ah + asrc);
        cp16(bAl + doff, Al + asrc);
        cp16(bBh + doff, Bh + bsrc);
        cp16(bBl + doff, Bl + bsrc);
        asm volatile("cp.async.commit_group;" ::: "memory");
    };

    int nch = K >> 4;
    issue(0, 0);

    for (int c = 0; c < nch; c++) {
        if (c + 1 < nch) {
            issue((c + 1) & 1, (c + 1) * 16);
            asm volatile("cp.async.wait_group 1;" ::: "memory");
        } else {
            asm volatile("cp.async.wait_group 0;" ::: "memory");
        }
        __syncthreads();

        uint32_t stoff = (uint32_t)((c & 1) * 128 * 8 * 4);

        uint32_t ah[2][4], al[2][4], bh[4][4], bl[4][4];
        ldm_x4(ah[0], bAh + stoff + aoff[0]);
        ldm_x4(ah[1], bAh + stoff + aoff[1]);
        ldm_x4(al[0], bAl + stoff + aoff[0]);
        ldm_x4(al[1], bAl + stoff + aoff[1]);
        #pragma unroll
        for (int ntp = 0; ntp < 4; ntp++) {
            ldm_x4(bh[ntp], bBh + stoff + boff[ntp]);
            ldm_x4(bl[ntp], bBl + stoff + boff[ntp]);
        }

        #pragma unroll
        for (int nt = 0; nt < 8; nt++) {
            int p = nt >> 1, q2 = (nt & 1) << 1;
            uint32_t b0h = bh[p][q2], b1h = bh[p][q2 + 1];
            uint32_t b0l = bl[p][q2], b1l = bl[p][q2 + 1];
            mma_bf16(acc[0][nt], ah[0], b0h, b1h);
            mma_bf16(acc[0][nt], ah[0], b0l, b1l);
            mma_bf16(acc[0][nt], al[0], b0h, b1h);
            mma_bf16(acc[1][nt], ah[1], b0h, b1h);
            mma_bf16(acc[1][nt], ah[1], b0l, b1l);
            mma_bf16(acc[1][nt], al[1], b0h, b1h);
        }
        __syncthreads();
    }

    #pragma unroll
    for (int mt = 0; mt < 2; mt++) {
        int r0 = bm + wm * 32 + mt * 16 + gid;
        float rs0 = (rowscale != nullptr) ? rowscale[r0] : 0.f;
        float rs8 = (rowscale != nullptr) ? rowscale[r0 + 8] : 0.f;
        #pragma unroll
        for (int nt = 0; nt < 8; nt++) {
            int col = bn + wn * 64 + nt * 8 + 2 * tig;
            size_t o0 = (size_t)r0 * ldc + col;
            size_t o8 = (size_t)(r0 + 8) * ldc + col;
            float2 v0 = make_float2(acc[mt][nt][0], acc[mt][nt][1]);
            float2 v8 = make_float2(acc[mt][nt][2], acc[mt][nt][3]);
            if (add1) {
                float2 x = *(const float2*)(add1 + o0);
                v0.x += x.x; v0.y += x.y;
                x = *(const float2*)(add1 + o8);
                v8.x += x.x; v8.y += x.y;
            }
            if (add2) {
                float2 x = *(const float2*)(add2 + o0);
                v0.x += rs0 * x.x; v0.y += rs0 * x.y;
                x = *(const float2*)(add2 + o8);
                v8.x += rs8 * x.x; v8.y += rs8 * x.y;
            }
            *(float2*)(C + o0) = v0;
            *(float2*)(C + o8) = v8;
        }
    }
}

// ---------------- s-attention + top-k sparse (strided inputs) ---------------
__global__ __launch_bounds__(256) void s_attn_kernel(
    const float* __restrict__ qmat,   // (T, ·) stride qld
    const float* __restrict__ kmat,   // (T*N, ·) stride kvld
    const float* __restrict__ vmat,   // (T*N, ·) stride kvld
    int qld, int kvld,
    __nv_bfloat16* __restrict__ as_h,
    __nv_bfloat16* __restrict__ as_l,
    float* __restrict__ rsp)
{
    int t = blockIdx.x;
    int tid = threadIdx.x;
    int warp = tid >> 5, lane = tid & 31;

    __shared__ float qs[DS];
    __shared__ float logits[HEADS][NSLOT];
    __shared__ float wattn[HEADS][NSLOT];
    __shared__ float wsp[NSLOT];

    for (int j = tid; j < DS; j += 256) qs[j] = qmat[(size_t)t * qld + j];
    __syncthreads();

    {
        int h = warp;
        #pragma unroll
        for (int n = 0; n < NSLOT; n++) {
            const float* krow = kmat + (size_t)(t * NSLOT + n) * kvld + h * DHS;
            const float* qrow = qs + h * DHS;
            float p = 0.f;
            #pragma unroll
            for (int d = lane; d < DHS; d += 32) p += qrow[d] * krow[d];
            #pragma unroll
            for (int off = 16; off; off >>= 1) p += __shfl_xor_sync(0xffffffffu, p, off);
            if (lane == 0) logits[h][n] = p;
        }
    }
    __syncthreads();

    if (tid < HEADS) {
        int h = tid;
        float m = -INFINITY;
        #pragma unroll
        for (int n = 0; n < NSLOT; n++) m = fmaxf(m, logits[h][n] * SCALE_S);
        float s = 0.f;
        #pragma unroll
        for (int n = 0; n < NSLOT; n++) {
            float e = __expf(logits[h][n] * SCALE_S - m);
            wattn[h][n] = e;
            s += e;
        }
        float inv = 1.f / s;
        #pragma unroll
        for (int n = 0; n < NSLOT; n++) wattn[h][n] *= inv;
    }
    if (tid == 8) {
        float sp[NSLOT];
        #pragma unroll
        for (int n = 0; n < NSLOT; n++) {
            float a = 0.f;
            #pragma unroll
            for (int h = 0; h < HEADS; h++) a += logits[h][n];
            sp[n] = a * SCALE_S;
        }
        bool sel[NSLOT];
        #pragma unroll
        for (int n = 0; n < NSLOT; n++) { sel[n] = false; wsp[n] = 0.f; }
        int idxs[TOPK];
        #pragma unroll
        for (int kk = 0; kk < TOPK; kk++) {
            int best = -1; float bv = -INFINITY;
            #pragma unroll
            for (int n = 0; n < NSLOT; n++)
                if (!sel[n] && sp[n] > bv) { bv = sp[n]; best = n; }
            sel[best] = true; idxs[kk] = best;
        }
        float m = -INFINITY;
        #pragma unroll
        for (int kk = 0; kk < TOPK; kk++) m = fmaxf(m, sp[idxs[kk]]);
        float s = 0.f, e[TOPK];
        #pragma unroll
        for (int kk = 0; kk < TOPK; kk++) { e[kk] = __expf(sp[idxs[kk]] - m); s += e[kk]; }
        float inv = 1.f / s;
        #pragma unroll
        for (int kk = 0; kk < TOPK; kk++) wsp[idxs[kk]] = e[kk] * inv;
    }
    __syncthreads();

    uint32_t* ph = (uint32_t*)(as_h + (size_t)t * DS);
    uint32_t* pl = (uint32_t*)(as_l + (size_t)t * DS);
    for (int j2 = tid; j2 < DS / 2; j2 += 256) {
        int j = 2 * j2;
        int h = j >> 7;
        float a0 = 0.f, a1 = 0.f, b0 = 0.f, b1 = 0.f;
        #pragma unroll
        for (int n = 0; n < NSLOT; n++) {
            float2 vv = *(const float2*)(vmat + (size_t)(t * NSLOT + n) * kvld + j);
            a0 += wattn[h][n] * vv.x;
            a1 += wattn[h][n] * vv.y;
            b0 += wsp[n] * vv.x;
            b1 += wsp[n] * vv.y;
        }
        uint32_t hh, ll;
        split2(a0, a1, hh, ll);
        ph[j2] = hh;
        pl[j2] = ll;
        *(float2*)(rsp + (size_t)t * DS + j) = make_float2(b0, b1);
    }
}

// ---------------- K/V pre-split converts ----------------
__global__ __launch_bounds__(256) void conv_k(
    const float* __restrict__ kr, int ld, uint32_t* __restrict__ kh,
    uint32_t* __restrict__ kl)
{
    int t = blockIdx.x, j = threadIdx.x;
    float2 v = *(const float2*)(kr + (size_t)t * ld + 2 * j);
    uint32_t h, l;
    split2(v.x, v.y, h, l);
    kh[(size_t)t * 256 + j] = h;
    kl[(size_t)t * 256 + j] = l;
}
__global__ __launch_bounds__(256) void conv_vt(
    const float* __restrict__ vr, int ld, uint32_t* __restrict__ vh,
    uint32_t* __restrict__ vl)
{
    int idx = blockIdx.x * 256 + threadIdx.x;
    int pp = idx & 511;
    int d = (idx >> 9) & 63;
    int h = idx >> 15;
    float v0 = vr[(size_t)(2 * pp) * ld + h * DHR + d];
    float v1 = vr[(size_t)(2 * pp + 1) * ld + h * DHR + d];
    uint32_t hh, ll;
    split2(v0, v1, hh, ll);
    vh[idx] = hh;
    vl[idx] = ll;
}

// ---------------- causal r-attention: MMA flash, pre-split K/V --------------
__global__ __launch_bounds__(128) void r_attn_mma(
    const float* __restrict__ qr, int qld,
    const uint32_t* __restrict__ kh_g, const uint32_t* __restrict__ kl_g,
    const uint32_t* __restrict__ vh_g, const uint32_t* __restrict__ vl_g,
    __nv_bfloat16* __restrict__ ar_h, __nv_bfloat16* __restrict__ ar_l)
{
    __shared__ __align__(16) uint32_t skh[64 * 32], skl[64 * 32];
    __shared__ __align__(16) uint32_t svh[64 * 32], svl[64 * 32];

    int tt = (int)(gridDim.x - 1 - blockIdx.x);
    int h = blockIdx.y;
    int t0 = tt * 8;
    int hb = h * DHR;

    int tid = threadIdx.x;
    int w = tid >> 5, lane = tid & 31;
    int gid = lane >> 2, tig = lane & 3;

    uint32_t bkh = smem_u32(skh), bkl = smem_u32(skl);
    uint32_t bvh = smem_u32(svh), bvl = smem_u32(svl);

    int r0 = t0 * 8 + 16 * w + gid;
    int r8 = r0 + 8;
    uint32_t qh[4][4], ql[4][4];
    #pragma unroll
    for (int kc = 0; kc < 4; kc++) {
        float2 x0 = *(const float2*)(qr + (size_t)r0 * qld + hb + kc * 16 + 2 * tig);
        float2 x1 = *(const float2*)(qr + (size_t)r8 * qld + hb + kc * 16 + 2 * tig);
        float2 x2 = *(const float2*)(qr + (size_t)r0 * qld + hb + kc * 16 + 2 * tig + 8);
        float2 x3 = *(const float2*)(qr + (size_t)r8 * qld + hb + kc * 16 + 2 * tig + 8);
        split2(x0.x * SCALE_R, x0.y * SCALE_R, qh[kc][0], ql[kc][0]);
        split2(x1.x * SCALE_R, x1.y * SCALE_R, qh[kc][1], ql[kc][1]);
        split2(x2.x * SCALE_R, x2.y * SCALE_R, qh[kc][2], ql[kc][2]);
        split2(x3.x * SCALE_R, x3.y * SCALE_R, qh[kc][3], ql[kc][3]);
    }
    int tok0 = t0 + ((16 * w + gid) >> 3);
    int tok8 = t0 + ((16 * w + gid + 8) >> 3);

    float m0 = -INFINITY, m1 = -INFINITY, l0 = 0.f, l1 = 0.f;
    float acco[8][4];
    #pragma unroll
    for (int i = 0; i < 8; i++)
        #pragma unroll
        for (int j = 0; j < 4; j++) acco[i][j] = 0.f;

    int plast = t0 + 7;
    for (int p0 = 0; p0 <= plast; p0 += 64) {
        __syncthreads();
        int pp0 = p0 >> 1;
        #pragma unroll
        for (int it = 0; it < 4; it++) {
            int idx = tid + it * 128;
            int p = idx >> 3, g = idx & 7;
            uint32_t doff = (uint32_t)(p * 32 + ((g ^ (p & 7)) << 2)) * 4;
            size_t ksrc = (size_t)(p0 + p) * 256 + h * 32 + g * 4;
            cp16(bkh + doff, kh_g + ksrc);
            cp16(bkl + doff, kl_g + ksrc);
            size_t vsrc = (size_t)h * 32768 + (size_t)p * 512 + pp0 + g * 4;
            cp16(bvh + doff, vh_g + vsrc);
            cp16(bvl + doff, vl_g + vsrc);
        }
        asm volatile("cp.async.commit_group;" ::: "memory");
        asm volatile("cp.async.wait_group 0;" ::: "memory");
        __syncthreads();

        float s[8][4];
        #pragma unroll
        for (int i = 0; i < 8; i++)
            #pragma unroll
            for (int j = 0; j < 4; j++) s[i][j] = 0.f;

        #pragma unroll
        for (int nt = 0; nt < 8; nt++) {
            int n0 = nt * 8 + gid;
            int sw = n0 & 7;
            #pragma unroll
            for (int kc = 0; kc < 4; kc++) {
                uint32_t o0 = n0 * 32 + (((2 * kc) ^ sw) << 2) + tig;
                uint32_t o1 = n0 * 32 + (((2 * kc + 1) ^ sw) << 2) + tig;
                uint32_t bh0 = skh[o0], bh1 = skh[o1];
                uint32_t bl0 = skl[o0], bl1 = skl[o1];
                mma_bf16(s[nt], qh[kc], bh0, bh1);
                mma_bf16(s[nt], qh[kc], bl0, bl1);
                mma_bf16(s[nt], ql[kc], bh0, bh1);
            }
        }

        if (p0 + 64 > t0) {
            #pragma unroll
            for (int nt = 0; nt < 8; nt++) {
                int pg = p0 + nt * 8 + 2 * tig;
                if (pg > tok0)     s[nt][0] = -INFINITY;
                if (pg + 1 > tok0) s[nt][1] = -INFINITY;
                if (pg > tok8)     s[nt][2] = -INFINITY;
                if (pg + 1 > tok8) s[nt][3] = -INFINITY;
            }
        }

        float mx0 = -INFINITY, mx1 = -INFINITY;
        #pragma unroll
        for (int nt = 0; nt < 8; nt++) {
            mx0 = fmaxf(mx0, fmaxf(s[nt][0], s[nt][1]));
            mx1 = fmaxf(mx1, fmaxf(s[nt][2], s[nt][3]));
        }
        mx0 = fmaxf(mx0, __shfl_xor_sync(0xffffffffu, mx0, 1));
        mx0 = fmaxf(mx0, __shfl_xor_sync(0xffffffffu, mx0, 2));
        mx1 = fmaxf(mx1, __shfl_xor_sync(0xffffffffu, mx1, 1));
        mx1 = fmaxf(mx1, __shfl_xor_sync(0xffffffffu, mx1, 2));
        float nm0 = fmaxf(m0, mx0), nm1 = fmaxf(m1, mx1);
        float cr0 = __expf(m0 - nm0), cr1 = __expf(m1 - nm1);
        m0 = nm0; m1 = nm1;

        float rs0 = 0.f, rs1 = 0.f;
        #pragma unroll
        for (int nt = 0; nt < 8; nt++) {
            s[nt][0] = __expf(s[nt][0] - nm0);
            s[nt][1] = __expf(s[nt][1] - nm0);
            s[nt][2] = __expf(s[nt][2] - nm1);
            s[nt][3] = __expf(s[nt][3] - nm1);
            rs0 += s[nt][0] + s[nt][1];
            rs1 += s[nt][2] + s[nt][3];
        }
        rs0 += __shfl_xor_sync(0xffffffffu, rs0, 1);
        rs0 += __shfl_xor_sync(0xffffffffu, rs0, 2);
        rs1 += __shfl_xor_sync(0xffffffffu, rs1, 1);
        rs1 += __shfl_xor_sync(0xffffffffu, rs1, 2);
        l0 = l0 * cr0 + rs0;
        l1 = l1 * cr1 + rs1;

        #pragma unroll
        for (int ntd = 0; ntd < 8; ntd++) {
            acco[ntd][0] *= cr0; acco[ntd][1] *= cr0;
            acco[ntd][2] *= cr1; acco[ntd][3] *= cr1;
        }

        #pragma unroll
        for (int kc = 0; kc < 4; kc++) {
            uint32_t pah[4], pal[4];
            split2(s[2 * kc][0],     s[2 * kc][1],     pah[0], pal[0]);
            split2(s[2 * kc][2],     s[2 * kc][3],     pah[1], pal[1]);
            split2(s[2 * kc + 1][0], s[2 * kc + 1][1], pah[2], pal[2]);
            split2(s[2 * kc + 1][2], s[2 * kc + 1][3], pah[3], pal[3]);
            #pragma unroll
            for (int ntd = 0; ntd < 8; ntd++) {
                int d0 = ntd * 8 + gid;
                int sw = d0 & 7;
                uint32_t o0 = d0 * 32 + (((2 * kc) ^ sw) << 2) + tig;
                uint32_t o1 = d0 * 32 + (((2 * kc + 1) ^ sw) << 2) + tig;
                uint32_t bh0 = svh[o0], bh1 = svh[o1];
                uint32_t bl0 = svl[o0], bl1 = svl[o1];
                mma_bf16(acco[ntd], pah, bh0, bh1);
                mma_bf16(acco[ntd], pah, bl0, bl1);
                mma_bf16(acco[ntd], pal, bh0, bh1);
            }
        }
    }

    float i0 = 1.f / l0, i1 = 1.f / l1;
    #pragma unroll
    for (int ntd = 0; ntd < 8; ntd++) {
        int col = hb + ntd * 8 + 2 * tig;
        uint32_t hh, ll;
        split2(acco[ntd][0] * i0, acco[ntd][1] * i0, hh, ll);
        *(uint32_t*)(ar_h + (size_t)r0 * DR + col) = hh;
        *(uint32_t*)(ar_l + (size_t)r0 * DR + col) = ll;
        split2(acco[ntd][2] * i1, acco[ntd][3] * i1, hh, ll);
        *(uint32_t*)(ar_h + (size_t)r8 * DR + col) = hh;
        *(uint32_t*)(ar_l + (size_t)r8 * DR + col) = ll;
    }
}

// ---------------- host launch ----------------
extern "C" void kernel_launch(void* const* d_in, const int* in_sizes, int n_in,
                              void* d_out, int out_size)
{
    const float* s      = (const float*)d_in[0];
    const float* r      = (const float*)d_in[1];
    const float* gate_v = (const float*)d_in[2];
    const float* nsw    = (const float*)d_in[3];
    const float* nrw    = (const float*)d_in[4];
    const float* Wsq    = (const float*)d_in[5];
    const float* Wsk    = (const float*)d_in[6];
    const float* Wsv    = (const float*)d_in[7];
    const float* Wso    = (const float*)d_in[8];
    const float* Wrq    = (const float*)d_in[9];
    const float* Wrk    = (const float*)d_in[10];
    const float* Wrv    = (const float*)d_in[11];
    const float* Wro    = (const float*)d_in[12];

    float* out_s = (float*)d_out;
    float* out_r = (float*)d_out + T_LEN * DS;

    __nv_bfloat16 *snh, *snl, *rnh, *rnl, *ash, *asl, *arh, *arl;
    __nv_bfloat16 *wsnh, *wsnl, *wrnh, *wrnl, *wsoh, *wsol, *wroh, *wrol;
    float *csn, *crn, *rsp;
    uint32_t *kh, *kl, *vth, *vtl;
    cudaGetSymbolAddress((void**)&snh, g_sn_h);
    cudaGetSymbolAddress((void**)&snl, g_sn_l);
    cudaGetSymbolAddress((void**)&rnh, g_rn_h);
    cudaGetSymbolAddress((void**)&rnl, g_rn_l);
    cudaGetSymbolAddress((void**)&ash, g_as_h);
    cudaGetSymbolAddress((void**)&asl, g_as_l);
    cudaGetSymbolAddress((void**)&arh, g_ar_h);
    cudaGetSymbolAddress((void**)&arl, g_ar_l);
    cudaGetSymbolAddress((void**)&wsnh, g_wsn_h);
    cudaGetSymbolAddress((void**)&wsnl, g_wsn_l);
    cudaGetSymbolAddress((void**)&wrnh, g_wrn_h);
    cudaGetSymbolAddress((void**)&wrnl, g_wrn_l);
    cudaGetSymbolAddress((void**)&wsoh, g_wso_h);
    cudaGetSymbolAddress((void**)&wsol, g_wso_l);
    cudaGetSymbolAddress((void**)&wroh, g_wro_h);
    cudaGetSymbolAddress((void**)&wrol, g_wro_l);
    cudaGetSymbolAddress((void**)&csn, g_csn);
    cudaGetSymbolAddress((void**)&crn, g_crn);
    cudaGetSymbolAddress((void**)&rsp, g_rsp);
    cudaGetSymbolAddress((void**)&kh, g_kh);
    cudaGetSymbolAddress((void**)&kl, g_kl);
    cudaGetSymbolAddress((void**)&vth, g_vth);
    cudaGetSymbolAddress((void**)&vtl, g_vtl);

    // ---- weight transpose+split into fused arenas ----
    // SN arena (K=1024): rows [0,1024)=WsqT, [1024,1536)=WrkT, [1536,2048)=WrvT
    wtrans_split<<<dim3(DS / 32, DS / 32), 256>>>(Wsq, wsnh, wsnl, DS, DS);
    wtrans_split<<<dim3(DR / 32, DS / 32), 256>>>(Wrk, wsnh + 1024 * DS,
                                                  wsnl + 1024 * DS, DS, DR);
    wtrans_split<<<dim3(DR / 32, DS / 32), 256>>>(Wrv, wsnh + 1536 * DS,
                                                  wsnl + 1536 * DS, DS, DR);
    // RN arena (K=512): rows [0,1024)=WskT, [1024,2048)=WsvT, [2048,2560)=WrqT
    wtrans_split<<<dim3(DS / 32, DR / 32), 256>>>(Wsk, wrnh, wrnl, DR, DS);
    wtrans_split<<<dim3(DS / 32, DR / 32), 256>>>(Wsv, wrnh + 1024 * DR,
                                                  wrnl + 1024 * DR, DR, DS);
    wtrans_split<<<dim3(DR / 32, DR / 32), 256>>>(Wrq, wrnh + 2048 * DR,
                                                  wrnl + 2048 * DR, DR, DR);
    wtrans_split<<<dim3(DS / 32, DS / 32), 256>>>(Wso, wsoh, wsol, DS, DS);
    wtrans_split<<<dim3(DR / 32, DR / 32), 256>>>(Wro, wroh, wrol, DR, DR);

    // ---- rmsnorm ----
    rmsnorm_split<<<T_LEN, 256>>>(s, nsw, snh, snl, DS);
    rmsnorm_split<<<ROWS_R, 256>>>(r, nrw, rnh, rnl, DR);

    // ---- fused projection GEMMs ----
    // C_sn = sn @ [Wsq | Wrk | Wrv]  (1024 x 2048)
    mma_gemm_bf<<<dim3(N_SN / 128, T_LEN / 128), 256>>>(
        snh, snl, wsnh, wsnl, csn, T_LEN, N_SN, DS, N_SN,
        nullptr, nullptr, nullptr);
    // C_rn = rn @ [Wsk | Wsv | Wrq]  (8192 x 2560)
    mma_gemm_bf<<<dim3(N_RN / 128, ROWS_R / 128), 256>>>(
        rnh, rnl, wrnh, wrnl, crn, ROWS_R, N_RN, DR, N_RN,
        nullptr, nullptr, nullptr);

    // ---- pre-split K/V for r-attention (from C_sn columns) ----
    conv_k<<<T_LEN, 256>>>(csn + 1024, N_SN, kh, kl);
    conv_vt<<<1024, 256>>>(csn + 1536, N_SN, vth, vtl);

    // ---- s-attention + sparse top-k ----
    s_attn_kernel<<<T_LEN, 256>>>(csn, crn, crn + 1024, N_SN, N_RN,
                                  ash, asl, rsp);

    // ---- causal r attention ----
    r_attn_mma<<<dim3(T_LEN / 8, HEADS), 128>>>(crn + 2048, N_RN,
                                                kh, kl, vth, vtl, arh, arl);

    // ---- outputs ----
    mma_gemm_bf<<<dim3(DS / 128, T_LEN / 128), 256>>>(
        ash, asl, wsoh, wsol, out_s, T_LEN, DS, DS, DS,
        s, rsp, gate_v);
    mma_gemm_bf<<<dim3(DR / 128, ROWS_R / 128), 256>>>(
        arh, arl, wroh, wrol, out_r, ROWS_R, DR, DR, DR,
        r, nullptr, nullptr);
}

// round 8
// speedup vs baseline: 3.7972x; 1.0314x over previous
#include <cuda_runtime.h>
#include <cuda_bf16.h>
#include <math.h>
#include <stdint.h>

// ---------------- problem constants ----------------
#define T_LEN 1024
#define NSLOT 8
#define DS 1024
#define DR 512
#define HEADS 8
#define DHS 128
#define DHR 64
#define TOPK 4
#define ROWS_R (T_LEN * NSLOT)   // 8192
#define SCALE_S 0.08838834764831845f  // 1/sqrt(128)
#define SCALE_R 0.125f                // 1/sqrt(64)
#define EPS 1e-6f

// fused layouts
#define N_SN 2048        // q(1024) | kr(512) | vr(512), K=1024
#define N_RN 2560        // k(1024) | v(1024) | qr(512), K=512

// ---------------- scratch (static device memory; no allocation) -------------
__device__ __nv_bfloat16 g_sn_h[T_LEN * DS], g_sn_l[T_LEN * DS];
__device__ __nv_bfloat16 g_rn_h[ROWS_R * DR], g_rn_l[ROWS_R * DR];
__device__ __nv_bfloat16 g_as_h[T_LEN * DS], g_as_l[T_LEN * DS];
__device__ __nv_bfloat16 g_ar_h[ROWS_R * DR], g_ar_l[ROWS_R * DR];
__device__ __nv_bfloat16 g_wsn_h[N_SN * DS], g_wsn_l[N_SN * DS];
__device__ __nv_bfloat16 g_wrn_h[N_RN * DR], g_wrn_l[N_RN * DR];
__device__ __nv_bfloat16 g_wso_h[DS * DS], g_wso_l[DS * DS];
__device__ __nv_bfloat16 g_wro_h[DR * DR], g_wro_l[DR * DR];
__device__ float g_csn[T_LEN * N_SN];     // q | kr | vr
__device__ float g_crn[ROWS_R * N_RN];    // k | v | qr
__device__ float g_rsp[T_LEN * DS];
__device__ uint32_t g_kh[T_LEN * 256], g_kl[T_LEN * 256];
__device__ uint32_t g_vth[HEADS * DHR * (T_LEN / 2)];
__device__ uint32_t g_vtl[HEADS * DHR * (T_LEN / 2)];

// ---------------- PTX helpers ----------------
__device__ __forceinline__ uint32_t smem_u32(const void* p) {
    uint32_t a;
    asm("{ .reg .u64 t; cvta.to.shared.u64 t, %1; cvt.u32.u64 %0, t; }"
        : "=r"(a) : "l"(p));
    return a;
}
__device__ __forceinline__ void cp16(uint32_t dst, const void* src) {
    asm volatile("cp.async.cg.shared.global [%0], [%1], 16;"
                 :: "r"(dst), "l"(src) : "memory");
}
__device__ __forceinline__ void ldm_x4(uint32_t* r, uint32_t addr) {
    asm volatile("ldmatrix.sync.aligned.m8n8.x4.shared.b16 {%0,%1,%2,%3}, [%4];"
                 : "=r"(r[0]), "=r"(r[1]), "=r"(r[2]), "=r"(r[3]) : "r"(addr));
}
__device__ __forceinline__ void mma_bf16(
    float* c, const uint32_t* a, uint32_t b0, uint32_t b1)
{
    asm volatile(
        "mma.sync.aligned.m16n8k16.row.col.f32.bf16.bf16.f32 "
        "{%0,%1,%2,%3}, {%4,%5,%6,%7}, {%8,%9}, {%0,%1,%2,%3};"
        : "+f"(c[0]), "+f"(c[1]), "+f"(c[2]), "+f"(c[3])
        : "r"(a[0]), "r"(a[1]), "r"(a[2]), "r"(a[3]), "r"(b0), "r"(b1));
}
__device__ __forceinline__ void split2(float x, float y,
                                       uint32_t& hi, uint32_t& lo)
{
    __nv_bfloat162 h = __floats2bfloat162_rn(x, y);
    float xr = x - __bfloat162float(h.x);
    float yr = y - __bfloat162float(h.y);
    __nv_bfloat162 l = __floats2bfloat162_rn(xr, yr);
    hi = *(uint32_t*)&h;
    lo = *(uint32_t*)&l;
}

// ---------------- batched weight transpose + split (single launch) ----------
// All 8 weights: W (K,N) -> Wt hi/lo (N,K) into fused arenas.
__global__ __launch_bounds__(256) void wtrans_all(
    const float* __restrict__ Wsq, const float* __restrict__ Wsk,
    const float* __restrict__ Wsv, const float* __restrict__ Wso,
    const float* __restrict__ Wrq, const float* __restrict__ Wrk,
    const float* __restrict__ Wrv, const float* __restrict__ Wro,
    __nv_bfloat16* __restrict__ wsnh, __nv_bfloat16* __restrict__ wsnl,
    __nv_bfloat16* __restrict__ wrnh, __nv_bfloat16* __restrict__ wrnl,
    __nv_bfloat16* __restrict__ wsoh, __nv_bfloat16* __restrict__ wsol,
    __nv_bfloat16* __restrict__ wroh, __nv_bfloat16* __restrict__ wrol)
{
    int b = blockIdx.x;
    const float* W;
    __nv_bfloat16 *th, *tl;
    int K, N;
    if (b < 1024)      { W = Wsq; th = wsnh; tl = wsnl; K = 1024; N = 1024; }
    else if (b < 1536) { b -= 1024; W = Wrk; th = wsnh + 1024 * 1024;
                         tl = wsnl + 1024 * 1024; K = 1024; N = 512; }
    else if (b < 2048) { b -= 1536; W = Wrv; th = wsnh + 1536 * 1024;
                         tl = wsnl + 1536 * 1024; K = 1024; N = 512; }
    else if (b < 2560) { b -= 2048; W = Wsk; th = wrnh; tl = wrnl;
                         K = 512; N = 1024; }
    else if (b < 3072) { b -= 2560; W = Wsv; th = wrnh + 1024 * 512;
                         tl = wrnl + 1024 * 512; K = 512; N = 1024; }
    else if (b < 3328) { b -= 3072; W = Wrq; th = wrnh + 2048 * 512;
                         tl = wrnl + 2048 * 512; K = 512; N = 512; }
    else if (b < 4352) { b -= 3328; W = Wso; th = wsoh; tl = wsol;
                         K = 1024; N = 1024; }
    else               { b -= 4352; W = Wro; th = wroh; tl = wrol;
                         K = 512; N = 512; }

    int ntx = N >> 5;
    int bx = (b % ntx) * 32;   // N dim
    int by = (b / ntx) * 32;   // K dim

    __shared__ float t[32][33];
    int tx = threadIdx.x & 31, ty = threadIdx.x >> 5;
    #pragma unroll
    for (int i = 0; i < 4; i++)
        t[ty + i * 8][tx] = W[(size_t)(by + ty + i * 8) * N + bx + tx];
    __syncthreads();
    #pragma unroll
    for (int i = 0; i < 4; i++) {
        int n = bx + ty + i * 8;
        int k = by + tx;
        float v = t[tx][ty + i * 8];
        __nv_bfloat16 h = __float2bfloat16(v);
        th[(size_t)n * K + k] = h;
        tl[(size_t)n * K + k] = __float2bfloat16(v - __bfloat162float(h));
    }
}

// ---------------- rmsnorm with split bf16 output ----------------
__global__ __launch_bounds__(256) void rmsnorm_split(
    const float* __restrict__ x, const float* __restrict__ w,
    __nv_bfloat16* __restrict__ oh, __nv_bfloat16* __restrict__ ol, int C)
{
    int row = blockIdx.x;
    const float* xr = x + (size_t)row * C;
    float s = 0.f;
    for (int j = threadIdx.x; j < C; j += 256) {
        float v = xr[j];
        s += v * v;
    }
    __shared__ float red[8];
    int lane = threadIdx.x & 31, warp = threadIdx.x >> 5;
    #pragma unroll
    for (int off = 16; off; off >>= 1) s += __shfl_xor_sync(0xffffffffu, s, off);
    if (lane == 0) red[warp] = s;
    __syncthreads();
    __shared__ float scale;
    if (threadIdx.x == 0) {
        float tot = 0.f;
        #pragma unroll
        for (int i = 0; i < 8; i++) tot += red[i];
        scale = rsqrtf(tot / (float)C + EPS);
    }
    __syncthreads();
    float sc = scale;
    uint32_t* ph = (uint32_t*)(oh + (size_t)row * C);
    uint32_t* pl = (uint32_t*)(ol + (size_t)row * C);
    for (int j2 = threadIdx.x; j2 < C / 2; j2 += 256) {
        float v0 = xr[2 * j2] * sc * w[2 * j2];
        float v1 = xr[2 * j2 + 1] * sc * w[2 * j2 + 1];
        uint32_t h, l;
        split2(v0, v1, h, l);
        ph[j2] = h;
        pl[j2] = l;
    }
}

// ---------------- bf16-split mma GEMM: 3-stage pipeline, 1 sync/chunk -------
// C(M x N, row stride ldc) = A(M,K) @ Bt(N,K)^T [+ add1] [+ rowscale*add2]
__global__ __launch_bounds__(256) void mma_gemm_bf(
    const __nv_bfloat16* __restrict__ Ah, const __nv_bfloat16* __restrict__ Al,
    const __nv_bfloat16* __restrict__ Bh, const __nv_bfloat16* __restrict__ Bl,
    float* __restrict__ C, int M, int N, int K, int ldc,
    const float* __restrict__ add1,
    const float* __restrict__ add2, const float* __restrict__ rowscale)
{
    __shared__ __align__(16) uint32_t sAh[3][128 * 8], sAl[3][128 * 8];
    __shared__ __align__(16) uint32_t sBh[3][128 * 8], sBl[3][128 * 8];

    int tid = threadIdx.x;
    int lane = tid & 31, wid = tid >> 5;
    int wm = wid >> 1, wn = wid & 1;
    int bm = blockIdx.y * 128, bn = blockIdx.x * 128;
    int gid = lane >> 2, tig = lane & 3;

    float acc[2][8][4];
    #pragma unroll
    for (int i = 0; i < 2; i++)
        #pragma unroll
        for (int j = 0; j < 8; j++)
            #pragma unroll
            for (int l = 0; l < 4; l++) acc[i][j][l] = 0.f;

    uint32_t bAh = smem_u32(sAh), bAl = smem_u32(sAl);
    uint32_t bBh = smem_u32(sBh), bBl = smem_u32(sBl);

    uint32_t aoff[2], boff[4];
    {
        int lrow = lane & 7;
        int rA = wm * 32 + lrow + (lane & 8);
        int cA = (lane & 16) >> 2;
        aoff[0] = (uint32_t)(rA * 8 + cA) * 4;
        aoff[1] = (uint32_t)((rA + 16) * 8 + cA) * 4;
        int rB = wn * 64 + lrow + ((lane & 16) >> 1);
        int cB = (lane & 8) >> 1;
        #pragma unroll
        for (int ntp = 0; ntp < 4; ntp++)
            boff[ntp] = (uint32_t)((rB + ntp * 16) * 8 + cB) * 4;
    }

    int row = tid >> 1;
    int gg = tid & 1;
    auto issue = [&](int st, int k0) {
        uint32_t doff = (uint32_t)(st * 128 * 8 + row * 8 + gg * 4) * 4;
        size_t asrc = (size_t)(bm + row) * K + k0 + gg * 8;
        size_t bsrc = (size_t)(bn + row) * K + k0 + gg * 8;
        cp16(bAh + doff, Ah + asrc);
        cp16(bAl + doff, Al + asrc);
        cp16(bBh + doff, Bh + bsrc);
        cp16(bBl + doff, Bl + bsrc);
        asm volatile("cp.async.commit_group;" ::: "memory");
    };

    int nch = K >> 4;
    issue(0, 0);
    if (nch > 1) issue(1, 16);

    for (int c = 0; c < nch; c++) {
        if (c + 1 < nch) {
            asm volatile("cp.async.wait_group 1;" ::: "memory");
        } else {
            asm volatile("cp.async.wait_group 0;" ::: "memory");
        }
        __syncthreads();
        if (c + 2 < nch) issue((c + 2) % 3, (c + 2) * 16);

        uint32_t stoff = (uint32_t)((c % 3) * 128 * 8 * 4);

        uint32_t ah[2][4], al[2][4], bh[4][4], bl[4][4];
        ldm_x4(ah[0], bAh + stoff + aoff[0]);
        ldm_x4(ah[1], bAh + stoff + aoff[1]);
        ldm_x4(al[0], bAl + stoff + aoff[0]);
        ldm_x4(al[1], bAl + stoff + aoff[1]);
        #pragma unroll
        for (int ntp = 0; ntp < 4; ntp++) {
            ldm_x4(bh[ntp], bBh + stoff + boff[ntp]);
            ldm_x4(bl[ntp], bBl + stoff + boff[ntp]);
        }

        #pragma unroll
        for (int nt = 0; nt < 8; nt++) {
            int p = nt >> 1, q2 = (nt & 1) << 1;
            uint32_t b0h = bh[p][q2], b1h = bh[p][q2 + 1];
            uint32_t b0l = bl[p][q2], b1l = bl[p][q2 + 1];
            mma_bf16(acc[0][nt], ah[0], b0h, b1h);
            mma_bf16(acc[0][nt], ah[0], b0l, b1l);
            mma_bf16(acc[0][nt], al[0], b0h, b1h);
            mma_bf16(acc[1][nt], ah[1], b0h, b1h);
            mma_bf16(acc[1][nt], ah[1], b0l, b1l);
            mma_bf16(acc[1][nt], al[1], b0h, b1h);
        }
    }

    #pragma unroll
    for (int mt = 0; mt < 2; mt++) {
        int r0 = bm + wm * 32 + mt * 16 + gid;
        float rs0 = (rowscale != nullptr) ? rowscale[r0] : 0.f;
        float rs8 = (rowscale != nullptr) ? rowscale[r0 + 8] : 0.f;
        #pragma unroll
        for (int nt = 0; nt < 8; nt++) {
            int col = bn + wn * 64 + nt * 8 + 2 * tig;
            size_t o0 = (size_t)r0 * ldc + col;
            size_t o8 = (size_t)(r0 + 8) * ldc + col;
            float2 v0 = make_float2(acc[mt][nt][0], acc[mt][nt][1]);
            float2 v8 = make_float2(acc[mt][nt][2], acc[mt][nt][3]);
            if (add1) {
                float2 x = *(const float2*)(add1 + o0);
                v0.x += x.x; v0.y += x.y;
                x = *(const float2*)(add1 + o8);
                v8.x += x.x; v8.y += x.y;
            }
            if (add2) {
                float2 x = *(const float2*)(add2 + o0);
                v0.x += rs0 * x.x; v0.y += rs0 * x.y;
                x = *(const float2*)(add2 + o8);
                v8.x += rs8 * x.x; v8.y += rs8 * x.y;
            }
            *(float2*)(C + o0) = v0;
            *(float2*)(C + o8) = v8;
        }
    }
}

// ---------------- s-attention + top-k sparse (strided inputs) ---------------
__global__ __launch_bounds__(256) void s_attn_kernel(
    const float* __restrict__ qmat,
    const float* __restrict__ kmat,
    const float* __restrict__ vmat,
    int qld, int kvld,
    __nv_bfloat16* __restrict__ as_h,
    __nv_bfloat16* __restrict__ as_l,
    float* __restrict__ rsp)
{
    int t = blockIdx.x;
    int tid = threadIdx.x;
    int warp = tid >> 5, lane = tid & 31;

    __shared__ float qs[DS];
    __shared__ float logits[HEADS][NSLOT];
    __shared__ float wattn[HEADS][NSLOT];
    __shared__ float wsp[NSLOT];

    for (int j = tid; j < DS; j += 256) qs[j] = qmat[(size_t)t * qld + j];
    __syncthreads();

    {
        int h = warp;
        #pragma unroll
        for (int n = 0; n < NSLOT; n++) {
            const float* krow = kmat + (size_t)(t * NSLOT + n) * kvld + h * DHS;
            const float* qrow = qs + h * DHS;
            float p = 0.f;
            #pragma unroll
            for (int d = lane; d < DHS; d += 32) p += qrow[d] * krow[d];
            #pragma unroll
            for (int off = 16; off; off >>= 1) p += __shfl_xor_sync(0xffffffffu, p, off);
            if (lane == 0) logits[h][n] = p;
        }
    }
    __syncthreads();

    if (tid < HEADS) {
        int h = tid;
        float m = -INFINITY;
        #pragma unroll
        for (int n = 0; n < NSLOT; n++) m = fmaxf(m, logits[h][n] * SCALE_S);
        float s = 0.f;
        #pragma unroll
        for (int n = 0; n < NSLOT; n++) {
            float e = __expf(logits[h][n] * SCALE_S - m);
            wattn[h][n] = e;
            s += e;
        }
        float inv = 1.f / s;
        #pragma unroll
        for (int n = 0; n < NSLOT; n++) wattn[h][n] *= inv;
    }
    if (tid == 8) {
        float sp[NSLOT];
        #pragma unroll
        for (int n = 0; n < NSLOT; n++) {
            float a = 0.f;
            #pragma unroll
            for (int h = 0; h < HEADS; h++) a += logits[h][n];
            sp[n] = a * SCALE_S;
        }
        bool sel[NSLOT];
        #pragma unroll
        for (int n = 0; n < NSLOT; n++) { sel[n] = false; wsp[n] = 0.f; }
        int idxs[TOPK];
        #pragma unroll
        for (int kk = 0; kk < TOPK; kk++) {
            int best = -1; float bv = -INFINITY;
            #pragma unroll
            for (int n = 0; n < NSLOT; n++)
                if (!sel[n] && sp[n] > bv) { bv = sp[n]; best = n; }
            sel[best] = true; idxs[kk] = best;
        }
        float m = -INFINITY;
        #pragma unroll
        for (int kk = 0; kk < TOPK; kk++) m = fmaxf(m, sp[idxs[kk]]);
        float s = 0.f, e[TOPK];
        #pragma unroll
        for (int kk = 0; kk < TOPK; kk++) { e[kk] = __expf(sp[idxs[kk]] - m); s += e[kk]; }
        float inv = 1.f / s;
        #pragma unroll
        for (int kk = 0; kk < TOPK; kk++) wsp[idxs[kk]] = e[kk] * inv;
    }
    __syncthreads();

    uint32_t* ph = (uint32_t*)(as_h + (size_t)t * DS);
    uint32_t* pl = (uint32_t*)(as_l + (size_t)t * DS);
    for (int j2 = tid; j2 < DS / 2; j2 += 256) {
        int j = 2 * j2;
        int h = j >> 7;
        float a0 = 0.f, a1 = 0.f, b0 = 0.f, b1 = 0.f;
        #pragma unroll
        for (int n = 0; n < NSLOT; n++) {
            float2 vv = *(const float2*)(vmat + (size_t)(t * NSLOT + n) * kvld + j);
            a0 += wattn[h][n] * vv.x;
            a1 += wattn[h][n] * vv.y;
            b0 += wsp[n] * vv.x;
            b1 += wsp[n] * vv.y;
        }
        uint32_t hh, ll;
        split2(a0, a1, hh, ll);
        ph[j2] = hh;
        pl[j2] = ll;
        *(float2*)(rsp + (size_t)t * DS + j) = make_float2(b0, b1);
    }
}

// ---------------- merged K/V pre-split convert ----------------
__global__ __launch_bounds__(256) void conv_kv(
    const float* __restrict__ kr, int kld,
    const float* __restrict__ vr, int vld,
    uint32_t* __restrict__ kh, uint32_t* __restrict__ kl,
    uint32_t* __restrict__ vh, uint32_t* __restrict__ vl)
{
    if (blockIdx.x < T_LEN) {
        int t = blockIdx.x, j = threadIdx.x;
        float2 v = *(const float2*)(kr + (size_t)t * kld + 2 * j);
        uint32_t h, l;
        split2(v.x, v.y, h, l);
        kh[(size_t)t * 256 + j] = h;
        kl[(size_t)t * 256 + j] = l;
    } else {
        int idx = (blockIdx.x - T_LEN) * 256 + threadIdx.x;
        int pp = idx & 511;
        int d = (idx >> 9) & 63;
        int h = idx >> 15;
        float v0 = vr[(size_t)(2 * pp) * vld + h * DHR + d];
        float v1 = vr[(size_t)(2 * pp + 1) * vld + h * DHR + d];
        uint32_t hh, ll;
        split2(v0, v1, hh, ll);
        vh[idx] = hh;
        vl[idx] = ll;
    }
}

// ---------------- causal r-attention: MMA flash, pre-split K/V --------------
__global__ __launch_bounds__(128) void r_attn_mma(
    const float* __restrict__ qr, int qld,
    const uint32_t* __restrict__ kh_g, const uint32_t* __restrict__ kl_g,
    const uint32_t* __restrict__ vh_g, const uint32_t* __restrict__ vl_g,
    __nv_bfloat16* __restrict__ ar_h, __nv_bfloat16* __restrict__ ar_l)
{
    __shared__ __align__(16) uint32_t skh[64 * 32], skl[64 * 32];
    __shared__ __align__(16) uint32_t svh[64 * 32], svl[64 * 32];

    int tt = (int)(gridDim.x - 1 - blockIdx.x);
    int h = blockIdx.y;
    int t0 = tt * 8;
    int hb = h * DHR;

    int tid = threadIdx.x;
    int w = tid >> 5, lane = tid & 31;
    int gid = lane >> 2, tig = lane & 3;

    uint32_t bkh = smem_u32(skh), bkl = smem_u32(skl);
    uint32_t bvh = smem_u32(svh), bvl = smem_u32(svl);

    int r0 = t0 * 8 + 16 * w + gid;
    int r8 = r0 + 8;
    uint32_t qh[4][4], ql[4][4];
    #pragma unroll
    for (int kc = 0; kc < 4; kc++) {
        float2 x0 = *(const float2*)(qr + (size_t)r0 * qld + hb + kc * 16 + 2 * tig);
        float2 x1 = *(const float2*)(qr + (size_t)r8 * qld + hb + kc * 16 + 2 * tig);
        float2 x2 = *(const float2*)(qr + (size_t)r0 * qld + hb + kc * 16 + 2 * tig + 8);
        float2 x3 = *(const float2*)(qr + (size_t)r8 * qld + hb + kc * 16 + 2 * tig + 8);
        split2(x0.x * SCALE_R, x0.y * SCALE_R, qh[kc][0], ql[kc][0]);
        split2(x1.x * SCALE_R, x1.y * SCALE_R, qh[kc][1], ql[kc][1]);
        split2(x2.x * SCALE_R, x2.y * SCALE_R, qh[kc][2], ql[kc][2]);
        split2(x3.x * SCALE_R, x3.y * SCALE_R, qh[kc][3], ql[kc][3]);
    }
    int tok0 = t0 + ((16 * w + gid) >> 3);
    int tok8 = t0 + ((16 * w + gid + 8) >> 3);

    float m0 = -INFINITY, m1 = -INFINITY, l0 = 0.f, l1 = 0.f;
    float acco[8][4];
    #pragma unroll
    for (int i = 0; i < 8; i++)
        #pragma unroll
        for (int j = 0; j < 4; j++) acco[i][j] = 0.f;

    int plast = t0 + 7;
    for (int p0 = 0; p0 <= plast; p0 += 64) {
        __syncthreads();
        int pp0 = p0 >> 1;
        #pragma unroll
        for (int it = 0; it < 4; it++) {
            int idx = tid + it * 128;
            int p = idx >> 3, g = idx & 7;
            uint32_t doff = (uint32_t)(p * 32 + ((g ^ (p & 7)) << 2)) * 4;
            size_t ksrc = (size_t)(p0 + p) * 256 + h * 32 + g * 4;
            cp16(bkh + doff, kh_g + ksrc);
            cp16(bkl + doff, kl_g + ksrc);
            size_t vsrc = (size_t)h * 32768 + (size_t)p * 512 + pp0 + g * 4;
            cp16(bvh + doff, vh_g + vsrc);
            cp16(bvl + doff, vl_g + vsrc);
        }
        asm volatile("cp.async.commit_group;" ::: "memory");
        asm volatile("cp.async.wait_group 0;" ::: "memory");
        __syncthreads();

        float s[8][4];
        #pragma unroll
        for (int i = 0; i < 8; i++)
            #pragma unroll
            for (int j = 0; j < 4; j++) s[i][j] = 0.f;

        #pragma unroll
        for (int nt = 0; nt < 8; nt++) {
            int n0 = nt * 8 + gid;
            int sw = n0 & 7;
            #pragma unroll
            for (int kc = 0; kc < 4; kc++) {
                uint32_t o0 = n0 * 32 + (((2 * kc) ^ sw) << 2) + tig;
                uint32_t o1 = n0 * 32 + (((2 * kc + 1) ^ sw) << 2) + tig;
                uint32_t bh0 = skh[o0], bh1 = skh[o1];
                uint32_t bl0 = skl[o0], bl1 = skl[o1];
                mma_bf16(s[nt], qh[kc], bh0, bh1);
                mma_bf16(s[nt], qh[kc], bl0, bl1);
                mma_bf16(s[nt], ql[kc], bh0, bh1);
            }
        }

        if (p0 + 64 > t0) {
            #pragma unroll
            for (int nt = 0; nt < 8; nt++) {
                int pg = p0 + nt * 8 + 2 * tig;
                if (pg > tok0)     s[nt][0] = -INFINITY;
                if (pg + 1 > tok0) s[nt][1] = -INFINITY;
                if (pg > tok8)     s[nt][2] = -INFINITY;
                if (pg + 1 > tok8) s[nt][3] = -INFINITY;
            }
        }

        float mx0 = -INFINITY, mx1 = -INFINITY;
        #pragma unroll
        for (int nt = 0; nt < 8; nt++) {
            mx0 = fmaxf(mx0, fmaxf(s[nt][0], s[nt][1]));
            mx1 = fmaxf(mx1, fmaxf(s[nt][2], s[nt][3]));
        }
        mx0 = fmaxf(mx0, __shfl_xor_sync(0xffffffffu, mx0, 1));
        mx0 = fmaxf(mx0, __shfl_xor_sync(0xffffffffu, mx0, 2));
        mx1 = fmaxf(mx1, __shfl_xor_sync(0xffffffffu, mx1, 1));
        mx1 = fmaxf(mx1, __shfl_xor_sync(0xffffffffu, mx1, 2));
        float nm0 = fmaxf(m0, mx0), nm1 = fmaxf(m1, mx1);
        float cr0 = __expf(m0 - nm0), cr1 = __expf(m1 - nm1);
        m0 = nm0; m1 = nm1;

        float rs0 = 0.f, rs1 = 0.f;
        #pragma unroll
        for (int nt = 0; nt < 8; nt++) {
            s[nt][0] = __expf(s[nt][0] - nm0);
            s[nt][1] = __expf(s[nt][1] - nm0);
            s[nt][2] = __expf(s[nt][2] - nm1);
            s[nt][3] = __expf(s[nt][3] - nm1);
            rs0 += s[nt][0] + s[nt][1];
            rs1 += s[nt][2] + s[nt][3];
        }
        rs0 += __shfl_xor_sync(0xffffffffu, rs0, 1);
        rs0 += __shfl_xor_sync(0xffffffffu, rs0, 2);
        rs1 += __shfl_xor_sync(0xffffffffu, rs1, 1);
        rs1 += __shfl_xor_sync(0xffffffffu, rs1, 2);
        l0 = l0 * cr0 + rs0;
        l1 = l1 * cr1 + rs1;

        #pragma unroll
        for (int ntd = 0; ntd < 8; ntd++) {
            acco[ntd][0] *= cr0; acco[ntd][1] *= cr0;
            acco[ntd][2] *= cr1; acco[ntd][3] *= cr1;
        }

        #pragma unroll
        for (int kc = 0; kc < 4; kc++) {
            uint32_t pah[4], pal[4];
            split2(s[2 * kc][0],     s[2 * kc][1],     pah[0], pal[0]);
            split2(s[2 * kc][2],     s[2 * kc][3],     pah[1], pal[1]);
            split2(s[2 * kc + 1][0], s[2 * kc + 1][1], pah[2], pal[2]);
            split2(s[2 * kc + 1][2], s[2 * kc + 1][3], pah[3], pal[3]);
            #pragma unroll
            for (int ntd = 0; ntd < 8; ntd++) {
                int d0 = ntd * 8 + gid;
                int sw = d0 & 7;
                uint32_t o0 = d0 * 32 + (((2 * kc) ^ sw) << 2) + tig;
                uint32_t o1 = d0 * 32 + (((2 * kc + 1) ^ sw) << 2) + tig;
                uint32_t bh0 = svh[o0], bh1 = svh[o1];
                uint32_t bl0 = svl[o0], bl1 = svl[o1];
                mma_bf16(acco[ntd], pah, bh0, bh1);
                mma_bf16(acco[ntd], pah, bl0, bl1);
                mma_bf16(acco[ntd], pal, bh0, bh1);
            }
        }
    }

    float i0 = 1.f / l0, i1 = 1.f / l1;
    #pragma unroll
    for (int ntd = 0; ntd < 8; ntd++) {
        int col = hb + ntd * 8 + 2 * tig;
        uint32_t hh, ll;
        split2(acco[ntd][0] * i0, acco[ntd][1] * i0, hh, ll);
        *(uint32_t*)(ar_h + (size_t)r0 * DR + col) = hh;
        *(uint32_t*)(ar_l + (size_t)r0 * DR + col) = ll;
        split2(acco[ntd][2] * i1, acco[ntd][3] * i1, hh, ll);
        *(uint32_t*)(ar_h + (size_t)r8 * DR + col) = hh;
        *(uint32_t*)(ar_l + (size_t)r8 * DR + col) = ll;
    }
}

// ---------------- host launch ----------------
extern "C" void kernel_launch(void* const* d_in, const int* in_sizes, int n_in,
                              void* d_out, int out_size)
{
    const float* s      = (const float*)d_in[0];
    const float* r      = (const float*)d_in[1];
    const float* gate_v = (const float*)d_in[2];
    const float* nsw    = (const float*)d_in[3];
    const float* nrw    = (const float*)d_in[4];
    const float* Wsq    = (const float*)d_in[5];
    const float* Wsk    = (const float*)d_in[6];
    const float* Wsv    = (const float*)d_in[7];
    const float* Wso    = (const float*)d_in[8];
    const float* Wrq    = (const float*)d_in[9];
    const float* Wrk    = (const float*)d_in[10];
    const float* Wrv    = (const float*)d_in[11];
    const float* Wro    = (const float*)d_in[12];

    float* out_s = (float*)d_out;
    float* out_r = (float*)d_out + T_LEN * DS;

    __nv_bfloat16 *snh, *snl, *rnh, *rnl, *ash, *asl, *arh, *arl;
    __nv_bfloat16 *wsnh, *wsnl, *wrnh, *wrnl, *wsoh, *wsol, *wroh, *wrol;
    float *csn, *crn, *rsp;
    uint32_t *kh, *kl, *vth, *vtl;
    cudaGetSymbolAddress((void**)&snh, g_sn_h);
    cudaGetSymbolAddress((void**)&snl, g_sn_l);
    cudaGetSymbolAddress((void**)&rnh, g_rn_h);
    cudaGetSymbolAddress((void**)&rnl, g_rn_l);
    cudaGetSymbolAddress((void**)&ash, g_as_h);
    cudaGetSymbolAddress((void**)&asl, g_as_l);
    cudaGetSymbolAddress((void**)&arh, g_ar_h);
    cudaGetSymbolAddress((void**)&arl, g_ar_l);
    cudaGetSymbolAddress((void**)&wsnh, g_wsn_h);
    cudaGetSymbolAddress((void**)&wsnl, g_wsn_l);
    cudaGetSymbolAddress((void**)&wrnh, g_wrn_h);
    cudaGetSymbolAddress((void**)&wrnl, g_wrn_l);
    cudaGetSymbolAddress((void**)&wsoh, g_wso_h);
    cudaGetSymbolAddress((void**)&wsol, g_wso_l);
    cudaGetSymbolAddress((void**)&wroh, g_wro_h);
    cudaGetSymbolAddress((void**)&wrol, g_wro_l);
    cudaGetSymbolAddress((void**)&csn, g_csn);
    cudaGetSymbolAddress((void**)&crn, g_crn);
    cudaGetSymbolAddress((void**)&rsp, g_rsp);
    cudaGetSymbolAddress((void**)&kh, g_kh);
    cudaGetSymbolAddress((void**)&kl, g_kl);
    cudaGetSymbolAddress((void**)&vth, g_vth);
    cudaGetSymbolAddress((void**)&vtl, g_vtl);

    // ---- all weight transposes in ONE launch ----
    wtrans_all<<<4608, 256>>>(Wsq, Wsk, Wsv, Wso, Wrq, Wrk, Wrv, Wro,
                              wsnh, wsnl, wrnh, wrnl, wsoh, wsol, wroh, wrol);

    // ---- rmsnorm ----
    rmsnorm_split<<<T_LEN, 256>>>(s, nsw, snh, snl, DS);
    rmsnorm_split<<<ROWS_R, 256>>>(r, nrw, rnh, rnl, DR);

    // ---- fused projection GEMMs ----
    mma_gemm_bf<<<dim3(N_SN / 128, T_LEN / 128), 256>>>(
        snh, snl, wsnh, wsnl, csn, T_LEN, N_SN, DS, N_SN,
        nullptr, nullptr, nullptr);
    mma_gemm_bf<<<dim3(N_RN / 128, ROWS_R / 128), 256>>>(
        rnh, rnl, wrnh, wrnl, crn, ROWS_R, N_RN, DR, N_RN,
        nullptr, nullptr, nullptr);

    // ---- pre-split K/V for r-attention (single launch) ----
    conv_kv<<<T_LEN + 1024, 256>>>(csn + 1024, N_SN, csn + 1536, N_SN,
                                   kh, kl, vth, vtl);

    // ---- s-attention + sparse top-k ----
    s_attn_kernel<<<T_LEN, 256>>>(csn, crn, crn + 1024, N_SN, N_RN,
                                  ash, asl, rsp);

    // ---- causal r attention ----
    r_attn_mma<<<dim3(T_LEN / 8, HEADS), 128>>>(crn + 2048, N_RN,
                                                kh, kl, vth, vtl, arh, arl);

    // ---- outputs ----
    mma_gemm_bf<<<dim3(DS / 128, T_LEN / 128), 256>>>(
        ash, asl, wsoh, wsol, out_s, T_LEN, DS, DS, DS,
        s, rsp, gate_v);
    mma_gemm_bf<<<dim3(DR / 128, ROWS_R / 128), 256>>>(
        arh, arl, wroh, wrol, out_r, ROWS_R, DR, DR, DR,
        r, nullptr, nullptr);
}

// round 9
// speedup vs baseline: 4.5179x; 1.1898x over previous
#include <cuda_runtime.h>
#include <cuda_bf16.h>
#include <math.h>
#include <stdint.h>

// ---------------- problem constants ----------------
#define T_LEN 1024
#define NSLOT 8
#define DS 1024
#define DR 512
#define HEADS 8
#define DHS 128
#define DHR 64
#define TOPK 4
#define ROWS_R (T_LEN * NSLOT)   // 8192
#define SCALE_S 0.08838834764831845f  // 1/sqrt(128)
#define SCALE_R 0.125f                // 1/sqrt(64)
#define EPS 1e-6f

// fused layouts
#define N_SN 2048        // q(1024) | kr(512) | vr(512), K=1024
#define N_RN 2560        // k(1024) | v(1024) | qr(512), K=512

// ---------------- scratch (static device memory; no allocation) -------------
__device__ __nv_bfloat16 g_sn_h[T_LEN * DS], g_sn_l[T_LEN * DS];
__device__ __nv_bfloat16 g_rn_h[ROWS_R * DR], g_rn_l[ROWS_R * DR];
__device__ __nv_bfloat16 g_as_h[T_LEN * DS], g_as_l[T_LEN * DS];
__device__ __nv_bfloat16 g_ar_h[ROWS_R * DR], g_ar_l[ROWS_R * DR];
__device__ __nv_bfloat16 g_wsn_h[N_SN * DS], g_wsn_l[N_SN * DS];
__device__ __nv_bfloat16 g_wrn_h[N_RN * DR], g_wrn_l[N_RN * DR];
__device__ __nv_bfloat16 g_wso_h[DS * DS], g_wso_l[DS * DS];
__device__ __nv_bfloat16 g_wro_h[DR * DR], g_wro_l[DR * DR];
__device__ float g_csn[T_LEN * N_SN];     // q | kr | vr
__device__ float g_crn[ROWS_R * N_RN];    // k | v | qr
__device__ float g_rsp[T_LEN * DS];
__device__ uint32_t g_kh[T_LEN * 256], g_kl[T_LEN * 256];
__device__ uint32_t g_vth[HEADS * DHR * (T_LEN / 2)];
__device__ uint32_t g_vtl[HEADS * DHR * (T_LEN / 2)];

// ---------------- PTX helpers ----------------
__device__ __forceinline__ uint32_t smem_u32(const void* p) {
    uint32_t a;
    asm("{ .reg .u64 t; cvta.to.shared.u64 t, %1; cvt.u32.u64 %0, t; }"
        : "=r"(a) : "l"(p));
    return a;
}
__device__ __forceinline__ void cp16(uint32_t dst, const void* src) {
    asm volatile("cp.async.cg.shared.global [%0], [%1], 16;"
                 :: "r"(dst), "l"(src) : "memory");
}
__device__ __forceinline__ void ldm_x4(uint32_t* r, uint32_t addr) {
    asm volatile("ldmatrix.sync.aligned.m8n8.x4.shared.b16 {%0,%1,%2,%3}, [%4];"
                 : "=r"(r[0]), "=r"(r[1]), "=r"(r[2]), "=r"(r[3]) : "r"(addr));
}
__device__ __forceinline__ void mma_bf16(
    float* c, const uint32_t* a, uint32_t b0, uint32_t b1)
{
    asm volatile(
        "mma.sync.aligned.m16n8k16.row.col.f32.bf16.bf16.f32 "
        "{%0,%1,%2,%3}, {%4,%5,%6,%7}, {%8,%9}, {%0,%1,%2,%3};"
        : "+f"(c[0]), "+f"(c[1]), "+f"(c[2]), "+f"(c[3])
        : "r"(a[0]), "r"(a[1]), "r"(a[2]), "r"(a[3]), "r"(b0), "r"(b1));
}
__device__ __forceinline__ void split2(float x, float y,
                                       uint32_t& hi, uint32_t& lo)
{
    __nv_bfloat162 h = __floats2bfloat162_rn(x, y);
    float xr = x - __bfloat162float(h.x);
    float yr = y - __bfloat162float(h.y);
    __nv_bfloat162 l = __floats2bfloat162_rn(xr, yr);
    hi = *(uint32_t*)&h;
    lo = *(uint32_t*)&l;
}

// ---------------- batched weight transpose + split (single launch) ----------
__global__ __launch_bounds__(256) void wtrans_all(
    const float* __restrict__ Wsq, const float* __restrict__ Wsk,
    const float* __restrict__ Wsv, const float* __restrict__ Wso,
    const float* __restrict__ Wrq, const float* __restrict__ Wrk,
    const float* __restrict__ Wrv, const float* __restrict__ Wro,
    __nv_bfloat16* __restrict__ wsnh, __nv_bfloat16* __restrict__ wsnl,
    __nv_bfloat16* __restrict__ wrnh, __nv_bfloat16* __restrict__ wrnl,
    __nv_bfloat16* __restrict__ wsoh, __nv_bfloat16* __restrict__ wsol,
    __nv_bfloat16* __restrict__ wroh, __nv_bfloat16* __restrict__ wrol)
{
    int b = blockIdx.x;
    const float* W;
    __nv_bfloat16 *th, *tl;
    int K, N;
    if (b < 1024)      { W = Wsq; th = wsnh; tl = wsnl; K = 1024; N = 1024; }
    else if (b < 1536) { b -= 1024; W = Wrk; th = wsnh + 1024 * 1024;
                         tl = wsnl + 1024 * 1024; K = 1024; N = 512; }
    else if (b < 2048) { b -= 1536; W = Wrv; th = wsnh + 1536 * 1024;
                         tl = wsnl + 1536 * 1024; K = 1024; N = 512; }
    else if (b < 2560) { b -= 2048; W = Wsk; th = wrnh; tl = wrnl;
                         K = 512; N = 1024; }
    else if (b < 3072) { b -= 2560; W = Wsv; th = wrnh + 1024 * 512;
                         tl = wrnl + 1024 * 512; K = 512; N = 1024; }
    else if (b < 3328) { b -= 3072; W = Wrq; th = wrnh + 2048 * 512;
                         tl = wrnl + 2048 * 512; K = 512; N = 512; }
    else if (b < 4352) { b -= 3328; W = Wso; th = wsoh; tl = wsol;
                         K = 1024; N = 1024; }
    else               { b -= 4352; W = Wro; th = wroh; tl = wrol;
                         K = 512; N = 512; }

    int ntx = N >> 5;
    int bx = (b % ntx) * 32;
    int by = (b / ntx) * 32;

    __shared__ float t[32][33];
    int tx = threadIdx.x & 31, ty = threadIdx.x >> 5;
    #pragma unroll
    for (int i = 0; i < 4; i++)
        t[ty + i * 8][tx] = W[(size_t)(by + ty + i * 8) * N + bx + tx];
    __syncthreads();
    #pragma unroll
    for (int i = 0; i < 4; i++) {
        int n = bx + ty + i * 8;
        int k = by + tx;
        float v = t[tx][ty + i * 8];
        __nv_bfloat16 h = __float2bfloat16(v);
        th[(size_t)n * K + k] = h;
        tl[(size_t)n * K + k] = __float2bfloat16(v - __bfloat162float(h));
    }
}

// ---------------- rmsnorm with split bf16 output ----------------
__global__ __launch_bounds__(256) void rmsnorm_split(
    const float* __restrict__ x, const float* __restrict__ w,
    __nv_bfloat16* __restrict__ oh, __nv_bfloat16* __restrict__ ol, int C)
{
    int row = blockIdx.x;
    const float* xr = x + (size_t)row * C;
    float s = 0.f;
    for (int j = threadIdx.x; j < C; j += 256) {
        float v = xr[j];
        s += v * v;
    }
    __shared__ float red[8];
    int lane = threadIdx.x & 31, warp = threadIdx.x >> 5;
    #pragma unroll
    for (int off = 16; off; off >>= 1) s += __shfl_xor_sync(0xffffffffu, s, off);
    if (lane == 0) red[warp] = s;
    __syncthreads();
    __shared__ float scale;
    if (threadIdx.x == 0) {
        float tot = 0.f;
        #pragma unroll
        for (int i = 0; i < 8; i++) tot += red[i];
        scale = rsqrtf(tot / (float)C + EPS);
    }
    __syncthreads();
    float sc = scale;
    uint32_t* ph = (uint32_t*)(oh + (size_t)row * C);
    uint32_t* pl = (uint32_t*)(ol + (size_t)row * C);
    for (int j2 = threadIdx.x; j2 < C / 2; j2 += 256) {
        float v0 = xr[2 * j2] * sc * w[2 * j2];
        float v1 = xr[2 * j2 + 1] * sc * w[2 * j2 + 1];
        uint32_t h, l;
        split2(v0, v1, h, l);
        ph[j2] = h;
        pl[j2] = l;
    }
}

// ---------------- bf16-split mma GEMM: 64x128 tile, 2 CTAs/SM ---------------
// C(M x N, row stride ldc) = A(M,K) @ Bt(N,K)^T [+ add1] [+ rowscale*add2]
// 256 threads = 8 warps (2 x 4), warp tile 32x32, 3-stage cp.async ring.
__global__ __launch_bounds__(256, 2) void mma_gemm_bf(
    const __nv_bfloat16* __restrict__ Ah, const __nv_bfloat16* __restrict__ Al,
    const __nv_bfloat16* __restrict__ Bh, const __nv_bfloat16* __restrict__ Bl,
    float* __restrict__ C, int M, int N, int K, int ldc,
    const float* __restrict__ add1,
    const float* __restrict__ add2, const float* __restrict__ rowscale)
{
    __shared__ __align__(16) uint32_t sAh[3][64 * 8], sAl[3][64 * 8];
    __shared__ __align__(16) uint32_t sBh[3][128 * 8], sBl[3][128 * 8];

    int tid = threadIdx.x;
    int lane = tid & 31, wid = tid >> 5;
    int wm = wid & 1, wn = wid >> 1;          // 2 x 4 warp grid
    int bm = blockIdx.y * 64, bn = blockIdx.x * 128;
    int gid = lane >> 2, tig = lane & 3;

    float acc[2][4][4];
    #pragma unroll
    for (int i = 0; i < 2; i++)
        #pragma unroll
        for (int j = 0; j < 4; j++)
            #pragma unroll
            for (int l = 0; l < 4; l++) acc[i][j][l] = 0.f;

    uint32_t bAh = smem_u32(sAh), bAl = smem_u32(sAl);
    uint32_t bBh = smem_u32(sBh), bBl = smem_u32(sBl);

    uint32_t aoff[2], boff[2];
    {
        int lrow = lane & 7;
        int rA = wm * 32 + lrow + (lane & 8);
        int cA = (lane & 16) >> 2;
        aoff[0] = (uint32_t)(rA * 8 + cA) * 4;
        aoff[1] = (uint32_t)((rA + 16) * 8 + cA) * 4;
        int rB = wn * 32 + lrow + ((lane & 16) >> 1);
        int cB = (lane & 8) >> 1;
        boff[0] = (uint32_t)(rB * 8 + cB) * 4;
        boff[1] = (uint32_t)((rB + 16) * 8 + cB) * 4;
    }

    int row = tid >> 1;           // 0..127
    int gg = tid & 1;
    auto issue = [&](int st, int k0) {
        // B: all 256 threads, 128 rows x 2 granules
        uint32_t bdoff = (uint32_t)(st * 128 * 8 + row * 8 + gg * 4) * 4;
        size_t bsrc = (size_t)(bn + row) * K + k0 + gg * 8;
        cp16(bBh + bdoff, Bh + bsrc);
        cp16(bBl + bdoff, Bl + bsrc);
        // A: threads 0..127, 64 rows x 2 granules
        if (tid < 128) {
            uint32_t adoff = (uint32_t)(st * 64 * 8 + row * 8 + gg * 4) * 4;
            size_t asrc = (size_t)(bm + row) * K + k0 + gg * 8;
            cp16(bAh + adoff, Ah + asrc);
            cp16(bAl + adoff, Al + asrc);
        }
        asm volatile("cp.async.commit_group;" ::: "memory");
    };

    int nch = K >> 4;
    issue(0, 0);
    if (nch > 1) issue(1, 16);

    for (int c = 0; c < nch; c++) {
        if (c + 1 < nch) {
            asm volatile("cp.async.wait_group 1;" ::: "memory");
        } else {
            asm volatile("cp.async.wait_group 0;" ::: "memory");
        }
        __syncthreads();
        if (c + 2 < nch) issue((c + 2) % 3, (c + 2) * 16);

        uint32_t aoffst = (uint32_t)((c % 3) * 64 * 8 * 4);
        uint32_t boffst = (uint32_t)((c % 3) * 128 * 8 * 4);

        uint32_t ah[2][4], al[2][4], bh[2][4], bl[2][4];
        ldm_x4(ah[0], bAh + aoffst + aoff[0]);
        ldm_x4(ah[1], bAh + aoffst + aoff[1]);
        ldm_x4(al[0], bAl + aoffst + aoff[0]);
        ldm_x4(al[1], bAl + aoffst + aoff[1]);
        ldm_x4(bh[0], bBh + boffst + boff[0]);
        ldm_x4(bh[1], bBh + boffst + boff[1]);
        ldm_x4(bl[0], bBl + boffst + boff[0]);
        ldm_x4(bl[1], bBl + boffst + boff[1]);

        #pragma unroll
        for (int nt = 0; nt < 4; nt++) {
            int p = nt >> 1, q2 = (nt & 1) << 1;
            uint32_t b0h = bh[p][q2], b1h = bh[p][q2 + 1];
            uint32_t b0l = bl[p][q2], b1l = bl[p][q2 + 1];
            mma_bf16(acc[0][nt], ah[0], b0h, b1h);
            mma_bf16(acc[0][nt], ah[0], b0l, b1l);
            mma_bf16(acc[0][nt], al[0], b0h, b1h);
            mma_bf16(acc[1][nt], ah[1], b0h, b1h);
            mma_bf16(acc[1][nt], ah[1], b0l, b1l);
            mma_bf16(acc[1][nt], al[1], b0h, b1h);
        }
    }

    #pragma unroll
    for (int mt = 0; mt < 2; mt++) {
        int r0 = bm + wm * 32 + mt * 16 + gid;
        float rs0 = (rowscale != nullptr) ? rowscale[r0] : 0.f;
        float rs8 = (rowscale != nullptr) ? rowscale[r0 + 8] : 0.f;
        #pragma unroll
        for (int nt = 0; nt < 4; nt++) {
            int col = bn + wn * 32 + nt * 8 + 2 * tig;
            size_t o0 = (size_t)r0 * ldc + col;
            size_t o8 = (size_t)(r0 + 8) * ldc + col;
            float2 v0 = make_float2(acc[mt][nt][0], acc[mt][nt][1]);
            float2 v8 = make_float2(acc[mt][nt][2], acc[mt][nt][3]);
            if (add1) {
                float2 x = *(const float2*)(add1 + o0);
                v0.x += x.x; v0.y += x.y;
                x = *(const float2*)(add1 + o8);
                v8.x += x.x; v8.y += x.y;
            }
            if (add2) {
                float2 x = *(const float2*)(add2 + o0);
                v0.x += rs0 * x.x; v0.y += rs0 * x.y;
                x = *(const float2*)(add2 + o8);
                v8.x += rs8 * x.x; v8.y += rs8 * x.y;
            }
            *(float2*)(C + o0) = v0;
            *(float2*)(C + o8) = v8;
        }
    }
}

// ---------------- s-attention + top-k sparse (strided inputs) ---------------
__global__ __launch_bounds__(256) void s_attn_kernel(
    const float* __restrict__ qmat,
    const float* __restrict__ kmat,
    const float* __restrict__ vmat,
    int qld, int kvld,
    __nv_bfloat16* __restrict__ as_h,
    __nv_bfloat16* __restrict__ as_l,
    float* __restrict__ rsp)
{
    int t = blockIdx.x;
    int tid = threadIdx.x;
    int warp = tid >> 5, lane = tid & 31;

    __shared__ float qs[DS];
    __shared__ float logits[HEADS][NSLOT];
    __shared__ float wattn[HEADS][NSLOT];
    __shared__ float wsp[NSLOT];

    for (int j = tid; j < DS; j += 256) qs[j] = qmat[(size_t)t * qld + j];
    __syncthreads();

    {
        int h = warp;
        #pragma unroll
        for (int n = 0; n < NSLOT; n++) {
            const float* krow = kmat + (size_t)(t * NSLOT + n) * kvld + h * DHS;
            const float* qrow = qs + h * DHS;
            float p = 0.f;
            #pragma unroll
            for (int d = lane; d < DHS; d += 32) p += qrow[d] * krow[d];
            #pragma unroll
            for (int off = 16; off; off >>= 1) p += __shfl_xor_sync(0xffffffffu, p, off);
            if (lane == 0) logits[h][n] = p;
        }
    }
    __syncthreads();

    if (tid < HEADS) {
        int h = tid;
        float m = -INFINITY;
        #pragma unroll
        for (int n = 0; n < NSLOT; n++) m = fmaxf(m, logits[h][n] * SCALE_S);
        float s = 0.f;
        #pragma unroll
        for (int n = 0; n < NSLOT; n++) {
            float e = __expf(logits[h][n] * SCALE_S - m);
            wattn[h][n] = e;
            s += e;
        }
        float inv = 1.f / s;
        #pragma unroll
        for (int n = 0; n < NSLOT; n++) wattn[h][n] *= inv;
    }
    if (tid == 8) {
        float sp[NSLOT];
        #pragma unroll
        for (int n = 0; n < NSLOT; n++) {
            float a = 0.f;
            #pragma unroll
            for (int h = 0; h < HEADS; h++) a += logits[h][n];
            sp[n] = a * SCALE_S;
        }
        bool sel[NSLOT];
        #pragma unroll
        for (int n = 0; n < NSLOT; n++) { sel[n] = false; wsp[n] = 0.f; }
        int idxs[TOPK];
        #pragma unroll
        for (int kk = 0; kk < TOPK; kk++) {
            int best = -1; float bv = -INFINITY;
            #pragma unroll
            for (int n = 0; n < NSLOT; n++)
                if (!sel[n] && sp[n] > bv) { bv = sp[n]; best = n; }
            sel[best] = true; idxs[kk] = best;
        }
        float m = -INFINITY;
        #pragma unroll
        for (int kk = 0; kk < TOPK; kk++) m = fmaxf(m, sp[idxs[kk]]);
        float s = 0.f, e[TOPK];
        #pragma unroll
        for (int kk = 0; kk < TOPK; kk++) { e[kk] = __expf(sp[idxs[kk]] - m); s += e[kk]; }
        float inv = 1.f / s;
        #pragma unroll
        for (int kk = 0; kk < TOPK; kk++) wsp[idxs[kk]] = e[kk] * inv;
    }
    __syncthreads();

    uint32_t* ph = (uint32_t*)(as_h + (size_t)t * DS);
    uint32_t* pl = (uint32_t*)(as_l + (size_t)t * DS);
    for (int j2 = tid; j2 < DS / 2; j2 += 256) {
        int j = 2 * j2;
        int h = j >> 7;
        float a0 = 0.f, a1 = 0.f, b0 = 0.f, b1 = 0.f;
        #pragma unroll
        for (int n = 0; n < NSLOT; n++) {
            float2 vv = *(const float2*)(vmat + (size_t)(t * NSLOT + n) * kvld + j);
            a0 += wattn[h][n] * vv.x;
            a1 += wattn[h][n] * vv.y;
            b0 += wsp[n] * vv.x;
            b1 += wsp[n] * vv.y;
        }
        uint32_t hh, ll;
        split2(a0, a1, hh, ll);
        ph[j2] = hh;
        pl[j2] = ll;
        *(float2*)(rsp + (size_t)t * DS + j) = make_float2(b0, b1);
    }
}

// ---------------- merged K/V pre-split convert ----------------
__global__ __launch_bounds__(256) void conv_kv(
    const float* __restrict__ kr, int kld,
    const float* __restrict__ vr, int vld,
    uint32_t* __restrict__ kh, uint32_t* __restrict__ kl,
    uint32_t* __restrict__ vh, uint32_t* __restrict__ vl)
{
    if (blockIdx.x < T_LEN) {
        int t = blockIdx.x, j = threadIdx.x;
        float2 v = *(const float2*)(kr + (size_t)t * kld + 2 * j);
        uint32_t h, l;
        split2(v.x, v.y, h, l);
        kh[(size_t)t * 256 + j] = h;
        kl[(size_t)t * 256 + j] = l;
    } else {
        int idx = (blockIdx.x - T_LEN) * 256 + threadIdx.x;
        int pp = idx & 511;
        int d = (idx >> 9) & 63;
        int h = idx >> 15;
        float v0 = vr[(size_t)(2 * pp) * vld + h * DHR + d];
        float v1 = vr[(size_t)(2 * pp + 1) * vld + h * DHR + d];
        uint32_t hh, ll;
        split2(v0, v1, hh, ll);
        vh[idx] = hh;
        vl[idx] = ll;
    }
}

// ---------------- causal r-attention: MMA flash, pre-split K/V --------------
__global__ __launch_bounds__(128) void r_attn_mma(
    const float* __restrict__ qr, int qld,
    const uint32_t* __restrict__ kh_g, const uint32_t* __restrict__ kl_g,
    const uint32_t* __restrict__ vh_g, const uint32_t* __restrict__ vl_g,
    __nv_bfloat16* __restrict__ ar_h, __nv_bfloat16* __restrict__ ar_l)
{
    __shared__ __align__(16) uint32_t skh[64 * 32], skl[64 * 32];
    __shared__ __align__(16) uint32_t svh[64 * 32], svl[64 * 32];

    int tt = (int)(gridDim.x - 1 - blockIdx.x);
    int h = blockIdx.y;
    int t0 = tt * 8;
    int hb = h * DHR;

    int tid = threadIdx.x;
    int w = tid >> 5, lane = tid & 31;
    int gid = lane >> 2, tig = lane & 3;

    uint32_t bkh = smem_u32(skh), bkl = smem_u32(skl);
    uint32_t bvh = smem_u32(svh), bvl = smem_u32(svl);

    int r0 = t0 * 8 + 16 * w + gid;
    int r8 = r0 + 8;
    uint32_t qh[4][4], ql[4][4];
    #pragma unroll
    for (int kc = 0; kc < 4; kc++) {
        float2 x0 = *(const float2*)(qr + (size_t)r0 * qld + hb + kc * 16 + 2 * tig);
        float2 x1 = *(const float2*)(qr + (size_t)r8 * qld + hb + kc * 16 + 2 * tig);
        float2 x2 = *(const float2*)(qr + (size_t)r0 * qld + hb + kc * 16 + 2 * tig + 8);
        float2 x3 = *(const float2*)(qr + (size_t)r8 * qld + hb + kc * 16 + 2 * tig + 8);
        split2(x0.x * SCALE_R, x0.y * SCALE_R, qh[kc][0], ql[kc][0]);
        split2(x1.x * SCALE_R, x1.y * SCALE_R, qh[kc][1], ql[kc][1]);
        split2(x2.x * SCALE_R, x2.y * SCALE_R, qh[kc][2], ql[kc][2]);
        split2(x3.x * SCALE_R, x3.y * SCALE_R, qh[kc][3], ql[kc][3]);
    }
    int tok0 = t0 + ((16 * w + gid) >> 3);
    int tok8 = t0 + ((16 * w + gid + 8) >> 3);

    float m0 = -INFINITY, m1 = -INFINITY, l0 = 0.f, l1 = 0.f;
    float acco[8][4];
    #pragma unroll
    for (int i = 0; i < 8; i++)
        #pragma unroll
        for (int j = 0; j < 4; j++) acco[i][j] = 0.f;

    int plast = t0 + 7;
    for (int p0 = 0; p0 <= plast; p0 += 64) {
        __syncthreads();
        int pp0 = p0 >> 1;
        #pragma unroll
        for (int it = 0; it < 4; it++) {
            int idx = tid + it * 128;
            int p = idx >> 3, g = idx & 7;
            uint32_t doff = (uint32_t)(p * 32 + ((g ^ (p & 7)) << 2)) * 4;
            size_t ksrc = (size_t)(p0 + p) * 256 + h * 32 + g * 4;
            cp16(bkh + doff, kh_g + ksrc);
            cp16(bkl + doff, kl_g + ksrc);
            size_t vsrc = (size_t)h * 32768 + (size_t)p * 512 + pp0 + g * 4;
            cp16(bvh + doff, vh_g + vsrc);
            cp16(bvl + doff, vl_g + vsrc);
        }
        asm volatile("cp.async.commit_group;" ::: "memory");
        asm volatile("cp.async.wait_group 0;" ::: "memory");
        __syncthreads();

        float s[8][4];
        #pragma unroll
        for (int i = 0; i < 8; i++)
            #pragma unroll
            for (int j = 0; j < 4; j++) s[i][j] = 0.f;

        #pragma unroll
        for (int nt = 0; nt < 8; nt++) {
            int n0 = nt * 8 + gid;
            int sw = n0 & 7;
            #pragma unroll
            for (int kc = 0; kc < 4; kc++) {
                uint32_t o0 = n0 * 32 + (((2 * kc) ^ sw) << 2) + tig;
                uint32_t o1 = n0 * 32 + (((2 * kc + 1) ^ sw) << 2) + tig;
                uint32_t bh0 = skh[o0], bh1 = skh[o1];
                uint32_t bl0 = skl[o0], bl1 = skl[o1];
                mma_bf16(s[nt], qh[kc], bh0, bh1);
                mma_bf16(s[nt], qh[kc], bl0, bl1);
                mma_bf16(s[nt], ql[kc], bh0, bh1);
            }
        }

        if (p0 + 64 > t0) {
            #pragma unroll
            for (int nt = 0; nt < 8; nt++) {
                int pg = p0 + nt * 8 + 2 * tig;
                if (pg > tok0)     s[nt][0] = -INFINITY;
                if (pg + 1 > tok0) s[nt][1] = -INFINITY;
                if (pg > tok8)     s[nt][2] = -INFINITY;
                if (pg + 1 > tok8) s[nt][3] = -INFINITY;
            }
        }

        float mx0 = -INFINITY, mx1 = -INFINITY;
        #pragma unroll
        for (int nt = 0; nt < 8; nt++) {
            mx0 = fmaxf(mx0, fmaxf(s[nt][0], s[nt][1]));
            mx1 = fmaxf(mx1, fmaxf(s[nt][2], s[nt][3]));
        }
        mx0 = fmaxf(mx0, __shfl_xor_sync(0xffffffffu, mx0, 1));
        mx0 = fmaxf(mx0, __shfl_xor_sync(0xffffffffu, mx0, 2));
        mx1 = fmaxf(mx1, __shfl_xor_sync(0xffffffffu, mx1, 1));
        mx1 = fmaxf(mx1, __shfl_xor_sync(0xffffffffu, mx1, 2));
        float nm0 = fmaxf(m0, mx0), nm1 = fmaxf(m1, mx1);
        float cr0 = __expf(m0 - nm0), cr1 = __expf(m1 - nm1);
        m0 = nm0; m1 = nm1;

        float rs0 = 0.f, rs1 = 0.f;
        #pragma unroll
        for (int nt = 0; nt < 8; nt++) {
            s[nt][0] = __expf(s[nt][0] - nm0);
            s[nt][1] = __expf(s[nt][1] - nm0);
            s[nt][2] = __expf(s[nt][2] - nm1);
            s[nt][3] = __expf(s[nt][3] - nm1);
            rs0 += s[nt][0] + s[nt][1];
            rs1 += s[nt][2] + s[nt][3];
        }
        rs0 += __shfl_xor_sync(0xffffffffu, rs0, 1);
        rs0 += __shfl_xor_sync(0xffffffffu, rs0, 2);
        rs1 += __shfl_xor_sync(0xffffffffu, rs1, 1);
        rs1 += __shfl_xor_sync(0xffffffffu, rs1, 2);
        l0 = l0 * cr0 + rs0;
        l1 = l1 * cr1 + rs1;

        #pragma unroll
        for (int ntd = 0; ntd < 8; ntd++) {
            acco[ntd][0] *= cr0; acco[ntd][1] *= cr0;
            acco[ntd][2] *= cr1; acco[ntd][3] *= cr1;
        }

        #pragma unroll
        for (int kc = 0; kc < 4; kc++) {
            uint32_t pah[4], pal[4];
            split2(s[2 * kc][0],     s[2 * kc][1],     pah[0], pal[0]);
            split2(s[2 * kc][2],     s[2 * kc][3],     pah[1], pal[1]);
            split2(s[2 * kc + 1][0], s[2 * kc + 1][1], pah[2], pal[2]);
            split2(s[2 * kc + 1][2], s[2 * kc + 1][3], pah[3], pal[3]);
            #pragma unroll
            for (int ntd = 0; ntd < 8; ntd++) {
                int d0 = ntd * 8 + gid;
                int sw = d0 & 7;
                uint32_t o0 = d0 * 32 + (((2 * kc) ^ sw) << 2) + tig;
                uint32_t o1 = d0 * 32 + (((2 * kc + 1) ^ sw) << 2) + tig;
                uint32_t bh0 = svh[o0], bh1 = svh[o1];
                uint32_t bl0 = svl[o0], bl1 = svl[o1];
                mma_bf16(acco[ntd], pah, bh0, bh1);
                mma_bf16(acco[ntd], pah, bl0, bl1);
                mma_bf16(acco[ntd], pal, bh0, bh1);
            }
        }
    }

    float i0 = 1.f / l0, i1 = 1.f / l1;
    #pragma unroll
    for (int ntd = 0; ntd < 8; ntd++) {
        int col = hb + ntd * 8 + 2 * tig;
        uint32_t hh, ll;
        split2(acco[ntd][0] * i0, acco[ntd][1] * i0, hh, ll);
        *(uint32_t*)(ar_h + (size_t)r0 * DR + col) = hh;
        *(uint32_t*)(ar_l + (size_t)r0 * DR + col) = ll;
        split2(acco[ntd][2] * i1, acco[ntd][3] * i1, hh, ll);
        *(uint32_t*)(ar_h + (size_t)r8 * DR + col) = hh;
        *(uint32_t*)(ar_l + (size_t)r8 * DR + col) = ll;
    }
}

// ---------------- host launch ----------------
extern "C" void kernel_launch(void* const* d_in, const int* in_sizes, int n_in,
                              void* d_out, int out_size)
{
    const float* s      = (const float*)d_in[0];
    const float* r      = (const float*)d_in[1];
    const float* gate_v = (const float*)d_in[2];
    const float* nsw    = (const float*)d_in[3];
    const float* nrw    = (const float*)d_in[4];
    const float* Wsq    = (const float*)d_in[5];
    const float* Wsk    = (const float*)d_in[6];
    const float* Wsv    = (const float*)d_in[7];
    const float* Wso    = (const float*)d_in[8];
    const float* Wrq    = (const float*)d_in[9];
    const float* Wrk    = (const float*)d_in[10];
    const float* Wrv    = (const float*)d_in[11];
    const float* Wro    = (const float*)d_in[12];

    float* out_s = (float*)d_out;
    float* out_r = (float*)d_out + T_LEN * DS;

    __nv_bfloat16 *snh, *snl, *rnh, *rnl, *ash, *asl, *arh, *arl;
    __nv_bfloat16 *wsnh, *wsnl, *wrnh, *wrnl, *wsoh, *wsol, *wroh, *wrol;
    float *csn, *crn, *rsp;
    uint32_t *kh, *kl, *vth, *vtl;
    cudaGetSymbolAddress((void**)&snh, g_sn_h);
    cudaGetSymbolAddress((void**)&snl, g_sn_l);
    cudaGetSymbolAddress((void**)&rnh, g_rn_h);
    cudaGetSymbolAddress((void**)&rnl, g_rn_l);
    cudaGetSymbolAddress((void**)&ash, g_as_h);
    cudaGetSymbolAddress((void**)&asl, g_as_l);
    cudaGetSymbolAddress((void**)&arh, g_ar_h);
    cudaGetSymbolAddress((void**)&arl, g_ar_l);
    cudaGetSymbolAddress((void**)&wsnh, g_wsn_h);
    cudaGetSymbolAddress((void**)&wsnl, g_wsn_l);
    cudaGetSymbolAddress((void**)&wrnh, g_wrn_h);
    cudaGetSymbolAddress((void**)&wrnl, g_wrn_l);
    cudaGetSymbolAddress((void**)&wsoh, g_wso_h);
    cudaGetSymbolAddress((void**)&wsol, g_wso_l);
    cudaGetSymbolAddress((void**)&wroh, g_wro_h);
    cudaGetSymbolAddress((void**)&wrol, g_wro_l);
    cudaGetSymbolAddress((void**)&csn, g_csn);
    cudaGetSymbolAddress((void**)&crn, g_crn);
    cudaGetSymbolAddress((void**)&rsp, g_rsp);
    cudaGetSymbolAddress((void**)&kh, g_kh);
    cudaGetSymbolAddress((void**)&kl, g_kl);
    cudaGetSymbolAddress((void**)&vth, g_vth);
    cudaGetSymbolAddress((void**)&vtl, g_vtl);

    // ---- all weight transposes in ONE launch ----
    wtrans_all<<<4608, 256>>>(Wsq, Wsk, Wsv, Wso, Wrq, Wrk, Wrv, Wro,
                              wsnh, wsnl, wrnh, wrnl, wsoh, wsol, wroh, wrol);

    // ---- rmsnorm ----
    rmsnorm_split<<<T_LEN, 256>>>(s, nsw, snh, snl, DS);
    rmsnorm_split<<<ROWS_R, 256>>>(r, nrw, rnh, rnl, DR);

    // ---- fused projection GEMMs (64-row tiles) ----
    mma_gemm_bf<<<dim3(N_SN / 128, T_LEN / 64), 256>>>(
        snh, snl, wsnh, wsnl, csn, T_LEN, N_SN, DS, N_SN,
        nullptr, nullptr, nullptr);
    mma_gemm_bf<<<dim3(N_RN / 128, ROWS_R / 64), 256>>>(
        rnh, rnl, wrnh, wrnl, crn, ROWS_R, N_RN, DR, N_RN,
        nullptr, nullptr, nullptr);

    // ---- pre-split K/V for r-attention (single launch) ----
    conv_kv<<<T_LEN + 1024, 256>>>(csn + 1024, N_SN, csn + 1536, N_SN,
                                   kh, kl, vth, vtl);

    // ---- s-attention + sparse top-k ----
    s_attn_kernel<<<T_LEN, 256>>>(csn, crn, crn + 1024, N_SN, N_RN,
                                  ash, asl, rsp);

    // ---- causal r attention ----
    r_attn_mma<<<dim3(T_LEN / 8, HEADS), 128>>>(crn + 2048, N_RN,
                                                kh, kl, vth, vtl, arh, arl);

    // ---- outputs ----
    mma_gemm_bf<<<dim3(DS / 128, T_LEN / 64), 256>>>(
        ash, asl, wsoh, wsol, out_s, T_LEN, DS, DS, DS,
        s, rsp, gate_v);
    mma_gemm_bf<<<dim3(DR / 128, ROWS_R / 64), 256>>>(
        arh, arl, wroh, wrol, out_r, ROWS_R, DR, DR, DR,
        r, nullptr, nullptr);
}

// round 10
// speedup vs baseline: 4.7385x; 1.0488x over previous
#include <cuda_runtime.h>
#include <cuda_bf16.h>
#include <math.h>
#include <stdint.h>

// ---------------- problem constants ----------------
#define T_LEN 1024
#define NSLOT 8
#define DS 1024
#define DR 512
#define HEADS 8
#define DHS 128
#define DHR 64
#define TOPK 4
#define ROWS_R (T_LEN * NSLOT)   // 8192
#define SCALE_S 0.08838834764831845f  // 1/sqrt(128)
#define SCALE_R 0.125f                // 1/sqrt(64)
#define EPS 1e-6f

// fused layouts
#define N_SN 2048        // q(1024) | kr(512) | vr(512), K=1024
#define N_RN 2560        // k(1024) | v(1024) | qr(512), K=512

// ---------------- scratch (static device memory; no allocation) -------------
__device__ __nv_bfloat16 g_sn_h[T_LEN * DS], g_sn_l[T_LEN * DS];
__device__ __nv_bfloat16 g_rn_h[ROWS_R * DR], g_rn_l[ROWS_R * DR];
__device__ __nv_bfloat16 g_as_h[T_LEN * DS], g_as_l[T_LEN * DS];
__device__ __nv_bfloat16 g_ar_h[ROWS_R * DR], g_ar_l[ROWS_R * DR];
__device__ __nv_bfloat16 g_wsn_h[N_SN * DS], g_wsn_l[N_SN * DS];
__device__ __nv_bfloat16 g_wrn_h[N_RN * DR], g_wrn_l[N_RN * DR];
__device__ __nv_bfloat16 g_wso_h[DS * DS], g_wso_l[DS * DS];
__device__ __nv_bfloat16 g_wro_h[DR * DR], g_wro_l[DR * DR];
__device__ float g_csn[T_LEN * N_SN];     // q | kr | vr
__device__ float g_crn[ROWS_R * N_RN];    // k | v | qr
__device__ float g_rsp[T_LEN * DS];
__device__ uint32_t g_kh[T_LEN * 256], g_kl[T_LEN * 256];
__device__ uint32_t g_vth[HEADS * DHR * (T_LEN / 2)];
__device__ uint32_t g_vtl[HEADS * DHR * (T_LEN / 2)];

// ---------------- PTX helpers ----------------
__device__ __forceinline__ uint32_t smem_u32(const void* p) {
    uint32_t a;
    asm("{ .reg .u64 t; cvta.to.shared.u64 t, %1; cvt.u32.u64 %0, t; }"
        : "=r"(a) : "l"(p));
    return a;
}
__device__ __forceinline__ void cp16(uint32_t dst, const void* src) {
    asm volatile("cp.async.cg.shared.global [%0], [%1], 16;"
                 :: "r"(dst), "l"(src) : "memory");
}
__device__ __forceinline__ void ldm_x4(uint32_t* r, uint32_t addr) {
    asm volatile("ldmatrix.sync.aligned.m8n8.x4.shared.b16 {%0,%1,%2,%3}, [%4];"
                 : "=r"(r[0]), "=r"(r[1]), "=r"(r[2]), "=r"(r[3]) : "r"(addr));
}
__device__ __forceinline__ void mma_bf16(
    float* c, const uint32_t* a, uint32_t b0, uint32_t b1)
{
    asm volatile(
        "mma.sync.aligned.m16n8k16.row.col.f32.bf16.bf16.f32 "
        "{%0,%1,%2,%3}, {%4,%5,%6,%7}, {%8,%9}, {%0,%1,%2,%3};"
        : "+f"(c[0]), "+f"(c[1]), "+f"(c[2]), "+f"(c[3])
        : "r"(a[0]), "r"(a[1]), "r"(a[2]), "r"(a[3]), "r"(b0), "r"(b1));
}
__device__ __forceinline__ void split2(float x, float y,
                                       uint32_t& hi, uint32_t& lo)
{
    __nv_bfloat162 h = __floats2bfloat162_rn(x, y);
    float xr = x - __bfloat162float(h.x);
    float yr = y - __bfloat162float(h.y);
    __nv_bfloat162 l = __floats2bfloat162_rn(xr, yr);
    hi = *(uint32_t*)&h;
    lo = *(uint32_t*)&l;
}

// ---------------- merged prep: 8 weight transposes + 2 rmsnorms -------------
__global__ __launch_bounds__(256) void prep_kernel(
    const float* __restrict__ Wsq, const float* __restrict__ Wsk,
    const float* __restrict__ Wsv, const float* __restrict__ Wso,
    const float* __restrict__ Wrq, const float* __restrict__ Wrk,
    const float* __restrict__ Wrv, const float* __restrict__ Wro,
    __nv_bfloat16* __restrict__ wsnh, __nv_bfloat16* __restrict__ wsnl,
    __nv_bfloat16* __restrict__ wrnh, __nv_bfloat16* __restrict__ wrnl,
    __nv_bfloat16* __restrict__ wsoh, __nv_bfloat16* __restrict__ wsol,
    __nv_bfloat16* __restrict__ wroh, __nv_bfloat16* __restrict__ wrol,
    const float* __restrict__ s, const float* __restrict__ nsw,
    __nv_bfloat16* __restrict__ snh, __nv_bfloat16* __restrict__ snl,
    const float* __restrict__ r, const float* __restrict__ nrw,
    __nv_bfloat16* __restrict__ rnh, __nv_bfloat16* __restrict__ rnl)
{
    int b = blockIdx.x;
    if (b < 4608) {
        // ---- weight transpose segment ----
        const float* W;
        __nv_bfloat16 *th, *tl;
        int K, N;
        if (b < 1024)      { W = Wsq; th = wsnh; tl = wsnl; K = 1024; N = 1024; }
        else if (b < 1536) { b -= 1024; W = Wrk; th = wsnh + 1024 * 1024;
                             tl = wsnl + 1024 * 1024; K = 1024; N = 512; }
        else if (b < 2048) { b -= 1536; W = Wrv; th = wsnh + 1536 * 1024;
                             tl = wsnl + 1536 * 1024; K = 1024; N = 512; }
        else if (b < 2560) { b -= 2048; W = Wsk; th = wrnh; tl = wrnl;
                             K = 512; N = 1024; }
        else if (b < 3072) { b -= 2560; W = Wsv; th = wrnh + 1024 * 512;
                             tl = wrnl + 1024 * 512; K = 512; N = 1024; }
        else if (b < 3328) { b -= 3072; W = Wrq; th = wrnh + 2048 * 512;
                             tl = wrnl + 2048 * 512; K = 512; N = 512; }
        else if (b < 4352) { b -= 3328; W = Wso; th = wsoh; tl = wsol;
                             K = 1024; N = 1024; }
        else               { b -= 4352; W = Wro; th = wroh; tl = wrol;
                             K = 512; N = 512; }

        int ntx = N >> 5;
        int bx = (b % ntx) * 32;
        int by = (b / ntx) * 32;

        __shared__ float t[32][33];
        int tx = threadIdx.x & 31, ty = threadIdx.x >> 5;
        #pragma unroll
        for (int i = 0; i < 4; i++)
            t[ty + i * 8][tx] = W[(size_t)(by + ty + i * 8) * N + bx + tx];
        __syncthreads();
        #pragma unroll
        for (int i = 0; i < 4; i++) {
            int n = bx + ty + i * 8;
            int k = by + tx;
            float v = t[tx][ty + i * 8];
            __nv_bfloat16 h = __float2bfloat16(v);
            th[(size_t)n * K + k] = h;
            tl[(size_t)n * K + k] = __float2bfloat16(v - __bfloat162float(h));
        }
        return;
    }
    // ---- rmsnorm segment ----
    const float *x, *w;
    __nv_bfloat16 *oh, *ol;
    int C, row;
    if (b < 4608 + T_LEN) {
        row = b - 4608; x = s; w = nsw; oh = snh; ol = snl; C = DS;
    } else {
        row = b - 4608 - T_LEN; x = r; w = nrw; oh = rnh; ol = rnl; C = DR;
    }
    const float* xr = x + (size_t)row * C;
    float acc = 0.f;
    for (int j = threadIdx.x; j < C; j += 256) {
        float v = xr[j];
        acc += v * v;
    }
    __shared__ float red[8];
    int lane = threadIdx.x & 31, warp = threadIdx.x >> 5;
    #pragma unroll
    for (int off = 16; off; off >>= 1) acc += __shfl_xor_sync(0xffffffffu, acc, off);
    if (lane == 0) red[warp] = acc;
    __syncthreads();
    __shared__ float scale;
    if (threadIdx.x == 0) {
        float tot = 0.f;
        #pragma unroll
        for (int i = 0; i < 8; i++) tot += red[i];
        scale = rsqrtf(tot / (float)C + EPS);
    }
    __syncthreads();
    float sc = scale;
    uint32_t* ph = (uint32_t*)(oh + (size_t)row * C);
    uint32_t* pl = (uint32_t*)(ol + (size_t)row * C);
    for (int j2 = threadIdx.x; j2 < C / 2; j2 += 256) {
        float v0 = xr[2 * j2] * sc * w[2 * j2];
        float v1 = xr[2 * j2 + 1] * sc * w[2 * j2 + 1];
        uint32_t h, l;
        split2(v0, v1, h, l);
        ph[j2] = h;
        pl[j2] = l;
    }
}

// ---------------- bf16-split mma GEMM body (64x128 tile) --------------------
struct GArg {
    const __nv_bfloat16 *Ah, *Al, *Bh, *Bl;
    float* C;
    int M, N, K, ldc;
    const float *add1, *add2, *rowscale;
};

__device__ __forceinline__ void gemm_body(
    const GArg g, int bx, int by,
    uint32_t bAh, uint32_t bAl, uint32_t bBh, uint32_t bBl)
{
    int tid = threadIdx.x;
    int lane = tid & 31, wid = tid >> 5;
    int wm = wid & 1, wn = wid >> 1;          // 2 x 4 warp grid
    int bm = by * 64, bn = bx * 128;
    int gid = lane >> 2, tig = lane & 3;
    int K = g.K;

    float acc[2][4][4];
    #pragma unroll
    for (int i = 0; i < 2; i++)
        #pragma unroll
        for (int j = 0; j < 4; j++)
            #pragma unroll
            for (int l = 0; l < 4; l++) acc[i][j][l] = 0.f;

    uint32_t aoff0, aoff1, boff0, boff1;
    {
        int lrow = lane & 7;
        int rA = wm * 32 + lrow + (lane & 8);
        int cA = (lane & 16) >> 2;
        aoff0 = (uint32_t)(rA * 8 + cA) * 4;
        aoff1 = (uint32_t)((rA + 16) * 8 + cA) * 4;
        int rB = wn * 32 + lrow + ((lane & 16) >> 1);
        int cB = (lane & 8) >> 1;
        boff0 = (uint32_t)(rB * 8 + cB) * 4;
        boff1 = (uint32_t)((rB + 16) * 8 + cB) * 4;
    }

    int row = tid >> 1;
    int gg = tid & 1;
    const __nv_bfloat16 *Ah = g.Ah, *Al = g.Al, *Bh = g.Bh, *Bl = g.Bl;
    auto issue = [&](int st, int k0) {
        uint32_t bdoff = (uint32_t)(st * 128 * 8 + row * 8 + gg * 4) * 4;
        size_t bsrc = (size_t)(bn + row) * K + k0 + gg * 8;
        cp16(bBh + bdoff, Bh + bsrc);
        cp16(bBl + bdoff, Bl + bsrc);
        if (tid < 128) {
            uint32_t adoff = (uint32_t)(st * 64 * 8 + row * 8 + gg * 4) * 4;
            size_t asrc = (size_t)(bm + row) * K + k0 + gg * 8;
            cp16(bAh + adoff, Ah + asrc);
            cp16(bAl + adoff, Al + asrc);
        }
        asm volatile("cp.async.commit_group;" ::: "memory");
    };

    int nch = K >> 4;
    issue(0, 0);
    if (nch > 1) issue(1, 16);

    for (int c = 0; c < nch; c++) {
        if (c + 1 < nch) {
            asm volatile("cp.async.wait_group 1;" ::: "memory");
        } else {
            asm volatile("cp.async.wait_group 0;" ::: "memory");
        }
        __syncthreads();
        if (c + 2 < nch) issue((c + 2) % 3, (c + 2) * 16);

        uint32_t aoffst = (uint32_t)((c % 3) * 64 * 8 * 4);
        uint32_t boffst = (uint32_t)((c % 3) * 128 * 8 * 4);

        uint32_t ah[2][4], al[2][4];
        ldm_x4(ah[0], bAh + aoffst + aoff0);
        ldm_x4(ah[1], bAh + aoffst + aoff1);
        ldm_x4(al[0], bAl + aoffst + aoff0);
        ldm_x4(al[1], bAl + aoffst + aoff1);

        #pragma unroll
        for (int p = 0; p < 2; p++) {
            uint32_t bh[4], bl[4];
            ldm_x4(bh, bBh + boffst + (p ? boff1 : boff0));
            ldm_x4(bl, bBl + boffst + (p ? boff1 : boff0));
            #pragma unroll
            for (int q = 0; q < 2; q++) {
                int nt = p * 2 + q;
                uint32_t b0h = bh[2 * q], b1h = bh[2 * q + 1];
                uint32_t b0l = bl[2 * q], b1l = bl[2 * q + 1];
                mma_bf16(acc[0][nt], ah[0], b0h, b1h);
                mma_bf16(acc[0][nt], ah[0], b0l, b1l);
                mma_bf16(acc[0][nt], al[0], b0h, b1h);
                mma_bf16(acc[1][nt], ah[1], b0h, b1h);
                mma_bf16(acc[1][nt], ah[1], b0l, b1l);
                mma_bf16(acc[1][nt], al[1], b0h, b1h);
            }
        }
    }

    #pragma unroll
    for (int mt = 0; mt < 2; mt++) {
        int r0 = bm + wm * 32 + mt * 16 + gid;
        float rs0 = (g.rowscale != nullptr) ? g.rowscale[r0] : 0.f;
        float rs8 = (g.rowscale != nullptr) ? g.rowscale[r0 + 8] : 0.f;
        #pragma unroll
        for (int nt = 0; nt < 4; nt++) {
            int col = bn + wn * 32 + nt * 8 + 2 * tig;
            size_t o0 = (size_t)r0 * g.ldc + col;
            size_t o8 = (size_t)(r0 + 8) * g.ldc + col;
            float2 v0 = make_float2(acc[mt][nt][0], acc[mt][nt][1]);
            float2 v8 = make_float2(acc[mt][nt][2], acc[mt][nt][3]);
            if (g.add1) {
                float2 x = *(const float2*)(g.add1 + o0);
                v0.x += x.x; v0.y += x.y;
                x = *(const float2*)(g.add1 + o8);
                v8.x += x.x; v8.y += x.y;
            }
            if (g.add2) {
                float2 x = *(const float2*)(g.add2 + o0);
                v0.x += rs0 * x.x; v0.y += rs0 * x.y;
                x = *(const float2*)(g.add2 + o8);
                v8.x += rs8 * x.x; v8.y += rs8 * x.y;
            }
            *(float2*)(g.C + o0) = v0;
            *(float2*)(g.C + o8) = v8;
        }
    }
}

// merged pair-of-GEMMs launch; 3 CTAs/SM target
__global__ __launch_bounds__(256, 3) void gemm_pair(
    GArg g0, GArg g1, int nblk0, int gx0, int gx1)
{
    __shared__ __align__(16) uint32_t sAh[3][64 * 8], sAl[3][64 * 8];
    __shared__ __align__(16) uint32_t sBh[3][128 * 8], sBl[3][128 * 8];
    uint32_t bAh = smem_u32(sAh), bAl = smem_u32(sAl);
    uint32_t bBh = smem_u32(sBh), bBl = smem_u32(sBl);

    int b = blockIdx.x;
    if (b < nblk0)
        gemm_body(g0, b % gx0, b / gx0, bAh, bAl, bBh, bBl);
    else {
        b -= nblk0;
        gemm_body(g1, b % gx1, b / gx1, bAh, bAl, bBh, bBl);
    }
}

// ---------------- merged conv_kv + s-attention ----------------
__global__ __launch_bounds__(256) void conv_sattn_kernel(
    const float* __restrict__ csn,   // (T, N_SN): q | kr | vr
    const float* __restrict__ crn,   // (T*N, N_RN): k | v | qr
    uint32_t* __restrict__ kh, uint32_t* __restrict__ kl,
    uint32_t* __restrict__ vh, uint32_t* __restrict__ vl,
    __nv_bfloat16* __restrict__ as_h, __nv_bfloat16* __restrict__ as_l,
    float* __restrict__ rsp)
{
    int b = blockIdx.x;
    if (b < T_LEN) {
        // conv_k from csn cols [1024,1536)
        int t = b, j = threadIdx.x;
        float2 v = *(const float2*)(csn + (size_t)t * N_SN + 1024 + 2 * j);
        uint32_t h, l;
        split2(v.x, v.y, h, l);
        kh[(size_t)t * 256 + j] = h;
        kl[(size_t)t * 256 + j] = l;
        return;
    }
    if (b < T_LEN + 1024) {
        // conv_vt from csn cols [1536,2048)
        int idx = (b - T_LEN) * 256 + threadIdx.x;
        int pp = idx & 511;
        int d = (idx >> 9) & 63;
        int h = idx >> 15;
        float v0 = csn[(size_t)(2 * pp) * N_SN + 1536 + h * DHR + d];
        float v1 = csn[(size_t)(2 * pp + 1) * N_SN + 1536 + h * DHR + d];
        uint32_t hh, ll;
        split2(v0, v1, hh, ll);
        vh[idx] = hh;
        vl[idx] = ll;
        return;
    }
    // ---- s-attention segment ----
    int t = b - T_LEN - 1024;
    int tid = threadIdx.x;
    int warp = tid >> 5, lane = tid & 31;

    __shared__ float qs[DS];
    __shared__ float logits[HEADS][NSLOT];
    __shared__ float wattn[HEADS][NSLOT];
    __shared__ float wsp[NSLOT];

    for (int j = tid; j < DS; j += 256) qs[j] = csn[(size_t)t * N_SN + j];
    __syncthreads();

    {
        int h = warp;
        #pragma unroll
        for (int n = 0; n < NSLOT; n++) {
            const float* krow = crn + (size_t)(t * NSLOT + n) * N_RN + h * DHS;
            const float* qrow = qs + h * DHS;
            float p = 0.f;
            #pragma unroll
            for (int d = lane; d < DHS; d += 32) p += qrow[d] * krow[d];
            #pragma unroll
            for (int off = 16; off; off >>= 1) p += __shfl_xor_sync(0xffffffffu, p, off);
            if (lane == 0) logits[h][n] = p;
        }
    }
    __syncthreads();

    if (tid < HEADS) {
        int h = tid;
        float m = -INFINITY;
        #pragma unroll
        for (int n = 0; n < NSLOT; n++) m = fmaxf(m, logits[h][n] * SCALE_S);
        float sum = 0.f;
        #pragma unroll
        for (int n = 0; n < NSLOT; n++) {
            float e = __expf(logits[h][n] * SCALE_S - m);
            wattn[h][n] = e;
            sum += e;
        }
        float inv = 1.f / sum;
        #pragma unroll
        for (int n = 0; n < NSLOT; n++) wattn[h][n] *= inv;
    }
    if (tid == 8) {
        float sp[NSLOT];
        #pragma unroll
        for (int n = 0; n < NSLOT; n++) {
            float a = 0.f;
            #pragma unroll
            for (int h = 0; h < HEADS; h++) a += logits[h][n];
            sp[n] = a * SCALE_S;
        }
        bool sel[NSLOT];
        #pragma unroll
        for (int n = 0; n < NSLOT; n++) { sel[n] = false; wsp[n] = 0.f; }
        int idxs[TOPK];
        #pragma unroll
        for (int kk = 0; kk < TOPK; kk++) {
            int best = -1; float bv = -INFINITY;
            #pragma unroll
            for (int n = 0; n < NSLOT; n++)
                if (!sel[n] && sp[n] > bv) { bv = sp[n]; best = n; }
            sel[best] = true; idxs[kk] = best;
        }
        float m = -INFINITY;
        #pragma unroll
        for (int kk = 0; kk < TOPK; kk++) m = fmaxf(m, sp[idxs[kk]]);
        float sum = 0.f, e[TOPK];
        #pragma unroll
        for (int kk = 0; kk < TOPK; kk++) { e[kk] = __expf(sp[idxs[kk]] - m); sum += e[kk]; }
        float inv = 1.f / sum;
        #pragma unroll
        for (int kk = 0; kk < TOPK; kk++) wsp[idxs[kk]] = e[kk] * inv;
    }
    __syncthreads();

    uint32_t* ph = (uint32_t*)(as_h + (size_t)t * DS);
    uint32_t* pl = (uint32_t*)(as_l + (size_t)t * DS);
    for (int j2 = tid; j2 < DS / 2; j2 += 256) {
        int j = 2 * j2;
        int h = j >> 7;
        float a0 = 0.f, a1 = 0.f, b0 = 0.f, b1 = 0.f;
        #pragma unroll
        for (int n = 0; n < NSLOT; n++) {
            float2 vv = *(const float2*)(crn + (size_t)(t * NSLOT + n) * N_RN + 1024 + j);
            a0 += wattn[h][n] * vv.x;
            a1 += wattn[h][n] * vv.y;
            b0 += wsp[n] * vv.x;
            b1 += wsp[n] * vv.y;
        }
        uint32_t hh, ll;
        split2(a0, a1, hh, ll);
        ph[j2] = hh;
        pl[j2] = ll;
        *(float2*)(rsp + (size_t)t * DS + j) = make_float2(b0, b1);
    }
}

// ---------------- causal r-attention: MMA flash, pre-split K/V --------------
__global__ __launch_bounds__(128) void r_attn_mma(
    const float* __restrict__ qr, int qld,
    const uint32_t* __restrict__ kh_g, const uint32_t* __restrict__ kl_g,
    const uint32_t* __restrict__ vh_g, const uint32_t* __restrict__ vl_g,
    __nv_bfloat16* __restrict__ ar_h, __nv_bfloat16* __restrict__ ar_l)
{
    __shared__ __align__(16) uint32_t skh[64 * 32], skl[64 * 32];
    __shared__ __align__(16) uint32_t svh[64 * 32], svl[64 * 32];

    int tt = (int)(gridDim.x - 1 - blockIdx.x);
    int h = blockIdx.y;
    int t0 = tt * 8;
    int hb = h * DHR;

    int tid = threadIdx.x;
    int w = tid >> 5, lane = tid & 31;
    int gid = lane >> 2, tig = lane & 3;

    uint32_t bkh = smem_u32(skh), bkl = smem_u32(skl);
    uint32_t bvh = smem_u32(svh), bvl = smem_u32(svl);

    int r0 = t0 * 8 + 16 * w + gid;
    int r8 = r0 + 8;
    uint32_t qh[4][4], ql[4][4];
    #pragma unroll
    for (int kc = 0; kc < 4; kc++) {
        float2 x0 = *(const float2*)(qr + (size_t)r0 * qld + hb + kc * 16 + 2 * tig);
        float2 x1 = *(const float2*)(qr + (size_t)r8 * qld + hb + kc * 16 + 2 * tig);
        float2 x2 = *(const float2*)(qr + (size_t)r0 * qld + hb + kc * 16 + 2 * tig + 8);
        float2 x3 = *(const float2*)(qr + (size_t)r8 * qld + hb + kc * 16 + 2 * tig + 8);
        split2(x0.x * SCALE_R, x0.y * SCALE_R, qh[kc][0], ql[kc][0]);
        split2(x1.x * SCALE_R, x1.y * SCALE_R, qh[kc][1], ql[kc][1]);
        split2(x2.x * SCALE_R, x2.y * SCALE_R, qh[kc][2], ql[kc][2]);
        split2(x3.x * SCALE_R, x3.y * SCALE_R, qh[kc][3], ql[kc][3]);
    }
    int tok0 = t0 + ((16 * w + gid) >> 3);
    int tok8 = t0 + ((16 * w + gid + 8) >> 3);

    float m0 = -INFINITY, m1 = -INFINITY, l0 = 0.f, l1 = 0.f;
    float acco[8][4];
    #pragma unroll
    for (int i = 0; i < 8; i++)
        #pragma unroll
        for (int j = 0; j < 4; j++) acco[i][j] = 0.f;

    int plast = t0 + 7;
    for (int p0 = 0; p0 <= plast; p0 += 64) {
        __syncthreads();
        int pp0 = p0 >> 1;
        #pragma unroll
        for (int it = 0; it < 4; it++) {
            int idx = tid + it * 128;
            int p = idx >> 3, g = idx & 7;
            uint32_t doff = (uint32_t)(p * 32 + ((g ^ (p & 7)) << 2)) * 4;
            size_t ksrc = (size_t)(p0 + p) * 256 + h * 32 + g * 4;
            cp16(bkh + doff, kh_g + ksrc);
            cp16(bkl + doff, kl_g + ksrc);
            size_t vsrc = (size_t)h * 32768 + (size_t)p * 512 + pp0 + g * 4;
            cp16(bvh + doff, vh_g + vsrc);
            cp16(bvl + doff, vl_g + vsrc);
        }
        asm volatile("cp.async.commit_group;" ::: "memory");
        asm volatile("cp.async.wait_group 0;" ::: "memory");
        __syncthreads();

        float s[8][4];
        #pragma unroll
        for (int i = 0; i < 8; i++)
            #pragma unroll
            for (int j = 0; j < 4; j++) s[i][j] = 0.f;

        #pragma unroll
        for (int nt = 0; nt < 8; nt++) {
            int n0 = nt * 8 + gid;
            int sw = n0 & 7;
            #pragma unroll
            for (int kc = 0; kc < 4; kc++) {
                uint32_t o0 = n0 * 32 + (((2 * kc) ^ sw) << 2) + tig;
                uint32_t o1 = n0 * 32 + (((2 * kc + 1) ^ sw) << 2) + tig;
                uint32_t bh0 = skh[o0], bh1 = skh[o1];
                uint32_t bl0 = skl[o0], bl1 = skl[o1];
                mma_bf16(s[nt], qh[kc], bh0, bh1);
                mma_bf16(s[nt], qh[kc], bl0, bl1);
                mma_bf16(s[nt], ql[kc], bh0, bh1);
            }
        }

        if (p0 + 64 > t0) {
            #pragma unroll
            for (int nt = 0; nt < 8; nt++) {
                int pg = p0 + nt * 8 + 2 * tig;
                if (pg > tok0)     s[nt][0] = -INFINITY;
                if (pg + 1 > tok0) s[nt][1] = -INFINITY;
                if (pg > tok8)     s[nt][2] = -INFINITY;
                if (pg + 1 > tok8) s[nt][3] = -INFINITY;
            }
        }

        float mx0 = -INFINITY, mx1 = -INFINITY;
        #pragma unroll
        for (int nt = 0; nt < 8; nt++) {
            mx0 = fmaxf(mx0, fmaxf(s[nt][0], s[nt][1]));
            mx1 = fmaxf(mx1, fmaxf(s[nt][2], s[nt][3]));
        }
        mx0 = fmaxf(mx0, __shfl_xor_sync(0xffffffffu, mx0, 1));
        mx0 = fmaxf(mx0, __shfl_xor_sync(0xffffffffu, mx0, 2));
        mx1 = fmaxf(mx1, __shfl_xor_sync(0xffffffffu, mx1, 1));
        mx1 = fmaxf(mx1, __shfl_xor_sync(0xffffffffu, mx1, 2));
        float nm0 = fmaxf(m0, mx0), nm1 = fmaxf(m1, mx1);
        float cr0 = __expf(m0 - nm0), cr1 = __expf(m1 - nm1);
        m0 = nm0; m1 = nm1;

        float rs0 = 0.f, rs1 = 0.f;
        #pragma unroll
        for (int nt = 0; nt < 8; nt++) {
            s[nt][0] = __expf(s[nt][0] - nm0);
            s[nt][1] = __expf(s[nt][1] - nm0);
            s[nt][2] = __expf(s[nt][2] - nm1);
            s[nt][3] = __expf(s[nt][3] - nm1);
            rs0 += s[nt][0] + s[nt][1];
            rs1 += s[nt][2] + s[nt][3];
        }
        rs0 += __shfl_xor_sync(0xffffffffu, rs0, 1);
        rs0 += __shfl_xor_sync(0xffffffffu, rs0, 2);
        rs1 += __shfl_xor_sync(0xffffffffu, rs1, 1);
        rs1 += __shfl_xor_sync(0xffffffffu, rs1, 2);
        l0 = l0 * cr0 + rs0;
        l1 = l1 * cr1 + rs1;

        #pragma unroll
        for (int ntd = 0; ntd < 8; ntd++) {
            acco[ntd][0] *= cr0; acco[ntd][1] *= cr0;
            acco[ntd][2] *= cr1; acco[ntd][3] *= cr1;
        }

        #pragma unroll
        for (int kc = 0; kc < 4; kc++) {
            uint32_t pah[4], pal[4];
            split2(s[2 * kc][0],     s[2 * kc][1],     pah[0], pal[0]);
            split2(s[2 * kc][2],     s[2 * kc][3],     pah[1], pal[1]);
            split2(s[2 * kc + 1][0], s[2 * kc + 1][1], pah[2], pal[2]);
            split2(s[2 * kc + 1][2], s[2 * kc + 1][3], pah[3], pal[3]);
            #pragma unroll
            for (int ntd = 0; ntd < 8; ntd++) {
                int d0 = ntd * 8 + gid;
                int sw = d0 & 7;
                uint32_t o0 = d0 * 32 + (((2 * kc) ^ sw) << 2) + tig;
                uint32_t o1 = d0 * 32 + (((2 * kc + 1) ^ sw) << 2) + tig;
                uint32_t bh0 = svh[o0], bh1 = svh[o1];
                uint32_t bl0 = svl[o0], bl1 = svl[o1];
                mma_bf16(acco[ntd], pah, bh0, bh1);
                mma_bf16(acco[ntd], pah, bl0, bl1);
                mma_bf16(acco[ntd], pal, bh0, bh1);
            }
        }
    }

    float i0 = 1.f / l0, i1 = 1.f / l1;
    #pragma unroll
    for (int ntd = 0; ntd < 8; ntd++) {
        int col = hb + ntd * 8 + 2 * tig;
        uint32_t hh, ll;
        split2(acco[ntd][0] * i0, acco[ntd][1] * i0, hh, ll);
        *(uint32_t*)(ar_h + (size_t)r0 * DR + col) = hh;
        *(uint32_t*)(ar_l + (size_t)r0 * DR + col) = ll;
        split2(acco[ntd][2] * i1, acco[ntd][3] * i1, hh, ll);
        *(uint32_t*)(ar_h + (size_t)r8 * DR + col) = hh;
        *(uint32_t*)(ar_l + (size_t)r8 * DR + col) = ll;
    }
}

// ---------------- host launch ----------------
extern "C" void kernel_launch(void* const* d_in, const int* in_sizes, int n_in,
                              void* d_out, int out_size)
{
    const float* s      = (const float*)d_in[0];
    const float* r      = (const float*)d_in[1];
    const float* gate_v = (const float*)d_in[2];
    const float* nsw    = (const float*)d_in[3];
    const float* nrw    = (const float*)d_in[4];
    const float* Wsq    = (const float*)d_in[5];
    const float* Wsk    = (const float*)d_in[6];
    const float* Wsv    = (const float*)d_in[7];
    const float* Wso    = (const float*)d_in[8];
    const float* Wrq    = (const float*)d_in[9];
    const float* Wrk    = (const float*)d_in[10];
    const float* Wrv    = (const float*)d_in[11];
    const float* Wro    = (const float*)d_in[12];

    float* out_s = (float*)d_out;
    float* out_r = (float*)d_out + T_LEN * DS;

    __nv_bfloat16 *snh, *snl, *rnh, *rnl, *ash, *asl, *arh, *arl;
    __nv_bfloat16 *wsnh, *wsnl, *wrnh, *wrnl, *wsoh, *wsol, *wroh, *wrol;
    float *csn, *crn, *rsp;
    uint32_t *kh, *kl, *vth, *vtl;
    cudaGetSymbolAddress((void**)&snh, g_sn_h);
    cudaGetSymbolAddress((void**)&snl, g_sn_l);
    cudaGetSymbolAddress((void**)&rnh, g_rn_h);
    cudaGetSymbolAddress((void**)&rnl, g_rn_l);
    cudaGetSymbolAddress((void**)&ash, g_as_h);
    cudaGetSymbolAddress((void**)&asl, g_as_l);
    cudaGetSymbolAddress((void**)&arh, g_ar_h);
    cudaGetSymbolAddress((void**)&arl, g_ar_l);
    cudaGetSymbolAddress((void**)&wsnh, g_wsn_h);
    cudaGetSymbolAddress((void**)&wsnl, g_wsn_l);
    cudaGetSymbolAddress((void**)&wrnh, g_wrn_h);
    cudaGetSymbolAddress((void**)&wrnl, g_wrn_l);
    cudaGetSymbolAddress((void**)&wsoh, g_wso_h);
    cudaGetSymbolAddress((void**)&wsol, g_wso_l);
    cudaGetSymbolAddress((void**)&wroh, g_wro_h);
    cudaGetSymbolAddress((void**)&wrol, g_wro_l);
    cudaGetSymbolAddress((void**)&csn, g_csn);
    cudaGetSymbolAddress((void**)&crn, g_crn);
    cudaGetSymbolAddress((void**)&rsp, g_rsp);
    cudaGetSymbolAddress((void**)&kh, g_kh);
    cudaGetSymbolAddress((void**)&kl, g_kl);
    cudaGetSymbolAddress((void**)&vth, g_vth);
    cudaGetSymbolAddress((void**)&vtl, g_vtl);

    // ---- 1. prep: weight transposes + rmsnorms ----
    prep_kernel<<<4608 + T_LEN + ROWS_R, 256>>>(
        Wsq, Wsk, Wsv, Wso, Wrq, Wrk, Wrv, Wro,
        wsnh, wsnl, wrnh, wrnl, wsoh, wsol, wroh, wrol,
        s, nsw, snh, snl, r, nrw, rnh, rnl);

    // ---- 2. merged projection GEMMs ----
    {
        GArg g0 = {snh, snl, wsnh, wsnl, csn, T_LEN, N_SN, DS, N_SN,
                   nullptr, nullptr, nullptr};
        GArg g1 = {rnh, rnl, wrnh, wrnl, crn, ROWS_R, N_RN, DR, N_RN,
                   nullptr, nullptr, nullptr};
        int gx0 = N_SN / 128, gy0 = T_LEN / 64;
        int gx1 = N_RN / 128, gy1 = ROWS_R / 64;
        gemm_pair<<<gx0 * gy0 + gx1 * gy1, 256>>>(g0, g1, gx0 * gy0, gx0, gx1);
    }

    // ---- 3. conv_kv + s-attention ----
    conv_sattn_kernel<<<T_LEN + 1024 + T_LEN, 256>>>(
        csn, crn, kh, kl, vth, vtl, ash, asl, rsp);

    // ---- 4. causal r attention ----
    r_attn_mma<<<dim3(T_LEN / 8, HEADS), 128>>>(crn + 2048, N_RN,
                                                kh, kl, vth, vtl, arh, arl);

    // ---- 5. merged output GEMMs ----
    {
        GArg g0 = {ash, asl, wsoh, wsol, out_s, T_LEN, DS, DS, DS,
                   s, rsp, gate_v};
        GArg g1 = {arh, arl, wroh, wrol, out_r, ROWS_R, DR, DR, DR,
                   r, nullptr, nullptr};
        int gx0 = DS / 128, gy0 = T_LEN / 64;
        int gx1 = DR / 128, gy1 = ROWS_R / 64;
        gemm_pair<<<gx0 * gy0 + gx1 * gy1, 256>>>(g0, g1, gx0 * gy0, gx0, gx1);
    }
}